// round 4
// baseline (speedup 1.0000x reference)
#include <cuda_runtime.h>

// ---------------------------------------------------------------------------
// MoE GraphSAGE (N=32768 nodes, E=262144 edges, D=512, 4 experts, top-2, 2 layers)
//
//   1. detect edge_index dtype (int32 vs int64) on device
//   2. degree count -> prefix scan -> CSR fill
//   3. gate kernel: softmax + top-2 -> per-(node,expert) weight table
//   4. aggr(x) once (shared by all experts, layer 1)
//   5. 4x layer-1 GEMM: h1_e = relu(aggr@Wl + x@Wr + b)
//   6. memset(out, 0); 4x { aggr(h1_e); layer-2 GEMM + fused gated combine }
//
// GEMM: 128x128x16 tiles, 256 threads, 8x8 microtile with packed fma.rn.f32x2.
// ---------------------------------------------------------------------------

#define N_NODES 32768
#define N_EDGES 262144
#define D 512
#define NEXP 4
#define ND (N_NODES * D)

__device__ float g_h1[(size_t)NEXP * ND];
__device__ float g_aggr[ND];
__device__ float g_inv_deg[N_NODES];
__device__ int   g_deg[N_NODES];
__device__ int   g_rowptr[N_NODES + 1];
__device__ int   g_cursor[N_NODES];
__device__ int   g_colidx[N_EDGES];
__device__ float g_gatew[N_NODES * NEXP];
__device__ int   g_is64;

// ---------------------------------------------------------------------------
// Edge dtype detection. View as int32; little-endian int64 with values in
// [0, 32768) has every odd word == 0. Reads only first 1KB (in-bounds for
// both layouts).
// ---------------------------------------------------------------------------
__global__ void detect_kernel(const int* __restrict__ ei32) {
    if (threadIdx.x == 0) {
        int is64 = 1;
        for (int i = 0; i < 128; i++)
            if (ei32[2 * i + 1] != 0) { is64 = 0; break; }
        g_is64 = is64;
    }
}

__device__ __forceinline__ int edge_val(const int* __restrict__ ei32,
                                        int idx, int is64) {
    // element idx of the logical [2*N_EDGES] index array
    return is64 ? ei32[2 * idx] : ei32[idx];
}

// ---------------------------------------------------------------------------
// CSR construction
// ---------------------------------------------------------------------------
__global__ void zero_deg_kernel() {
    int i = blockIdx.x * blockDim.x + threadIdx.x;
    if (i < N_NODES) g_deg[i] = 0;
}

__global__ void deg_kernel(const int* __restrict__ ei32) {
    int i = blockIdx.x * blockDim.x + threadIdx.x;
    if (i < N_EDGES) {
        int dst = edge_val(ei32, N_EDGES + i, g_is64);
        atomicAdd(&g_deg[dst], 1);
    }
}

// Single block of 1024 threads: each thread scans 32 degrees, then
// block-wide Hillis-Steele over the 1024 partials.
__global__ void scan_kernel() {
    __shared__ int sm[1024];
    int t = threadIdx.x;
    int base = t * 32;
    int loc[32];
    int sum = 0;
#pragma unroll
    for (int i = 0; i < 32; i++) { loc[i] = sum; sum += g_deg[base + i]; }
    sm[t] = sum;
    __syncthreads();
    for (int off = 1; off < 1024; off <<= 1) {
        int v = (t >= off) ? sm[t - off] : 0;
        __syncthreads();
        sm[t] += v;
        __syncthreads();
    }
    int excl = sm[t] - sum;
#pragma unroll
    for (int i = 0; i < 32; i++) {
        int rp = excl + loc[i];
        g_rowptr[base + i] = rp;
        g_cursor[base + i] = rp;
        int d = g_deg[base + i];
        g_inv_deg[base + i] = (d > 0) ? 1.0f / (float)d : 0.0f;
    }
    if (t == 1023) g_rowptr[N_NODES] = sm[1023];
}

__global__ void fill_kernel(const int* __restrict__ ei32) {
    int i = blockIdx.x * blockDim.x + threadIdx.x;
    if (i < N_EDGES) {
        int is64 = g_is64;
        int src = edge_val(ei32, i, is64);
        int dst = edge_val(ei32, N_EDGES + i, is64);
        int pos = atomicAdd(&g_cursor[dst], 1);
        g_colidx[pos] = src;
    }
}

// ---------------------------------------------------------------------------
// Gate: one warp per node. Tie behavior matches jax.lax.top_k (lower index
// wins ties via strict '>').
// ---------------------------------------------------------------------------
__global__ void gate_kernel(const float* __restrict__ x,
                            const float* __restrict__ gW,
                            const float* __restrict__ gb) {
    int gtid = blockIdx.x * blockDim.x + threadIdx.x;
    int node = gtid >> 5;
    int lane = gtid & 31;
    if (node >= N_NODES) return;
    const float* xr = x + (size_t)node * D;
    float a0 = 0.f, a1 = 0.f, a2 = 0.f, a3 = 0.f;
    for (int i = lane; i < D; i += 32) {
        float xv = xr[i];
        float4 w = *(const float4*)&gW[i * 4];
        a0 = fmaf(xv, w.x, a0);
        a1 = fmaf(xv, w.y, a1);
        a2 = fmaf(xv, w.z, a2);
        a3 = fmaf(xv, w.w, a3);
    }
#pragma unroll
    for (int off = 16; off; off >>= 1) {
        a0 += __shfl_down_sync(0xffffffffu, a0, off);
        a1 += __shfl_down_sync(0xffffffffu, a1, off);
        a2 += __shfl_down_sync(0xffffffffu, a2, off);
        a3 += __shfl_down_sync(0xffffffffu, a3, off);
    }
    if (lane == 0) {
        float l[4] = {a0 + gb[0], a1 + gb[1], a2 + gb[2], a3 + gb[3]};
        float m = fmaxf(fmaxf(l[0], l[1]), fmaxf(l[2], l[3]));
        float e[4], s = 0.f;
#pragma unroll
        for (int k = 0; k < 4; k++) { e[k] = expf(l[k] - m); s += e[k]; }
        float inv = 1.0f / s;
        float p[4];
#pragma unroll
        for (int k = 0; k < 4; k++) p[k] = e[k] * inv;
        int i1 = 0;
#pragma unroll
        for (int k = 1; k < 4; k++) if (p[k] > p[i1]) i1 = k;
        int i2 = -1;
#pragma unroll
        for (int k = 0; k < 4; k++) {
            if (k == i1) continue;
            if (i2 < 0 || p[k] > p[i2]) i2 = k;
        }
#pragma unroll
        for (int k = 0; k < 4; k++) {
            float w = (k == i1) ? p[i1] : ((k == i2) ? p[i2] : 0.0f);
            g_gatew[node * 4 + k] = w;
        }
    }
}

// ---------------------------------------------------------------------------
// Mean aggregation via CSR: one block per node, 128 threads x float4.
// ---------------------------------------------------------------------------
__global__ void aggregate_kernel(const float* __restrict__ xin, int expert) {
    const float* __restrict__ h =
        (expert >= 0) ? (g_h1 + (size_t)expert * ND) : xin;
    int node = blockIdx.x;
    int c = threadIdx.x * 4;
    float4 acc = make_float4(0.f, 0.f, 0.f, 0.f);
    int beg = g_rowptr[node], end = g_rowptr[node + 1];
    for (int j = beg; j < end; j++) {
        int s = g_colidx[j];
        float4 v = *(const float4*)&h[(size_t)s * D + c];
        acc.x += v.x; acc.y += v.y; acc.z += v.z; acc.w += v.w;
    }
    float inv = g_inv_deg[node];
    acc.x *= inv; acc.y *= inv; acc.z *= inv; acc.w *= inv;
    *(float4*)&g_aggr[(size_t)node * D + c] = acc;
}

// ---------------------------------------------------------------------------
// Packed fp32x2 helpers (Blackwell FFMA2 — PTX-only)
// ---------------------------------------------------------------------------
__device__ __forceinline__ unsigned long long pk2(float x) {
    unsigned long long r;
    asm("mov.b64 %0, {%1, %2};" : "=l"(r) : "f"(x), "f"(x));
    return r;
}
__device__ __forceinline__ unsigned long long ffma2(unsigned long long a,
                                                    unsigned long long b,
                                                    unsigned long long c) {
    unsigned long long d;
    asm("fma.rn.f32x2 %0, %1, %2, %3;" : "=l"(d) : "l"(a), "l"(b), "l"(c));
    return d;
}
__device__ __forceinline__ float2 upk2(unsigned long long v) {
    float2 f;
    asm("mov.b64 {%0, %1}, %2;" : "=f"(f.x), "=f"(f.y) : "l"(v));
    return f;
}

// ---------------------------------------------------------------------------
// Fused SAGE GEMM: C = relu(aggr@Wl + Ah@Wr + bias), logically K=1024.
//   store_expert >= 0: write into g_h1[store_expert]   (layer 1)
//   store_expert <  0: out[row] += gatew[row][e] * relu(...)  (layer 2)
// ---------------------------------------------------------------------------
#define BM 128
#define BN 128
#define BK 16

__global__ __launch_bounds__(256, 2)
void sage_gemm_kernel(const float* __restrict__ Ah_ext, int ah_expert,
                      const float* __restrict__ Wl, const float* __restrict__ Wr,
                      const float* __restrict__ bias,
                      float* __restrict__ out_ext, int store_expert,
                      int gate_expert) {
    __shared__ float As[BK][BM];
    __shared__ float Bs[BK][BN];

    const float* __restrict__ Aagg = g_aggr;
    const float* __restrict__ Ah =
        (ah_expert >= 0) ? (g_h1 + (size_t)ah_expert * ND) : Ah_ext;

    int tid = threadIdx.x;
    int tx = tid & 15, ty = tid >> 4;
    int bm = blockIdx.y * BM, bn = blockIdx.x * BN;

    unsigned long long acc2[8][4];
#pragma unroll
    for (int i = 0; i < 8; i++)
#pragma unroll
        for (int j = 0; j < 4; j++) acc2[i][j] = 0ULL;

    float4 ar[2], br[2];
    const int NSTEP = 2 * (D / BK);  // 64

    auto gload = [&](int step) {
        int phase = step >> 5;
        int k0 = (step & 31) * BK;
        const float* Ap = phase ? Ah : Aagg;
        const float* Wp = phase ? Wr : Wl;
#pragma unroll
        for (int i = 0; i < 2; i++) {
            int f = tid + i * 256;
            ar[i] = *(const float4*)&Ap[(size_t)(bm + (f >> 2)) * D + k0 + (f & 3) * 4];
            br[i] = *(const float4*)&Wp[(size_t)(k0 + (f >> 5)) * D + bn + (f & 31) * 4];
        }
    };
    auto sstore = [&]() {
#pragma unroll
        for (int i = 0; i < 2; i++) {
            int f = tid + i * 256;
            int row = f >> 2, c4 = f & 3;
            As[c4 * 4 + 0][row] = ar[i].x;
            As[c4 * 4 + 1][row] = ar[i].y;
            As[c4 * 4 + 2][row] = ar[i].z;
            As[c4 * 4 + 3][row] = ar[i].w;
            int brow = f >> 5, bc4 = f & 31;
            *(float4*)&Bs[brow][bc4 * 4] = br[i];
        }
    };

    gload(0);
    for (int step = 0; step < NSTEP; step++) {
        __syncthreads();
        sstore();
        __syncthreads();
        if (step + 1 < NSTEP) gload(step + 1);
#pragma unroll
        for (int k = 0; k < BK; k++) {
            float a_s[8];
#pragma unroll
            for (int i = 0; i < 8; i++) a_s[i] = As[k][ty * 8 + i];
            unsigned long long bv[4];
#pragma unroll
            for (int j = 0; j < 4; j++)
                bv[j] = *(const unsigned long long*)&Bs[k][2 * (tx + 16 * j)];
#pragma unroll
            for (int i = 0; i < 8; i++) {
                unsigned long long av = pk2(a_s[i]);
#pragma unroll
                for (int j = 0; j < 4; j++)
                    acc2[i][j] = ffma2(av, bv[j], acc2[i][j]);
            }
        }
    }

    float2 bb[4];
#pragma unroll
    for (int j = 0; j < 4; j++)
        bb[j] = *(const float2*)&bias[bn + 2 * (tx + 16 * j)];

    if (store_expert >= 0) {
        float* C = g_h1 + (size_t)store_expert * ND;
#pragma unroll
        for (int i = 0; i < 8; i++) {
            size_t row = bm + ty * 8 + i;
#pragma unroll
            for (int j = 0; j < 4; j++) {
                float2 v = upk2(acc2[i][j]);
                v.x = fmaxf(v.x + bb[j].x, 0.0f);
                v.y = fmaxf(v.y + bb[j].y, 0.0f);
                *(float2*)&C[row * D + bn + 2 * (tx + 16 * j)] = v;
            }
        }
    } else {
#pragma unroll
        for (int i = 0; i < 8; i++) {
            int row = bm + ty * 8 + i;
            float w = g_gatew[row * 4 + gate_expert];
            if (w == 0.0f) continue;
#pragma unroll
            for (int j = 0; j < 4; j++) {
                float2 v = upk2(acc2[i][j]);
                float* p = &out_ext[(size_t)row * D + bn + 2 * (tx + 16 * j)];
                float2 cur = *(float2*)p;
                cur.x += w * fmaxf(v.x + bb[j].x, 0.0f);
                cur.y += w * fmaxf(v.y + bb[j].y, 0.0f);
                *(float2*)p = cur;
            }
        }
    }
}

// ---------------------------------------------------------------------------
// Launch. Inputs matched by element count (robust to metadata reordering):
//   x=16777216, gate_W=2048, gate_b=4, Wl=2097152(first), bl=4096,
//   Wr=2097152(second), edge_index=524288
// ---------------------------------------------------------------------------
extern "C" void kernel_launch(void* const* d_in, const int* in_sizes, int n_in,
                              void* d_out, int out_size) {
    const float* x = 0; const float* gW = 0; const float* gb = 0;
    const float* Wl = 0; const float* bl = 0; const float* Wr = 0;
    const int*   ei = 0;
    for (int i = 0; i < n_in; i++) {
        long long s = in_sizes[i];
        if (s == 16777216)      { if (!x)  x  = (const float*)d_in[i]; }
        else if (s == 2048)     { if (!gW) gW = (const float*)d_in[i]; }
        else if (s == 4)        { if (!gb) gb = (const float*)d_in[i]; }
        else if (s == 2097152)  { if (!Wl) Wl = (const float*)d_in[i];
                                  else if (!Wr) Wr = (const float*)d_in[i]; }
        else if (s == 4096)     { if (!bl) bl = (const float*)d_in[i]; }
        else if (s == 524288)   { if (!ei) ei = (const int*)d_in[i]; }
    }
    // Fallback to declared order if size matching failed
    if (!x)  x  = (const float*)d_in[0];
    if (!gW) gW = (const float*)d_in[1];
    if (!gb) gb = (const float*)d_in[2];
    if (!Wl) Wl = (const float*)d_in[3];
    if (!bl) bl = (const float*)d_in[4];
    if (!Wr) Wr = (const float*)d_in[5];
    if (!ei) ei = (const int*)d_in[6];
    float* out = (float*)d_out;

    detect_kernel<<<1, 32>>>(ei);
    zero_deg_kernel<<<N_NODES / 256, 256>>>();
    deg_kernel<<<N_EDGES / 256, 256>>>(ei);
    scan_kernel<<<1, 1024>>>();
    fill_kernel<<<N_EDGES / 256, 256>>>(ei);
    gate_kernel<<<N_NODES / 8, 256>>>(x, gW, gb);

    aggregate_kernel<<<N_NODES, 128>>>(x, -1);

    dim3 gg(D / BN, N_NODES / BM);  // (4, 256)
    for (int e = 0; e < NEXP; e++) {
        const float* wl = Wl + ((size_t)e * 2 + 0) * D * D;
        const float* wr = Wr + ((size_t)e * 2 + 0) * D * D;
        const float* bp = bl + ((size_t)e * 2 + 0) * D;
        sage_gemm_kernel<<<gg, 256>>>(x, -1, wl, wr, bp, nullptr, e, -1);
    }

    cudaMemsetAsync(out, 0, (size_t)out_size * sizeof(float));
    for (int e = 0; e < NEXP; e++) {
        aggregate_kernel<<<N_NODES, 128>>>(nullptr, e);
        const float* wl = Wl + ((size_t)e * 2 + 1) * D * D;
        const float* wr = Wr + ((size_t)e * 2 + 1) * D * D;
        const float* bp = bl + ((size_t)e * 2 + 1) * D;
        sage_gemm_kernel<<<gg, 256>>>(nullptr, e, wl, wr, bp, out, -1, e);
    }
}

// round 8
// speedup vs baseline: 1.5155x; 1.5155x over previous
#include <cuda_runtime.h>
#include <cuda_fp16.h>
#include <cstdint>

// ---------------------------------------------------------------------------
// MoE GraphSAGE, tensor cores via baseline PTX mma.sync m16n8k16 (fp16,
// fp32 accum). fp32 emulated as fp16x3 split: C = Ahi@Bhi + Ahi@Blo + Alo@Bhi.
//
// ROUND-7 FIX: __device__ global arrays are NEVER passed as kernel arguments
// from host code (host shadow address != device address; on GB300 ATS this
// silently reads host memory instead of faulting — the R5/R6 rel_err=0.957).
// All globals are resolved in device code from integer selectors (R3 pattern).
// ---------------------------------------------------------------------------

#define N_NODES 32768
#define N_EDGES 262144
#define D 512
#define NEXP 4
#define ND (N_NODES * D)

typedef __half fp16;

__device__ fp16  g_xhi[ND], g_xlo[ND];
__device__ fp16  g_ahi[ND], g_alo[ND];
__device__ fp16  g_h1hi[(size_t)NEXP * ND];
__device__ fp16  g_h1lo[(size_t)NEXP * ND];
__device__ fp16  g_wthi[8ull * 512 * 1024];   // [w_idx][n][k], k contiguous
__device__ fp16  g_wtlo[8ull * 512 * 1024];
__device__ float g_inv_deg[N_NODES];
__device__ int   g_deg[N_NODES];
__device__ int   g_rowptr[N_NODES + 1];
__device__ int   g_cursor[N_NODES];
__device__ int   g_colidx[N_EDGES];
__device__ float g_gatew[N_NODES * NEXP];
__device__ int   g_is64;

__device__ __forceinline__ void split_f16(float v, fp16& h, fp16& l) {
    h = __float2half_rn(v);
    l = __float2half_rn(v - __half2float(h));
}

// ---------------------------------------------------------------------------
// Edge dtype detect + CSR (proven R3)
// ---------------------------------------------------------------------------
__global__ void detect_kernel(const int* __restrict__ ei32) {
    if (threadIdx.x == 0) {
        int is64 = 1;
        for (int i = 0; i < 128; i++)
            if (ei32[2 * i + 1] != 0) { is64 = 0; break; }
        g_is64 = is64;
    }
}
__device__ __forceinline__ int edge_val(const int* __restrict__ e, int idx, int is64) {
    return is64 ? e[2 * idx] : e[idx];
}
__global__ void zero_deg_kernel() {
    int i = blockIdx.x * blockDim.x + threadIdx.x;
    if (i < N_NODES) g_deg[i] = 0;
}
__global__ void deg_kernel(const int* __restrict__ ei32) {
    int i = blockIdx.x * blockDim.x + threadIdx.x;
    if (i < N_EDGES) atomicAdd(&g_deg[edge_val(ei32, N_EDGES + i, g_is64)], 1);
}
__global__ void scan_kernel() {
    __shared__ int sm[1024];
    int t = threadIdx.x;
    int base = t * 32;
    int loc[32];
    int sum = 0;
#pragma unroll
    for (int i = 0; i < 32; i++) { loc[i] = sum; sum += g_deg[base + i]; }
    sm[t] = sum;
    __syncthreads();
    for (int off = 1; off < 1024; off <<= 1) {
        int v = (t >= off) ? sm[t - off] : 0;
        __syncthreads();
        sm[t] += v;
        __syncthreads();
    }
    int excl = sm[t] - sum;
#pragma unroll
    for (int i = 0; i < 32; i++) {
        int rp = excl + loc[i];
        g_rowptr[base + i] = rp;
        g_cursor[base + i] = rp;
        int d = g_deg[base + i];
        g_inv_deg[base + i] = (d > 0) ? 1.0f / (float)d : 0.0f;
    }
    if (t == 1023) g_rowptr[N_NODES] = sm[1023];
}
__global__ void fill_kernel(const int* __restrict__ ei32) {
    int i = blockIdx.x * blockDim.x + threadIdx.x;
    if (i < N_EDGES) {
        int is64 = g_is64;
        int src = edge_val(ei32, i, is64);
        int dst = edge_val(ei32, N_EDGES + i, is64);
        g_colidx[atomicAdd(&g_cursor[dst], 1)] = src;
    }
}

// ---------------------------------------------------------------------------
// Gate (proven R3)
// ---------------------------------------------------------------------------
__global__ void gate_kernel(const float* __restrict__ x,
                            const float* __restrict__ gW,
                            const float* __restrict__ gb) {
    int gtid = blockIdx.x * blockDim.x + threadIdx.x;
    int node = gtid >> 5, lane = gtid & 31;
    if (node >= N_NODES) return;
    const float* xr = x + (size_t)node * D;
    float a0 = 0.f, a1 = 0.f, a2 = 0.f, a3 = 0.f;
    for (int i = lane; i < D; i += 32) {
        float xv = xr[i];
        float4 w = *(const float4*)&gW[i * 4];
        a0 = fmaf(xv, w.x, a0); a1 = fmaf(xv, w.y, a1);
        a2 = fmaf(xv, w.z, a2); a3 = fmaf(xv, w.w, a3);
    }
#pragma unroll
    for (int off = 16; off; off >>= 1) {
        a0 += __shfl_down_sync(0xffffffffu, a0, off);
        a1 += __shfl_down_sync(0xffffffffu, a1, off);
        a2 += __shfl_down_sync(0xffffffffu, a2, off);
        a3 += __shfl_down_sync(0xffffffffu, a3, off);
    }
    if (lane == 0) {
        float l[4] = {a0 + gb[0], a1 + gb[1], a2 + gb[2], a3 + gb[3]};
        float m = fmaxf(fmaxf(l[0], l[1]), fmaxf(l[2], l[3]));
        float e[4], s = 0.f;
#pragma unroll
        for (int k = 0; k < 4; k++) { e[k] = expf(l[k] - m); s += e[k]; }
        float inv = 1.0f / s;
        float p[4];
#pragma unroll
        for (int k = 0; k < 4; k++) p[k] = e[k] * inv;
        int i1 = 0;
#pragma unroll
        for (int k = 1; k < 4; k++) if (p[k] > p[i1]) i1 = k;
        int i2 = -1;
#pragma unroll
        for (int k = 0; k < 4; k++) {
            if (k == i1) continue;
            if (i2 < 0 || p[k] > p[i2]) i2 = k;
        }
#pragma unroll
        for (int k = 0; k < 4; k++)
            g_gatew[node * 4 + k] = (k == i1) ? p[i1] : ((k == i2) ? p[i2] : 0.0f);
    }
}

// ---------------------------------------------------------------------------
// x -> fp16 hi/lo
// ---------------------------------------------------------------------------
__global__ void convert_x_kernel(const float* __restrict__ x) {
    int i = blockIdx.x * blockDim.x + threadIdx.x;
    float4 v = *(const float4*)&x[(size_t)i * 4];
    union { fp16 b[4]; uint2 u; } ph, pl;
    split_f16(v.x, ph.b[0], pl.b[0]);
    split_f16(v.y, ph.b[1], pl.b[1]);
    split_f16(v.z, ph.b[2], pl.b[2]);
    split_f16(v.w, ph.b[3], pl.b[3]);
    *(uint2*)&g_xhi[(size_t)i * 4] = ph.u;
    *(uint2*)&g_xlo[(size_t)i * 4] = pl.u;
}

// ---------------------------------------------------------------------------
// Weight prep: Wt[m][n][k] = (k<512 ? Wl[m][k][n] : Wr[m][k-512][n]), hi/lo
// ---------------------------------------------------------------------------
__global__ void prep_w_kernel(const float* __restrict__ Wl, const float* __restrict__ Wr) {
    __shared__ float sm[32][33];
    int m = blockIdx.z;
    int k0 = blockIdx.x * 32, n0 = blockIdx.y * 32;
    int tx = threadIdx.x, ty = threadIdx.y;
    const float* W = (k0 < 512) ? (Wl + (size_t)m * 512 * 512 + (size_t)(k0 + ty) * 512)
                                : (Wr + (size_t)m * 512 * 512 + (size_t)(k0 - 512 + ty) * 512);
    sm[ty][tx] = W[n0 + tx];
    __syncthreads();
    float v = sm[tx][ty];
    fp16 h, l;
    split_f16(v, h, l);
    size_t o = (size_t)m * 512 * 1024 + (size_t)(n0 + ty) * 1024 + (k0 + tx);
    g_wthi[o] = h;
    g_wtlo[o] = l;
}

// ---------------------------------------------------------------------------
// Aggregations (CSR mean) -> fp16 hi/lo
// ---------------------------------------------------------------------------
__global__ void aggregate_x_kernel(const float* __restrict__ x) {
    int node = blockIdx.x;
    int c = threadIdx.x * 4;
    float4 acc = make_float4(0.f, 0.f, 0.f, 0.f);
    int beg = g_rowptr[node], end = g_rowptr[node + 1];
    for (int j = beg; j < end; j++) {
        float4 v = *(const float4*)&x[(size_t)g_colidx[j] * D + c];
        acc.x += v.x; acc.y += v.y; acc.z += v.z; acc.w += v.w;
    }
    float inv = g_inv_deg[node];
    union { fp16 b[4]; uint2 u; } ph, pl;
    split_f16(acc.x * inv, ph.b[0], pl.b[0]);
    split_f16(acc.y * inv, ph.b[1], pl.b[1]);
    split_f16(acc.z * inv, ph.b[2], pl.b[2]);
    split_f16(acc.w * inv, ph.b[3], pl.b[3]);
    *(uint2*)&g_ahi[(size_t)node * D + c] = ph.u;
    *(uint2*)&g_alo[(size_t)node * D + c] = pl.u;
}

__global__ void aggregate_h_kernel(int expert) {
    const fp16* __restrict__ hh = g_h1hi + (size_t)expert * ND;
    const fp16* __restrict__ hl = g_h1lo + (size_t)expert * ND;
    int node = blockIdx.x;
    int c = threadIdx.x * 4;
    float4 acc = make_float4(0.f, 0.f, 0.f, 0.f);
    int beg = g_rowptr[node], end = g_rowptr[node + 1];
    for (int j = beg; j < end; j++) {
        size_t base = (size_t)g_colidx[j] * D + c;
        union { fp16 b[4]; uint2 u; } vh, vl;
        vh.u = *(const uint2*)&hh[base];
        vl.u = *(const uint2*)&hl[base];
        acc.x += __half2float(vh.b[0]) + __half2float(vl.b[0]);
        acc.y += __half2float(vh.b[1]) + __half2float(vl.b[1]);
        acc.z += __half2float(vh.b[2]) + __half2float(vl.b[2]);
        acc.w += __half2float(vh.b[3]) + __half2float(vl.b[3]);
    }
    float inv = g_inv_deg[node];
    union { fp16 b[4]; uint2 u; } ph, pl;
    split_f16(acc.x * inv, ph.b[0], pl.b[0]);
    split_f16(acc.y * inv, ph.b[1], pl.b[1]);
    split_f16(acc.z * inv, ph.b[2], pl.b[2]);
    split_f16(acc.w * inv, ph.b[3], pl.b[3]);
    *(uint2*)&g_ahi[(size_t)node * D + c] = ph.u;
    *(uint2*)&g_alo[(size_t)node * D + c] = pl.u;
}

// ---------------------------------------------------------------------------
// Tensor-core GEMM. BM=BN=128, BK=32, 256 threads (8 warps 2x4, warp tile
// 64x32). Logical K=1024: chunks 0-15 = aggr (@Wl half), 16-31 = own features
// (@Wr half). ALL global arrays resolved in device code from selectors:
//   a_sel: -1 -> x hi/lo, else h1[expert] hi/lo  (chunks 16-31 operand)
//   w_idx: weight matrix index (e*2 + layer)
//   store_expert >= 0 -> write h1[expert] hi/lo; else gated-combine into out
// ---------------------------------------------------------------------------
#define ROWB 80
#define TILE_B (128 * ROWB)                     // 10240
#define GEMM_SMEM (128 * 132 * 4)               // 67584

__device__ __forceinline__ void mma16816(float* c, const uint32_t* a, const uint32_t* b) {
    asm volatile("mma.sync.aligned.m16n8k16.row.col.f32.f16.f16.f32 "
                 "{%0,%1,%2,%3}, {%4,%5,%6,%7}, {%8,%9}, {%0,%1,%2,%3};"
                 : "+f"(c[0]), "+f"(c[1]), "+f"(c[2]), "+f"(c[3])
                 : "r"(a[0]), "r"(a[1]), "r"(a[2]), "r"(a[3]), "r"(b[0]), "r"(b[1]));
}

__global__ void __launch_bounds__(256, 1)
sage_gemm_mma(int a_sel, int w_idx, const float* __restrict__ bias,
              int store_expert, float* __restrict__ out, int gate_e) {
    extern __shared__ char smem[];
    int tid = threadIdx.x, lane = tid & 31, wid = tid >> 5;
    int wm = wid >> 2, wn = wid & 3;
    int g = lane >> 2, lam = lane & 3;
    int bn = blockIdx.x * 128, bm = blockIdx.y * 128;

    // device-side pointer resolution (THE fix)
    const fp16* __restrict__ ahh = (a_sel < 0) ? g_xhi : g_h1hi + (size_t)a_sel * ND;
    const fp16* __restrict__ ahl = (a_sel < 0) ? g_xlo : g_h1lo + (size_t)a_sel * ND;
    const fp16* __restrict__ bh = g_wthi + (size_t)w_idx * 512 * 1024;
    const fp16* __restrict__ bl = g_wtlo + (size_t)w_idx * 512 * 1024;

    float c[4][4][4];
#pragma unroll
    for (int i = 0; i < 4; i++)
#pragma unroll
        for (int j = 0; j < 4; j++)
#pragma unroll
            for (int q = 0; q < 4; q++) c[i][j][q] = 0.f;

    uint4 rg[4][2];
    int row_s = tid >> 2, kc_s = tid & 3;
    int row_s2 = (tid + 256) >> 2, kc_s2 = (tid + 256) & 3;

    auto gload = [&](int n) {
        const fp16 *Ah, *Al;
        int ka;
        if (n < 16) { Ah = g_ahi; Al = g_alo; ka = n * 32; }
        else        { Ah = ahh;   Al = ahl;   ka = (n - 16) * 32; }
        int kb = n * 32;
        rg[0][0] = *(const uint4*)(Ah + (size_t)(bm + row_s) * 512 + ka + kc_s * 8);
        rg[0][1] = *(const uint4*)(Ah + (size_t)(bm + row_s2) * 512 + ka + kc_s2 * 8);
        rg[1][0] = *(const uint4*)(Al + (size_t)(bm + row_s) * 512 + ka + kc_s * 8);
        rg[1][1] = *(const uint4*)(Al + (size_t)(bm + row_s2) * 512 + ka + kc_s2 * 8);
        rg[2][0] = *(const uint4*)(bh + (size_t)(bn + row_s) * 1024 + kb + kc_s * 8);
        rg[2][1] = *(const uint4*)(bh + (size_t)(bn + row_s2) * 1024 + kb + kc_s2 * 8);
        rg[3][0] = *(const uint4*)(bl + (size_t)(bn + row_s) * 1024 + kb + kc_s * 8);
        rg[3][1] = *(const uint4*)(bl + (size_t)(bn + row_s2) * 1024 + kb + kc_s2 * 8);
    };
    auto sstore = [&]() {
#pragma unroll
        for (int t = 0; t < 4; t++) {
            *(uint4*)(smem + t * TILE_B + row_s * ROWB + kc_s * 16) = rg[t][0];
            *(uint4*)(smem + t * TILE_B + row_s2 * ROWB + kc_s2 * 16) = rg[t][1];
        }
    };

    gload(0);
    for (int it = 0; it < 32; it++) {
        __syncthreads();
        sstore();
        __syncthreads();
        if (it + 1 < 32) gload(it + 1);

#pragma unroll
        for (int ks = 0; ks < 2; ks++) {
            uint32_t aH[4][4], aL[4][4], bH[4][2], bL[4][2];
#pragma unroll
            for (int mb = 0; mb < 4; mb++) {
                const char* p = smem + (wm * 64 + mb * 16 + g) * ROWB + ks * 32 + lam * 4;
                aH[mb][0] = *(const uint32_t*)(p);
                aH[mb][1] = *(const uint32_t*)(p + 8 * ROWB);
                aH[mb][2] = *(const uint32_t*)(p + 16);
                aH[mb][3] = *(const uint32_t*)(p + 8 * ROWB + 16);
                aL[mb][0] = *(const uint32_t*)(p + TILE_B);
                aL[mb][1] = *(const uint32_t*)(p + TILE_B + 8 * ROWB);
                aL[mb][2] = *(const uint32_t*)(p + TILE_B + 16);
                aL[mb][3] = *(const uint32_t*)(p + TILE_B + 8 * ROWB + 16);
            }
#pragma unroll
            for (int nb = 0; nb < 4; nb++) {
                const char* p = smem + 2 * TILE_B + (wn * 32 + nb * 8 + g) * ROWB
                                + ks * 32 + lam * 4;
                bH[nb][0] = *(const uint32_t*)(p);
                bH[nb][1] = *(const uint32_t*)(p + 16);
                bL[nb][0] = *(const uint32_t*)(p + TILE_B);
                bL[nb][1] = *(const uint32_t*)(p + TILE_B + 16);
            }
#pragma unroll
            for (int mb = 0; mb < 4; mb++)
#pragma unroll
                for (int nb = 0; nb < 4; nb++) {
                    mma16816(c[mb][nb], aH[mb], bH[nb]);
                    mma16816(c[mb][nb], aH[mb], bL[nb]);
                    mma16816(c[mb][nb], aL[mb], bH[nb]);
                }
        }
    }
    __syncthreads();

    // Epilogue: fragments -> SMEM fp32 stage -> coalesced stores
    float* sep = (float*)smem;  // [128][132]
#pragma unroll
    for (int mb = 0; mb < 4; mb++)
#pragma unroll
        for (int nb = 0; nb < 4; nb++)
#pragma unroll
            for (int q = 0; q < 4; q++) {
                int row = wm * 64 + mb * 16 + g + ((q >> 1) << 3);
                int col = wn * 32 + nb * 8 + 2 * lam + (q & 1);
                sep[row * 132 + col] = c[mb][nb][q];
            }
    __syncthreads();

    if (store_expert >= 0) {
        fp16* ohi = g_h1hi + (size_t)store_expert * ND;
        fp16* olo = g_h1lo + (size_t)store_expert * ND;
        int w = tid & 63, rs = tid >> 6;
        float b0 = bias[bn + 2 * w], b1 = bias[bn + 2 * w + 1];
#pragma unroll
        for (int it = 0; it < 32; it++) {
            int rr = rs + it * 4;
            float v0 = fmaxf(sep[rr * 132 + 2 * w] + b0, 0.f);
            float v1 = fmaxf(sep[rr * 132 + 2 * w + 1] + b1, 0.f);
            union { fp16 b[2]; uint32_t u; } ph, pl;
            split_f16(v0, ph.b[0], pl.b[0]);
            split_f16(v1, ph.b[1], pl.b[1]);
            size_t o = (size_t)(bm + rr) * D + bn + 2 * w;
            *(uint32_t*)&ohi[o] = ph.u;
            *(uint32_t*)&olo[o] = pl.u;
        }
    } else {
        float4 bc = *(const float4*)&bias[bn + lane * 4];
#pragma unroll
        for (int it = 0; it < 16; it++) {
            int rr = wid + it * 8;
            int m = bm + rr;
            float gw = g_gatew[m * 4 + gate_e];
            if (gw != 0.f) {
                float* p = out + (size_t)m * D + bn + lane * 4;
                float4 cur = *(float4*)p;
                cur.x += gw * fmaxf(sep[rr * 132 + lane * 4 + 0] + bc.x, 0.f);
                cur.y += gw * fmaxf(sep[rr * 132 + lane * 4 + 1] + bc.y, 0.f);
                cur.z += gw * fmaxf(sep[rr * 132 + lane * 4 + 2] + bc.z, 0.f);
                cur.w += gw * fmaxf(sep[rr * 132 + lane * 4 + 3] + bc.w, 0.f);
                *(float4*)p = cur;
            }
        }
    }
}

// ---------------------------------------------------------------------------
// Launch — only d_in/d_out pointers and integers cross the host boundary.
// ---------------------------------------------------------------------------
extern "C" void kernel_launch(void* const* d_in, const int* in_sizes, int n_in,
                              void* d_out, int out_size) {
    const float* x = 0; const float* gW = 0; const float* gb = 0;
    const float* Wl = 0; const float* blv = 0; const float* Wr = 0;
    const int*   ei = 0;
    for (int i = 0; i < n_in; i++) {
        long long s = in_sizes[i];
        if (s == 16777216)      { if (!x)  x  = (const float*)d_in[i]; }
        else if (s == 2048)     { if (!gW) gW = (const float*)d_in[i]; }
        else if (s == 4)        { if (!gb) gb = (const float*)d_in[i]; }
        else if (s == 2097152)  { if (!Wl) Wl = (const float*)d_in[i];
                                  else if (!Wr) Wr = (const float*)d_in[i]; }
        else if (s == 4096)     { if (!blv) blv = (const float*)d_in[i]; }
        else if (s == 524288)   { if (!ei) ei = (const int*)d_in[i]; }
    }
    if (!x)   x   = (const float*)d_in[0];
    if (!gW)  gW  = (const float*)d_in[1];
    if (!gb)  gb  = (const float*)d_in[2];
    if (!Wl)  Wl  = (const float*)d_in[3];
    if (!blv) blv = (const float*)d_in[4];
    if (!Wr)  Wr  = (const float*)d_in[5];
    if (!ei)  ei  = (const int*)d_in[6];
    float* out = (float*)d_out;

    cudaFuncSetAttribute(sage_gemm_mma,
                         cudaFuncAttributeMaxDynamicSharedMemorySize, GEMM_SMEM);

    detect_kernel<<<1, 32>>>(ei);
    zero_deg_kernel<<<N_NODES / 256, 256>>>();
    deg_kernel<<<N_EDGES / 256, 256>>>(ei);
    scan_kernel<<<1, 1024>>>();
    fill_kernel<<<N_EDGES / 256, 256>>>(ei);
    gate_kernel<<<N_NODES / 8, 256>>>(x, gW, gb);
    convert_x_kernel<<<ND / 4 / 256, 256>>>(x);
    prep_w_kernel<<<dim3(32, 16, 8), dim3(32, 32)>>>(Wl, Wr);

    dim3 gg(D / 128, N_NODES / 128);  // (4, 256)

    // Layer 1 (shared aggr(x)); a_sel=-1 -> x, store h1[e]
    aggregate_x_kernel<<<N_NODES, 128>>>(x);
    for (int e = 0; e < NEXP; e++)
        sage_gemm_mma<<<gg, 256, GEMM_SMEM>>>(-1, e * 2, blv + (e * 2) * 512,
                                              e, out, -1);

    // Layer 2 + fused gated combine; a_sel=e -> h1[e]
    cudaMemsetAsync(out, 0, (size_t)out_size * sizeof(float));
    for (int e = 0; e < NEXP; e++) {
        aggregate_h_kernel<<<N_NODES, 128>>>(e);
        sage_gemm_mma<<<gg, 256, GEMM_SMEM>>>(e, e * 2 + 1, blv + (e * 2 + 1) * 512,
                                              -1, out, e);
    }
}

// round 9
// speedup vs baseline: 1.7062x; 1.1258x over previous
#include <cuda_runtime.h>
#include <cuda_fp16.h>
#include <cstdint>

// ---------------------------------------------------------------------------
// MoE GraphSAGE, mma.sync m16n8k16 fp16 (fp32 accum), fp16x3 split GEMM.
// R9: ldmatrix + cp.async double-buffered mainloop (fragment mappings verified
// against the R8-passing direct-LDS layout); two-level prefix scan.
// __device__ globals are resolved ONLY in device code (R7 ATS lesson).
// ---------------------------------------------------------------------------

#define N_NODES 32768
#define N_EDGES 262144
#define D 512
#define NEXP 4
#define ND (N_NODES * D)

typedef __half fp16;

__device__ fp16  g_xhi[ND], g_xlo[ND];
__device__ fp16  g_ahi[ND], g_alo[ND];
__device__ fp16  g_h1hi[(size_t)NEXP * ND];
__device__ fp16  g_h1lo[(size_t)NEXP * ND];
__device__ fp16  g_wthi[8ull * 512 * 1024];   // [w_idx][n][k]
__device__ fp16  g_wtlo[8ull * 512 * 1024];
__device__ float g_inv_deg[N_NODES];
__device__ int   g_deg[N_NODES];
__device__ int   g_rowptr[N_NODES + 1];
__device__ int   g_cursor[N_NODES];
__device__ int   g_colidx[N_EDGES];
__device__ float g_gatew[N_NODES * NEXP];
__device__ int   g_pre[N_NODES];
__device__ int   g_bsum[128];
__device__ int   g_is64;

__device__ __forceinline__ void split_f16(float v, fp16& h, fp16& l) {
    h = __float2half_rn(v);
    l = __float2half_rn(v - __half2float(h));
}

// ---------------------------------------------------------------------------
// Edge dtype detect + CSR
// ---------------------------------------------------------------------------
__global__ void detect_kernel(const int* __restrict__ ei32) {
    if (threadIdx.x == 0) {
        int is64 = 1;
        for (int i = 0; i < 128; i++)
            if (ei32[2 * i + 1] != 0) { is64 = 0; break; }
        g_is64 = is64;
    }
}
__device__ __forceinline__ int edge_val(const int* __restrict__ e, int idx, int is64) {
    return is64 ? e[2 * idx] : e[idx];
}
__global__ void zero_deg_kernel() {
    int i = blockIdx.x * blockDim.x + threadIdx.x;
    if (i < N_NODES) g_deg[i] = 0;
}
__global__ void deg_kernel(const int* __restrict__ ei32) {
    int i = blockIdx.x * blockDim.x + threadIdx.x;
    if (i < N_EDGES) atomicAdd(&g_deg[edge_val(ei32, N_EDGES + i, g_is64)], 1);
}
// two-level scan: block-inclusive -> block sums -> apply
__global__ void scan1_kernel() {
    __shared__ int sm[256];
    int t = threadIdx.x, i = blockIdx.x * 256 + t;
    sm[t] = g_deg[i];
    __syncthreads();
    for (int off = 1; off < 256; off <<= 1) {
        int v = (t >= off) ? sm[t - off] : 0;
        __syncthreads();
        sm[t] += v;
        __syncthreads();
    }
    g_pre[i] = sm[t];
    if (t == 255) g_bsum[blockIdx.x] = sm[255];
}
__global__ void scan2_kernel() {
    __shared__ int sm[128];
    int t = threadIdx.x;
    int orig = g_bsum[t];
    sm[t] = orig;
    __syncthreads();
    for (int off = 1; off < 128; off <<= 1) {
        int v = (t >= off) ? sm[t - off] : 0;
        __syncthreads();
        sm[t] += v;
        __syncthreads();
    }
    g_bsum[t] = sm[t] - orig;            // exclusive block offset
    if (t == 127) g_rowptr[N_NODES] = sm[127];
}
__global__ void scan3_kernel() {
    int i = blockIdx.x * 256 + threadIdx.x;
    int d = g_deg[i];
    int rp = g_bsum[blockIdx.x] + g_pre[i] - d;
    g_rowptr[i] = rp;
    g_cursor[i] = rp;
    g_inv_deg[i] = (d > 0) ? 1.0f / (float)d : 0.0f;
}
__global__ void fill_kernel(const int* __restrict__ ei32) {
    int i = blockIdx.x * blockDim.x + threadIdx.x;
    if (i < N_EDGES) {
        int is64 = g_is64;
        int src = edge_val(ei32, i, is64);
        int dst = edge_val(ei32, N_EDGES + i, is64);
        g_colidx[atomicAdd(&g_cursor[dst], 1)] = src;
    }
}

// ---------------------------------------------------------------------------
// Gate
// ---------------------------------------------------------------------------
__global__ void gate_kernel(const float* __restrict__ x,
                            const float* __restrict__ gW,
                            const float* __restrict__ gb) {
    int gtid = blockIdx.x * blockDim.x + threadIdx.x;
    int node = gtid >> 5, lane = gtid & 31;
    if (node >= N_NODES) return;
    const float* xr = x + (size_t)node * D;
    float a0 = 0.f, a1 = 0.f, a2 = 0.f, a3 = 0.f;
    for (int i = lane; i < D; i += 32) {
        float xv = xr[i];
        float4 w = *(const float4*)&gW[i * 4];
        a0 = fmaf(xv, w.x, a0); a1 = fmaf(xv, w.y, a1);
        a2 = fmaf(xv, w.z, a2); a3 = fmaf(xv, w.w, a3);
    }
#pragma unroll
    for (int off = 16; off; off >>= 1) {
        a0 += __shfl_down_sync(0xffffffffu, a0, off);
        a1 += __shfl_down_sync(0xffffffffu, a1, off);
        a2 += __shfl_down_sync(0xffffffffu, a2, off);
        a3 += __shfl_down_sync(0xffffffffu, a3, off);
    }
    if (lane == 0) {
        float l[4] = {a0 + gb[0], a1 + gb[1], a2 + gb[2], a3 + gb[3]};
        float m = fmaxf(fmaxf(l[0], l[1]), fmaxf(l[2], l[3]));
        float e[4], s = 0.f;
#pragma unroll
        for (int k = 0; k < 4; k++) { e[k] = expf(l[k] - m); s += e[k]; }
        float inv = 1.0f / s;
        float p[4];
#pragma unroll
        for (int k = 0; k < 4; k++) p[k] = e[k] * inv;
        int i1 = 0;
#pragma unroll
        for (int k = 1; k < 4; k++) if (p[k] > p[i1]) i1 = k;
        int i2 = -1;
#pragma unroll
        for (int k = 0; k < 4; k++) {
            if (k == i1) continue;
            if (i2 < 0 || p[k] > p[i2]) i2 = k;
        }
#pragma unroll
        for (int k = 0; k < 4; k++)
            g_gatew[node * 4 + k] = (k == i1) ? p[i1] : ((k == i2) ? p[i2] : 0.0f);
    }
}

// ---------------------------------------------------------------------------
// Conversions / weight prep / aggregations (unchanged from R8)
// ---------------------------------------------------------------------------
__global__ void convert_x_kernel(const float* __restrict__ x) {
    int i = blockIdx.x * blockDim.x + threadIdx.x;
    float4 v = *(const float4*)&x[(size_t)i * 4];
    union { fp16 b[4]; uint2 u; } ph, pl;
    split_f16(v.x, ph.b[0], pl.b[0]);
    split_f16(v.y, ph.b[1], pl.b[1]);
    split_f16(v.z, ph.b[2], pl.b[2]);
    split_f16(v.w, ph.b[3], pl.b[3]);
    *(uint2*)&g_xhi[(size_t)i * 4] = ph.u;
    *(uint2*)&g_xlo[(size_t)i * 4] = pl.u;
}

__global__ void prep_w_kernel(const float* __restrict__ Wl, const float* __restrict__ Wr) {
    __shared__ float sm[32][33];
    int m = blockIdx.z;
    int k0 = blockIdx.x * 32, n0 = blockIdx.y * 32;
    int tx = threadIdx.x, ty = threadIdx.y;
    const float* W = (k0 < 512) ? (Wl + (size_t)m * 512 * 512 + (size_t)(k0 + ty) * 512)
                                : (Wr + (size_t)m * 512 * 512 + (size_t)(k0 - 512 + ty) * 512);
    sm[ty][tx] = W[n0 + tx];
    __syncthreads();
    float v = sm[tx][ty];
    fp16 h, l;
    split_f16(v, h, l);
    size_t o = (size_t)m * 512 * 1024 + (size_t)(n0 + ty) * 1024 + (k0 + tx);
    g_wthi[o] = h;
    g_wtlo[o] = l;
}

__global__ void aggregate_x_kernel(const float* __restrict__ x) {
    int node = blockIdx.x;
    int c = threadIdx.x * 4;
    float4 acc = make_float4(0.f, 0.f, 0.f, 0.f);
    int beg = g_rowptr[node], end = g_rowptr[node + 1];
    for (int j = beg; j < end; j++) {
        float4 v = *(const float4*)&x[(size_t)g_colidx[j] * D + c];
        acc.x += v.x; acc.y += v.y; acc.z += v.z; acc.w += v.w;
    }
    float inv = g_inv_deg[node];
    union { fp16 b[4]; uint2 u; } ph, pl;
    split_f16(acc.x * inv, ph.b[0], pl.b[0]);
    split_f16(acc.y * inv, ph.b[1], pl.b[1]);
    split_f16(acc.z * inv, ph.b[2], pl.b[2]);
    split_f16(acc.w * inv, ph.b[3], pl.b[3]);
    *(uint2*)&g_ahi[(size_t)node * D + c] = ph.u;
    *(uint2*)&g_alo[(size_t)node * D + c] = pl.u;
}

__global__ void aggregate_h_kernel(int expert) {
    const fp16* __restrict__ hh = g_h1hi + (size_t)expert * ND;
    const fp16* __restrict__ hl = g_h1lo + (size_t)expert * ND;
    int node = blockIdx.x;
    int c = threadIdx.x * 4;
    float4 acc = make_float4(0.f, 0.f, 0.f, 0.f);
    int beg = g_rowptr[node], end = g_rowptr[node + 1];
    for (int j = beg; j < end; j++) {
        size_t base = (size_t)g_colidx[j] * D + c;
        union { fp16 b[4]; uint2 u; } vh, vl;
        vh.u = *(const uint2*)&hh[base];
        vl.u = *(const uint2*)&hl[base];
        acc.x += __half2float(vh.b[0]) + __half2float(vl.b[0]);
        acc.y += __half2float(vh.b[1]) + __half2float(vl.b[1]);
        acc.z += __half2float(vh.b[2]) + __half2float(vl.b[2]);
        acc.w += __half2float(vh.b[3]) + __half2float(vl.b[3]);
    }
    float inv = g_inv_deg[node];
    union { fp16 b[4]; uint2 u; } ph, pl;
    split_f16(acc.x * inv, ph.b[0], pl.b[0]);
    split_f16(acc.y * inv, ph.b[1], pl.b[1]);
    split_f16(acc.z * inv, ph.b[2], pl.b[2]);
    split_f16(acc.w * inv, ph.b[3], pl.b[3]);
    *(uint2*)&g_ahi[(size_t)node * D + c] = ph.u;
    *(uint2*)&g_alo[(size_t)node * D + c] = pl.u;
}

// ---------------------------------------------------------------------------
// Tensor-core GEMM: ldmatrix + cp.async 2-stage pipeline.
// BM=BN=128, BK=32, 256 threads (8 warps 2x4, warp tile 64x32), K=1024 fused.
// ---------------------------------------------------------------------------
#define ROWB 80
#define TILE_B (128 * ROWB)      // 10240
#define STAGE_B (4 * TILE_B)     // 40960: [Ahi, Alo, Bhi, Blo]
#define GEMM_SMEM (2 * STAGE_B)  // 81920 (epilogue 67584 fits)

__device__ __forceinline__ uint32_t smem_u32(const void* p) {
    uint32_t a;
    asm("{ .reg .u64 t; cvta.to.shared.u64 t, %1; cvt.u32.u64 %0, t; }"
        : "=r"(a) : "l"(p));
    return a;
}
__device__ __forceinline__ void cp16(uint32_t dst, const void* src) {
    asm volatile("cp.async.cg.shared.global [%0], [%1], 16;" :: "r"(dst), "l"(src));
}
__device__ __forceinline__ void ldmx4(uint32_t* r, uint32_t addr) {
    asm volatile("ldmatrix.sync.aligned.m8n8.x4.shared.b16 {%0,%1,%2,%3}, [%4];"
                 : "=r"(r[0]), "=r"(r[1]), "=r"(r[2]), "=r"(r[3]) : "r"(addr));
}
__device__ __forceinline__ void mma16816(float* c, const uint32_t* a, const uint32_t* b) {
    asm volatile("mma.sync.aligned.m16n8k16.row.col.f32.f16.f16.f32 "
                 "{%0,%1,%2,%3}, {%4,%5,%6,%7}, {%8,%9}, {%0,%1,%2,%3};"
                 : "+f"(c[0]), "+f"(c[1]), "+f"(c[2]), "+f"(c[3])
                 : "r"(a[0]), "r"(a[1]), "r"(a[2]), "r"(a[3]), "r"(b[0]), "r"(b[1]));
}

__global__ void __launch_bounds__(256, 1)
sage_gemm_mma(int a_sel, int w_idx, const float* __restrict__ bias,
              int store_expert, float* __restrict__ out, int gate_e) {
    extern __shared__ char smem[];
    uint32_t sb = smem_u32(smem);
    int tid = threadIdx.x, lane = tid & 31, wid = tid >> 5;
    int wm = wid >> 2, wn = wid & 3;
    int g = lane >> 2, lam = lane & 3;
    int bn = blockIdx.x * 128, bm = blockIdx.y * 128;

    // device-side pointer resolution (never pass __device__ symbols from host)
    const fp16* __restrict__ ahh = (a_sel < 0) ? g_xhi : g_h1hi + (size_t)a_sel * ND;
    const fp16* __restrict__ ahl = (a_sel < 0) ? g_xlo : g_h1lo + (size_t)a_sel * ND;
    const fp16* __restrict__ bh = g_wthi + (size_t)w_idx * 512 * 1024;
    const fp16* __restrict__ bl = g_wtlo + (size_t)w_idx * 512 * 1024;

    float c[4][4][4];
#pragma unroll
    for (int i = 0; i < 4; i++)
#pragma unroll
        for (int j = 0; j < 4; j++)
#pragma unroll
            for (int q = 0; q < 4; q++) c[i][j][q] = 0.f;

    int row_s = tid >> 2, kc_s = tid & 3;
    int row_s2 = (tid + 256) >> 2, kc_s2 = (tid + 256) & 3;

    auto load_stage = [&](int n) {
        uint32_t st = sb + (n & 1) * STAGE_B;
        const fp16 *Ah, *Al;
        int ka;
        if (n < 16) { Ah = g_ahi; Al = g_alo; ka = n * 32; }
        else        { Ah = ahh;   Al = ahl;   ka = (n - 16) * 32; }
        int kb = n * 32;
        uint32_t d1 = st + row_s * ROWB + kc_s * 16;
        uint32_t d2 = st + row_s2 * ROWB + kc_s2 * 16;
        cp16(d1 + 0 * TILE_B, Ah + (size_t)(bm + row_s) * 512 + ka + kc_s * 8);
        cp16(d2 + 0 * TILE_B, Ah + (size_t)(bm + row_s2) * 512 + ka + kc_s2 * 8);
        cp16(d1 + 1 * TILE_B, Al + (size_t)(bm + row_s) * 512 + ka + kc_s * 8);
        cp16(d2 + 1 * TILE_B, Al + (size_t)(bm + row_s2) * 512 + ka + kc_s2 * 8);
        cp16(d1 + 2 * TILE_B, bh + (size_t)(bn + row_s) * 1024 + kb + kc_s * 8);
        cp16(d2 + 2 * TILE_B, bh + (size_t)(bn + row_s2) * 1024 + kb + kc_s2 * 8);
        cp16(d1 + 3 * TILE_B, bl + (size_t)(bn + row_s) * 1024 + kb + kc_s * 8);
        cp16(d2 + 3 * TILE_B, bl + (size_t)(bn + row_s2) * 1024 + kb + kc_s2 * 8);
    };

    load_stage(0);
    asm volatile("cp.async.commit_group;");

    for (int it = 0; it < 32; it++) {
        int buf = it & 1;
        if (it + 1 < 32) {
            load_stage(it + 1);
            asm volatile("cp.async.commit_group;");
            asm volatile("cp.async.wait_group 1;");
        } else {
            asm volatile("cp.async.wait_group 0;");
        }
        __syncthreads();

        uint32_t st = sb + buf * STAGE_B;
#pragma unroll
        for (int ks = 0; ks < 2; ks++) {
            uint32_t aH[4][4], aL[4][4], bH[4][2], bL[4][2];
            // A: x4 ldmatrix; lanes 0-15 rows, lanes>=16 k+8 halves (verified
            // equivalent to R8's direct-LDS fragment layout)
#pragma unroll
            for (int mb = 0; mb < 4; mb++) {
                uint32_t ra = st + (wm * 64 + mb * 16 + (lane & 15)) * ROWB
                              + ks * 32 + ((lane >> 4) << 4);
                ldmx4(aH[mb], ra);
                ldmx4(aL[mb], ra + TILE_B);
            }
            // B: x4 ldmatrix covering two n8 blocks
#pragma unroll
            for (int np = 0; np < 2; np++) {
                int brow = wn * 32 + np * 16 + (lane & 7) + ((lane & 16) ? 8 : 0);
                uint32_t rb = st + 2 * TILE_B + brow * ROWB + ks * 32
                              + ((lane & 8) ? 16 : 0);
                uint32_t q[4];
                ldmx4(q, rb);
                bH[np * 2][0] = q[0]; bH[np * 2][1] = q[1];
                bH[np * 2 + 1][0] = q[2]; bH[np * 2 + 1][1] = q[3];
                ldmx4(q, rb + TILE_B);
                bL[np * 2][0] = q[0]; bL[np * 2][1] = q[1];
                bL[np * 2 + 1][0] = q[2]; bL[np * 2 + 1][1] = q[3];
            }
#pragma unroll
            for (int mb = 0; mb < 4; mb++)
#pragma unroll
                for (int nb = 0; nb < 4; nb++) {
                    mma16816(c[mb][nb], aH[mb], bH[nb]);
                    mma16816(c[mb][nb], aH[mb], bL[nb]);
                    mma16816(c[mb][nb], aL[mb], bH[nb]);
                }
        }
        __syncthreads();
    }

    // Epilogue (unchanged, verified): fragments -> SMEM fp32 -> coalesced
    float* sep = (float*)smem;  // [128][132] = 67584 <= 81920
#pragma unroll
    for (int mb = 0; mb < 4; mb++)
#pragma unroll
        for (int nb = 0; nb < 4; nb++)
#pragma unroll
            for (int q = 0; q < 4; q++) {
                int row = wm * 64 + mb * 16 + g + ((q >> 1) << 3);
                int col = wn * 32 + nb * 8 + 2 * lam + (q & 1);
                sep[row * 132 + col] = c[mb][nb][q];
            }
    __syncthreads();

    if (store_expert >= 0) {
        fp16* ohi = g_h1hi + (size_t)store_expert * ND;
        fp16* olo = g_h1lo + (size_t)store_expert * ND;
        int w = tid & 63, rs = tid >> 6;
        float b0 = bias[bn + 2 * w], b1 = bias[bn + 2 * w + 1];
#pragma unroll
        for (int it = 0; it < 32; it++) {
            int rr = rs + it * 4;
            float v0 = fmaxf(sep[rr * 132 + 2 * w] + b0, 0.f);
            float v1 = fmaxf(sep[rr * 132 + 2 * w + 1] + b1, 0.f);
            union { fp16 b[2]; uint32_t u; } ph, pl;
            split_f16(v0, ph.b[0], pl.b[0]);
            split_f16(v1, ph.b[1], pl.b[1]);
            size_t o = (size_t)(bm + rr) * D + bn + 2 * w;
            *(uint32_t*)&ohi[o] = ph.u;
            *(uint32_t*)&olo[o] = pl.u;
        }
    } else {
        float4 bc = *(const float4*)&bias[bn + lane * 4];
#pragma unroll
        for (int it = 0; it < 16; it++) {
            int rr = wid + it * 8;
            int m = bm + rr;
            float gw = g_gatew[m * 4 + gate_e];
            if (gw != 0.f) {
                float* p = out + (size_t)m * D + bn + lane * 4;
                float4 cur = *(float4*)p;
                cur.x += gw * fmaxf(sep[rr * 132 + lane * 4 + 0] + bc.x, 0.f);
                cur.y += gw * fmaxf(sep[rr * 132 + lane * 4 + 1] + bc.y, 0.f);
                cur.z += gw * fmaxf(sep[rr * 132 + lane * 4 + 2] + bc.z, 0.f);
                cur.w += gw * fmaxf(sep[rr * 132 + lane * 4 + 3] + bc.w, 0.f);
                *(float4*)p = cur;
            }
        }
    }
}

// ---------------------------------------------------------------------------
// Launch — only harness pointers and integers cross the host boundary.
// ---------------------------------------------------------------------------
extern "C" void kernel_launch(void* const* d_in, const int* in_sizes, int n_in,
                              void* d_out, int out_size) {
    const float* x = 0; const float* gW = 0; const float* gb = 0;
    const float* Wl = 0; const float* blv = 0; const float* Wr = 0;
    const int*   ei = 0;
    for (int i = 0; i < n_in; i++) {
        long long s = in_sizes[i];
        if (s == 16777216)      { if (!x)  x  = (const float*)d_in[i]; }
        else if (s == 2048)     { if (!gW) gW = (const float*)d_in[i]; }
        else if (s == 4)        { if (!gb) gb = (const float*)d_in[i]; }
        else if (s == 2097152)  { if (!Wl) Wl = (const float*)d_in[i];
                                  else if (!Wr) Wr = (const float*)d_in[i]; }
        else if (s == 4096)     { if (!blv) blv = (const float*)d_in[i]; }
        else if (s == 524288)   { if (!ei) ei = (const int*)d_in[i]; }
    }
    if (!x)   x   = (const float*)d_in[0];
    if (!gW)  gW  = (const float*)d_in[1];
    if (!gb)  gb  = (const float*)d_in[2];
    if (!Wl)  Wl  = (const float*)d_in[3];
    if (!blv) blv = (const float*)d_in[4];
    if (!Wr)  Wr  = (const float*)d_in[5];
    if (!ei)  ei  = (const int*)d_in[6];
    float* out = (float*)d_out;

    cudaFuncSetAttribute(sage_gemm_mma,
                         cudaFuncAttributeMaxDynamicSharedMemorySize, GEMM_SMEM);

    detect_kernel<<<1, 32>>>(ei);
    zero_deg_kernel<<<N_NODES / 256, 256>>>();
    deg_kernel<<<N_EDGES / 256, 256>>>(ei);
    scan1_kernel<<<128, 256>>>();
    scan2_kernel<<<1, 128>>>();
    scan3_kernel<<<128, 256>>>();
    fill_kernel<<<N_EDGES / 256, 256>>>(ei);
    gate_kernel<<<N_NODES / 8, 256>>>(x, gW, gb);
    convert_x_kernel<<<ND / 4 / 256, 256>>>(x);
    prep_w_kernel<<<dim3(32, 16, 8), dim3(32, 32)>>>(Wl, Wr);

    dim3 gg(D / 128, N_NODES / 128);  // (4, 256)

    // Layer 1 (shared aggr(x)); a_sel=-1 -> x, store h1[e]
    aggregate_x_kernel<<<N_NODES, 128>>>(x);
    for (int e = 0; e < NEXP; e++)
        sage_gemm_mma<<<gg, 256, GEMM_SMEM>>>(-1, e * 2, blv + (e * 2) * 512,
                                              e, out, -1);

    // Layer 2 + fused gated combine; a_sel=e -> h1[e]
    cudaMemsetAsync(out, 0, (size_t)out_size * sizeof(float));
    for (int e = 0; e < NEXP; e++) {
        aggregate_h_kernel<<<N_NODES, 128>>>(e);
        sage_gemm_mma<<<gg, 256, GEMM_SMEM>>>(e, e * 2 + 1, blv + (e * 2 + 1) * 512,
                                              -1, out, e);
    }
}

// round 10
// speedup vs baseline: 2.1935x; 1.2856x over previous
#include <cuda_runtime.h>
#include <cuda_fp16.h>
#include <cstdint>

// ---------------------------------------------------------------------------
// MoE GraphSAGE, mma.sync m16n8k16 fp16 (fp32 accum), fp16x3 split GEMM.
// R10: layer-2 row compaction (skip gate-zero rows: -50% of layer-2 GEMM and
// aggregation work), batched layer-1 GEMM (gridDim.z=4).
// __device__ globals resolved ONLY in device code (R7 ATS lesson).
// ---------------------------------------------------------------------------

#define N_NODES 32768
#define N_EDGES 262144
#define D 512
#define NEXP 4
#define ND (N_NODES * D)

typedef __half fp16;

__device__ fp16  g_xhi[ND], g_xlo[ND];
__device__ fp16  g_ahi[ND], g_alo[ND];            // layer-1 aggr (all nodes)
__device__ fp16  g_cahi[(size_t)NEXP * ND];       // layer-2 compact aggr
__device__ fp16  g_calo[(size_t)NEXP * ND];
__device__ fp16  g_h1hi[(size_t)NEXP * ND];
__device__ fp16  g_h1lo[(size_t)NEXP * ND];
__device__ fp16  g_wthi[8ull * 512 * 1024];       // [w_idx][n][k]
__device__ fp16  g_wtlo[8ull * 512 * 1024];
__device__ float g_inv_deg[N_NODES];
__device__ int   g_deg[N_NODES];
__device__ int   g_rowptr[N_NODES + 1];
__device__ int   g_cursor[N_NODES];
__device__ int   g_colidx[N_EDGES];
__device__ float g_gatew[N_NODES * NEXP];
__device__ int   g_rows[NEXP][N_NODES];           // compacted active rows
__device__ int   g_cnt[NEXP];
__device__ int   g_pre[N_NODES];
__device__ int   g_bsum[128];
__device__ int   g_is64;

__device__ __forceinline__ void split_f16(float v, fp16& h, fp16& l) {
    h = __float2half_rn(v);
    l = __float2half_rn(v - __half2float(h));
}

// ---------------------------------------------------------------------------
// Edge dtype detect + CSR
// ---------------------------------------------------------------------------
__global__ void detect_kernel(const int* __restrict__ ei32) {
    if (threadIdx.x == 0) {
        int is64 = 1;
        for (int i = 0; i < 128; i++)
            if (ei32[2 * i + 1] != 0) { is64 = 0; break; }
        g_is64 = is64;
    }
}
__device__ __forceinline__ int edge_val(const int* __restrict__ e, int idx, int is64) {
    return is64 ? e[2 * idx] : e[idx];
}
__global__ void zero_deg_kernel() {
    int i = blockIdx.x * blockDim.x + threadIdx.x;
    if (i < N_NODES) g_deg[i] = 0;
    if (i < NEXP) g_cnt[i] = 0;
}
__global__ void deg_kernel(const int* __restrict__ ei32) {
    int i = blockIdx.x * blockDim.x + threadIdx.x;
    if (i < N_EDGES) atomicAdd(&g_deg[edge_val(ei32, N_EDGES + i, g_is64)], 1);
}
__global__ void scan1_kernel() {
    __shared__ int sm[256];
    int t = threadIdx.x, i = blockIdx.x * 256 + t;
    sm[t] = g_deg[i];
    __syncthreads();
    for (int off = 1; off < 256; off <<= 1) {
        int v = (t >= off) ? sm[t - off] : 0;
        __syncthreads();
        sm[t] += v;
        __syncthreads();
    }
    g_pre[i] = sm[t];
    if (t == 255) g_bsum[blockIdx.x] = sm[255];
}
__global__ void scan2_kernel() {
    __shared__ int sm[128];
    int t = threadIdx.x;
    int orig = g_bsum[t];
    sm[t] = orig;
    __syncthreads();
    for (int off = 1; off < 128; off <<= 1) {
        int v = (t >= off) ? sm[t - off] : 0;
        __syncthreads();
        sm[t] += v;
        __syncthreads();
    }
    g_bsum[t] = sm[t] - orig;
    if (t == 127) g_rowptr[N_NODES] = sm[127];
}
__global__ void scan3_kernel() {
    int i = blockIdx.x * 256 + threadIdx.x;
    int d = g_deg[i];
    int rp = g_bsum[blockIdx.x] + g_pre[i] - d;
    g_rowptr[i] = rp;
    g_cursor[i] = rp;
    g_inv_deg[i] = (d > 0) ? 1.0f / (float)d : 0.0f;
}
__global__ void fill_kernel(const int* __restrict__ ei32) {
    int i = blockIdx.x * blockDim.x + threadIdx.x;
    if (i < N_EDGES) {
        int is64 = g_is64;
        int src = edge_val(ei32, i, is64);
        int dst = edge_val(ei32, N_EDGES + i, is64);
        g_colidx[atomicAdd(&g_cursor[dst], 1)] = src;
    }
}

// ---------------------------------------------------------------------------
// Gate + active-row list build
// ---------------------------------------------------------------------------
__global__ void gate_kernel(const float* __restrict__ x,
                            const float* __restrict__ gW,
                            const float* __restrict__ gb) {
    int gtid = blockIdx.x * blockDim.x + threadIdx.x;
    int node = gtid >> 5, lane = gtid & 31;
    if (node >= N_NODES) return;
    const float* xr = x + (size_t)node * D;
    float a0 = 0.f, a1 = 0.f, a2 = 0.f, a3 = 0.f;
    for (int i = lane; i < D; i += 32) {
        float xv = xr[i];
        float4 w = *(const float4*)&gW[i * 4];
        a0 = fmaf(xv, w.x, a0); a1 = fmaf(xv, w.y, a1);
        a2 = fmaf(xv, w.z, a2); a3 = fmaf(xv, w.w, a3);
    }
#pragma unroll
    for (int off = 16; off; off >>= 1) {
        a0 += __shfl_down_sync(0xffffffffu, a0, off);
        a1 += __shfl_down_sync(0xffffffffu, a1, off);
        a2 += __shfl_down_sync(0xffffffffu, a2, off);
        a3 += __shfl_down_sync(0xffffffffu, a3, off);
    }
    if (lane == 0) {
        float l[4] = {a0 + gb[0], a1 + gb[1], a2 + gb[2], a3 + gb[3]};
        float m = fmaxf(fmaxf(l[0], l[1]), fmaxf(l[2], l[3]));
        float e[4], s = 0.f;
#pragma unroll
        for (int k = 0; k < 4; k++) { e[k] = expf(l[k] - m); s += e[k]; }
        float inv = 1.0f / s;
        float p[4];
#pragma unroll
        for (int k = 0; k < 4; k++) p[k] = e[k] * inv;
        int i1 = 0;
#pragma unroll
        for (int k = 1; k < 4; k++) if (p[k] > p[i1]) i1 = k;
        int i2 = -1;
#pragma unroll
        for (int k = 0; k < 4; k++) {
            if (k == i1) continue;
            if (i2 < 0 || p[k] > p[i2]) i2 = k;
        }
#pragma unroll
        for (int k = 0; k < 4; k++)
            g_gatew[node * 4 + k] = (k == i1) ? p[i1] : ((k == i2) ? p[i2] : 0.0f);
        int p1 = atomicAdd(&g_cnt[i1], 1);
        g_rows[i1][p1] = node;
        int p2 = atomicAdd(&g_cnt[i2], 1);
        g_rows[i2][p2] = node;
    }
}

// ---------------------------------------------------------------------------
// Conversions / weight prep
// ---------------------------------------------------------------------------
__global__ void convert_x_kernel(const float* __restrict__ x) {
    int i = blockIdx.x * blockDim.x + threadIdx.x;
    float4 v = *(const float4*)&x[(size_t)i * 4];
    union { fp16 b[4]; uint2 u; } ph, pl;
    split_f16(v.x, ph.b[0], pl.b[0]);
    split_f16(v.y, ph.b[1], pl.b[1]);
    split_f16(v.z, ph.b[2], pl.b[2]);
    split_f16(v.w, ph.b[3], pl.b[3]);
    *(uint2*)&g_xhi[(size_t)i * 4] = ph.u;
    *(uint2*)&g_xlo[(size_t)i * 4] = pl.u;
}

__global__ void prep_w_kernel(const float* __restrict__ Wl, const float* __restrict__ Wr) {
    __shared__ float sm[32][33];
    int m = blockIdx.z;
    int k0 = blockIdx.x * 32, n0 = blockIdx.y * 32;
    int tx = threadIdx.x, ty = threadIdx.y;
    const float* W = (k0 < 512) ? (Wl + (size_t)m * 512 * 512 + (size_t)(k0 + ty) * 512)
                                : (Wr + (size_t)m * 512 * 512 + (size_t)(k0 - 512 + ty) * 512);
    sm[ty][tx] = W[n0 + tx];
    __syncthreads();
    float v = sm[tx][ty];
    fp16 h, l;
    split_f16(v, h, l);
    size_t o = (size_t)m * 512 * 1024 + (size_t)(n0 + ty) * 1024 + (k0 + tx);
    g_wthi[o] = h;
    g_wtlo[o] = l;
}

// ---------------------------------------------------------------------------
// Aggregations
// ---------------------------------------------------------------------------
__global__ void aggregate_x_kernel(const float* __restrict__ x) {
    int node = blockIdx.x;
    int c = threadIdx.x * 4;
    float4 acc = make_float4(0.f, 0.f, 0.f, 0.f);
    int beg = g_rowptr[node], end = g_rowptr[node + 1];
    for (int j = beg; j < end; j++) {
        float4 v = *(const float4*)&x[(size_t)g_colidx[j] * D + c];
        acc.x += v.x; acc.y += v.y; acc.z += v.z; acc.w += v.w;
    }
    float inv = g_inv_deg[node];
    union { fp16 b[4]; uint2 u; } ph, pl;
    split_f16(acc.x * inv, ph.b[0], pl.b[0]);
    split_f16(acc.y * inv, ph.b[1], pl.b[1]);
    split_f16(acc.z * inv, ph.b[2], pl.b[2]);
    split_f16(acc.w * inv, ph.b[3], pl.b[3]);
    *(uint2*)&g_ahi[(size_t)node * D + c] = ph.u;
    *(uint2*)&g_alo[(size_t)node * D + c] = pl.u;
}

// layer-2: compact aggregation, grid (N_NODES, NEXP); early-exit above cnt.
__global__ void aggregate_h2_kernel() {
    int e = blockIdx.y;
    int i = blockIdx.x;
    if (i >= g_cnt[e]) return;
    int node = g_rows[e][i];
    const fp16* __restrict__ hh = g_h1hi + (size_t)e * ND;
    const fp16* __restrict__ hl = g_h1lo + (size_t)e * ND;
    int c = threadIdx.x * 4;
    float4 acc = make_float4(0.f, 0.f, 0.f, 0.f);
    int beg = g_rowptr[node], end = g_rowptr[node + 1];
    for (int j = beg; j < end; j++) {
        size_t base = (size_t)g_colidx[j] * D + c;
        union { fp16 b[4]; uint2 u; } vh, vl;
        vh.u = *(const uint2*)&hh[base];
        vl.u = *(const uint2*)&hl[base];
        acc.x += __half2float(vh.b[0]) + __half2float(vl.b[0]);
        acc.y += __half2float(vh.b[1]) + __half2float(vl.b[1]);
        acc.z += __half2float(vh.b[2]) + __half2float(vl.b[2]);
        acc.w += __half2float(vh.b[3]) + __half2float(vl.b[3]);
    }
    float inv = g_inv_deg[node];
    union { fp16 b[4]; uint2 u; } ph, pl;
    split_f16(acc.x * inv, ph.b[0], pl.b[0]);
    split_f16(acc.y * inv, ph.b[1], pl.b[1]);
    split_f16(acc.z * inv, ph.b[2], pl.b[2]);
    split_f16(acc.w * inv, ph.b[3], pl.b[3]);
    size_t o = (size_t)e * ND + (size_t)i * D + c;   // dense compact slot
    *(uint2*)&g_cahi[o] = ph.u;
    *(uint2*)&g_calo[o] = pl.u;
}

// ---------------------------------------------------------------------------
// Tensor-core GEMM: ldmatrix + cp.async 2-stage pipeline (R9-verified).
// layer==1: grid (4,256,4), z=expert, dense rows, store h1[e].
// layer==2: grid (4,256,1), expert passed; compacted rows (early-exit),
//           aggr phase reads dense compact buffer, h1 phase gathers via list,
//           epilogue read-modify-writes out at the listed rows.
// ---------------------------------------------------------------------------
#define ROWB 80
#define TILE_B (128 * ROWB)
#define STAGE_B (4 * TILE_B)
#define GEMM_SMEM (2 * STAGE_B)

__device__ __forceinline__ uint32_t smem_u32(const void* p) {
    uint32_t a;
    asm("{ .reg .u64 t; cvta.to.shared.u64 t, %1; cvt.u32.u64 %0, t; }"
        : "=r"(a) : "l"(p));
    return a;
}
__device__ __forceinline__ void cp16(uint32_t dst, const void* src) {
    asm volatile("cp.async.cg.shared.global [%0], [%1], 16;" :: "r"(dst), "l"(src));
}
__device__ __forceinline__ void ldmx4(uint32_t* r, uint32_t addr) {
    asm volatile("ldmatrix.sync.aligned.m8n8.x4.shared.b16 {%0,%1,%2,%3}, [%4];"
                 : "=r"(r[0]), "=r"(r[1]), "=r"(r[2]), "=r"(r[3]) : "r"(addr));
}
__device__ __forceinline__ void mma16816(float* c, const uint32_t* a, const uint32_t* b) {
    asm volatile("mma.sync.aligned.m16n8k16.row.col.f32.f16.f16.f32 "
                 "{%0,%1,%2,%3}, {%4,%5,%6,%7}, {%8,%9}, {%0,%1,%2,%3};"
                 : "+f"(c[0]), "+f"(c[1]), "+f"(c[2]), "+f"(c[3])
                 : "r"(a[0]), "r"(a[1]), "r"(a[2]), "r"(a[3]), "r"(b[0]), "r"(b[1]));
}

__global__ void __launch_bounds__(256, 1)
sage_gemm_mma(int layer, int expert_arg, const float* __restrict__ blv,
              float* __restrict__ out) {
    extern __shared__ char smem[];
    uint32_t sb = smem_u32(smem);
    int tid = threadIdx.x, lane = tid & 31, wid = tid >> 5;
    int wm = wid >> 2, wn = wid & 3;
    int g = lane >> 2, lam = lane & 3;
    int bn = blockIdx.x * 128, bm = blockIdx.y * 128;
    int e = (gridDim.z > 1) ? (int)blockIdx.z : expert_arg;
    int w_idx = (layer == 1) ? 2 * e : 2 * e + 1;
    const float* __restrict__ bias = blv + w_idx * 512;

    int cnt = 0;
    if (layer == 2) {
        cnt = g_cnt[e];
        if (bm >= cnt) return;
    }

    const fp16* __restrict__ bh = g_wthi + (size_t)w_idx * 512 * 1024;
    const fp16* __restrict__ bl = g_wtlo + (size_t)w_idx * 512 * 1024;

    int row_s = tid >> 2, kc_s = tid & 3;
    int row_s2 = (tid + 256) >> 2, kc_s2 = (tid + 256) & 3;

    // A-row global offsets (constant across the k loop)
    size_t aoff_s, aoff_s2;   // aggr phase (chunks 0-15)
    size_t hoff_s, hoff_s2;   // own-feature phase (chunks 16-31)
    const fp16 *p_ah, *p_al, *p_hh, *p_hl;
    if (layer == 1) {
        p_ah = g_ahi; p_al = g_alo;
        p_hh = g_xhi; p_hl = g_xlo;
        aoff_s = (size_t)(bm + row_s) * 512;  aoff_s2 = (size_t)(bm + row_s2) * 512;
        hoff_s = aoff_s;                      hoff_s2 = aoff_s2;
    } else {
        p_ah = g_cahi + (size_t)e * ND; p_al = g_calo + (size_t)e * ND;
        p_hh = g_h1hi + (size_t)e * ND; p_hl = g_h1lo + (size_t)e * ND;
        int cr_s = min(bm + row_s, cnt - 1), cr_s2 = min(bm + row_s2, cnt - 1);
        aoff_s = (size_t)cr_s * 512;  aoff_s2 = (size_t)cr_s2 * 512;
        hoff_s = (size_t)g_rows[e][cr_s] * 512;
        hoff_s2 = (size_t)g_rows[e][cr_s2] * 512;
    }

    float c[4][4][4];
#pragma unroll
    for (int i = 0; i < 4; i++)
#pragma unroll
        for (int j = 0; j < 4; j++)
#pragma unroll
            for (int q = 0; q < 4; q++) c[i][j][q] = 0.f;

    auto load_stage = [&](int n) {
        uint32_t st = sb + (n & 1) * STAGE_B;
        int ka = (n & 15) * 32, kb = n * 32;
        const fp16 *Ah, *Al;
        size_t o1, o2;
        if (n < 16) { Ah = p_ah; Al = p_al; o1 = aoff_s; o2 = aoff_s2; }
        else        { Ah = p_hh; Al = p_hl; o1 = hoff_s; o2 = hoff_s2; }
        uint32_t d1 = st + row_s * ROWB + kc_s * 16;
        uint32_t d2 = st + row_s2 * ROWB + kc_s2 * 16;
        cp16(d1 + 0 * TILE_B, Ah + o1 + ka + kc_s * 8);
        cp16(d2 + 0 * TILE_B, Ah + o2 + ka + kc_s2 * 8);
        cp16(d1 + 1 * TILE_B, Al + o1 + ka + kc_s * 8);
        cp16(d2 + 1 * TILE_B, Al + o2 + ka + kc_s2 * 8);
        cp16(d1 + 2 * TILE_B, bh + (size_t)(bn + row_s) * 1024 + kb + kc_s * 8);
        cp16(d2 + 2 * TILE_B, bh + (size_t)(bn + row_s2) * 1024 + kb + kc_s2 * 8);
        cp16(d1 + 3 * TILE_B, bl + (size_t)(bn + row_s) * 1024 + kb + kc_s * 8);
        cp16(d2 + 3 * TILE_B, bl + (size_t)(bn + row_s2) * 1024 + kb + kc_s2 * 8);
    };

    load_stage(0);
    asm volatile("cp.async.commit_group;");

    for (int it = 0; it < 32; it++) {
        int buf = it & 1;
        if (it + 1 < 32) {
            load_stage(it + 1);
            asm volatile("cp.async.commit_group;");
            asm volatile("cp.async.wait_group 1;");
        } else {
            asm volatile("cp.async.wait_group 0;");
        }
        __syncthreads();

        uint32_t st = sb + buf * STAGE_B;
#pragma unroll
        for (int ks = 0; ks < 2; ks++) {
            uint32_t aH[4][4], aL[4][4], bH[4][2], bL[4][2];
#pragma unroll
            for (int mb = 0; mb < 4; mb++) {
                uint32_t ra = st + (wm * 64 + mb * 16 + (lane & 15)) * ROWB
                              + ks * 32 + ((lane >> 4) << 4);
                ldmx4(aH[mb], ra);
                ldmx4(aL[mb], ra + TILE_B);
            }
#pragma unroll
            for (int np = 0; np < 2; np++) {
                int brow = wn * 32 + np * 16 + (lane & 7) + ((lane & 16) ? 8 : 0);
                uint32_t rb = st + 2 * TILE_B + brow * ROWB + ks * 32
                              + ((lane & 8) ? 16 : 0);
                uint32_t q[4];
                ldmx4(q, rb);
                bH[np * 2][0] = q[0]; bH[np * 2][1] = q[1];
                bH[np * 2 + 1][0] = q[2]; bH[np * 2 + 1][1] = q[3];
                ldmx4(q, rb + TILE_B);
                bL[np * 2][0] = q[0]; bL[np * 2][1] = q[1];
                bL[np * 2 + 1][0] = q[2]; bL[np * 2 + 1][1] = q[3];
            }
#pragma unroll
            for (int mb = 0; mb < 4; mb++)
#pragma unroll
                for (int nb = 0; nb < 4; nb++) {
                    mma16816(c[mb][nb], aH[mb], bH[nb]);
                    mma16816(c[mb][nb], aH[mb], bL[nb]);
                    mma16816(c[mb][nb], aL[mb], bH[nb]);
                }
        }
        __syncthreads();
    }

    // Epilogue: fragments -> SMEM fp32 -> coalesced stores
    float* sep = (float*)smem;  // [128][132]
#pragma unroll
    for (int mb = 0; mb < 4; mb++)
#pragma unroll
        for (int nb = 0; nb < 4; nb++)
#pragma unroll
            for (int q = 0; q < 4; q++) {
                int row = wm * 64 + mb * 16 + g + ((q >> 1) << 3);
                int col = wn * 32 + nb * 8 + 2 * lam + (q & 1);
                sep[row * 132 + col] = c[mb][nb][q];
            }
    __syncthreads();

    if (layer == 1) {
        fp16* ohi = g_h1hi + (size_t)e * ND;
        fp16* olo = g_h1lo + (size_t)e * ND;
        int w = tid & 63, rs = tid >> 6;
        float b0 = bias[bn + 2 * w], b1 = bias[bn + 2 * w + 1];
#pragma unroll
        for (int it = 0; it < 32; it++) {
            int rr = rs + it * 4;
            float v0 = fmaxf(sep[rr * 132 + 2 * w] + b0, 0.f);
            float v1 = fmaxf(sep[rr * 132 + 2 * w + 1] + b1, 0.f);
            union { fp16 b[2]; uint32_t u; } ph, pl;
            split_f16(v0, ph.b[0], pl.b[0]);
            split_f16(v1, ph.b[1], pl.b[1]);
            size_t o = (size_t)(bm + rr) * D + bn + 2 * w;
            *(uint32_t*)&ohi[o] = ph.u;
            *(uint32_t*)&olo[o] = pl.u;
        }
    } else {
        float4 bc = *(const float4*)&bias[bn + lane * 4];
#pragma unroll
        for (int it = 0; it < 16; it++) {
            int rr = wid + it * 8;
            if (bm + rr < cnt) {
                int m = g_rows[e][bm + rr];
                float gw = g_gatew[m * 4 + e];
                float* p = out + (size_t)m * D + bn + lane * 4;
                float4 cur = *(float4*)p;
                cur.x += gw * fmaxf(sep[rr * 132 + lane * 4 + 0] + bc.x, 0.f);
                cur.y += gw * fmaxf(sep[rr * 132 + lane * 4 + 1] + bc.y, 0.f);
                cur.z += gw * fmaxf(sep[rr * 132 + lane * 4 + 2] + bc.z, 0.f);
                cur.w += gw * fmaxf(sep[rr * 132 + lane * 4 + 3] + bc.w, 0.f);
                *(float4*)p = cur;
            }
        }
    }
}

// ---------------------------------------------------------------------------
// Launch — only harness pointers and integers cross the host boundary.
// ---------------------------------------------------------------------------
extern "C" void kernel_launch(void* const* d_in, const int* in_sizes, int n_in,
                              void* d_out, int out_size) {
    const float* x = 0; const float* gW = 0; const float* gb = 0;
    const float* Wl = 0; const float* blv = 0; const float* Wr = 0;
    const int*   ei = 0;
    for (int i = 0; i < n_in; i++) {
        long long s = in_sizes[i];
        if (s == 16777216)      { if (!x)  x  = (const float*)d_in[i]; }
        else if (s == 2048)     { if (!gW) gW = (const float*)d_in[i]; }
        else if (s == 4)        { if (!gb) gb = (const float*)d_in[i]; }
        else if (s == 2097152)  { if (!Wl) Wl = (const float*)d_in[i];
                                  else if (!Wr) Wr = (const float*)d_in[i]; }
        else if (s == 4096)     { if (!blv) blv = (const float*)d_in[i]; }
        else if (s == 524288)   { if (!ei) ei = (const int*)d_in[i]; }
    }
    if (!x)   x   = (const float*)d_in[0];
    if (!gW)  gW  = (const float*)d_in[1];
    if (!gb)  gb  = (const float*)d_in[2];
    if (!Wl)  Wl  = (const float*)d_in[3];
    if (!blv) blv = (const float*)d_in[4];
    if (!Wr)  Wr  = (const float*)d_in[5];
    if (!ei)  ei  = (const int*)d_in[6];
    float* out = (float*)d_out;

    cudaFuncSetAttribute(sage_gemm_mma,
                         cudaFuncAttributeMaxDynamicSharedMemorySize, GEMM_SMEM);

    detect_kernel<<<1, 32>>>(ei);
    zero_deg_kernel<<<N_NODES / 256, 256>>>();
    deg_kernel<<<N_EDGES / 256, 256>>>(ei);
    scan1_kernel<<<128, 256>>>();
    scan2_kernel<<<1, 128>>>();
    scan3_kernel<<<128, 256>>>();
    fill_kernel<<<N_EDGES / 256, 256>>>(ei);
    gate_kernel<<<N_NODES / 8, 256>>>(x, gW, gb);
    convert_x_kernel<<<ND / 4 / 256, 256>>>(x);
    prep_w_kernel<<<dim3(32, 16, 8), dim3(32, 32)>>>(Wl, Wr);

    // Layer 1: shared aggr(x), then all 4 experts in ONE batched launch
    aggregate_x_kernel<<<N_NODES, 128>>>(x);
    sage_gemm_mma<<<dim3(4, 256, 4), 256, GEMM_SMEM>>>(1, 0, blv, out);

    // Layer 2: compact aggregations (batched), then 4 sequential compacted
    // GEMMs (stream order keeps the RMW gated-combine race-free)
    cudaMemsetAsync(out, 0, (size_t)out_size * sizeof(float));
    aggregate_h2_kernel<<<dim3(N_NODES, NEXP), 128>>>();
    for (int e = 0; e < NEXP; e++)
        sage_gemm_mma<<<dim3(4, 256, 1), 256, GEMM_SMEM>>>(2, e, blv, out);
}

// round 11
// speedup vs baseline: 2.3765x; 1.0834x over previous
#include <cuda_runtime.h>
#include <cuda_fp16.h>
#include <cstdint>

// ---------------------------------------------------------------------------
// MoE GraphSAGE, mma.sync m16n8k16 fp16 (fp32 accum), fp16x3 split GEMM.
// R11: 3-stage cp.async pipeline (1 barrier/iter), layer-2 batched z=4 launch
// with deterministic atomicAdd combine (exactly 2 contributions per element
// on zeroed out => order-independent bitwise).
// __device__ globals resolved ONLY in device code (R7 ATS lesson).
// ---------------------------------------------------------------------------

#define N_NODES 32768
#define N_EDGES 262144
#define D 512
#define NEXP 4
#define ND (N_NODES * D)

typedef __half fp16;

__device__ fp16  g_xhi[ND], g_xlo[ND];
__device__ fp16  g_ahi[ND], g_alo[ND];            // layer-1 aggr (all nodes)
__device__ fp16  g_cahi[(size_t)NEXP * ND];       // layer-2 compact aggr
__device__ fp16  g_calo[(size_t)NEXP * ND];
__device__ fp16  g_h1hi[(size_t)NEXP * ND];
__device__ fp16  g_h1lo[(size_t)NEXP * ND];
__device__ fp16  g_wthi[8ull * 512 * 1024];       // [w_idx][n][k]
__device__ fp16  g_wtlo[8ull * 512 * 1024];
__device__ float g_inv_deg[N_NODES];
__device__ int   g_deg[N_NODES];
__device__ int   g_rowptr[N_NODES + 1];
__device__ int   g_cursor[N_NODES];
__device__ int   g_colidx[N_EDGES];
__device__ float g_gatew[N_NODES * NEXP];
__device__ int   g_rows[NEXP][N_NODES];
__device__ int   g_cnt[NEXP];
__device__ int   g_pre[N_NODES];
__device__ int   g_bsum[128];
__device__ int   g_is64;

__device__ __forceinline__ void split_f16(float v, fp16& h, fp16& l) {
    h = __float2half_rn(v);
    l = __float2half_rn(v - __half2float(h));
}

// ---------------------------------------------------------------------------
// Edge dtype detect + CSR
// ---------------------------------------------------------------------------
__global__ void detect_kernel(const int* __restrict__ ei32) {
    if (threadIdx.x == 0) {
        int is64 = 1;
        for (int i = 0; i < 128; i++)
            if (ei32[2 * i + 1] != 0) { is64 = 0; break; }
        g_is64 = is64;
    }
}
__device__ __forceinline__ int edge_val(const int* __restrict__ e, int idx, int is64) {
    return is64 ? e[2 * idx] : e[idx];
}
__global__ void zero_deg_kernel() {
    int i = blockIdx.x * blockDim.x + threadIdx.x;
    if (i < N_NODES) g_deg[i] = 0;
    if (i < NEXP) g_cnt[i] = 0;
}
__global__ void deg_kernel(const int* __restrict__ ei32) {
    int i = blockIdx.x * blockDim.x + threadIdx.x;
    if (i < N_EDGES) atomicAdd(&g_deg[edge_val(ei32, N_EDGES + i, g_is64)], 1);
}
__global__ void scan1_kernel() {
    __shared__ int sm[256];
    int t = threadIdx.x, i = blockIdx.x * 256 + t;
    sm[t] = g_deg[i];
    __syncthreads();
    for (int off = 1; off < 256; off <<= 1) {
        int v = (t >= off) ? sm[t - off] : 0;
        __syncthreads();
        sm[t] += v;
        __syncthreads();
    }
    g_pre[i] = sm[t];
    if (t == 255) g_bsum[blockIdx.x] = sm[255];
}
__global__ void scan2_kernel() {
    __shared__ int sm[128];
    int t = threadIdx.x;
    int orig = g_bsum[t];
    sm[t] = orig;
    __syncthreads();
    for (int off = 1; off < 128; off <<= 1) {
        int v = (t >= off) ? sm[t - off] : 0;
        __syncthreads();
        sm[t] += v;
        __syncthreads();
    }
    g_bsum[t] = sm[t] - orig;
    if (t == 127) g_rowptr[N_NODES] = sm[127];
}
__global__ void scan3_kernel() {
    int i = blockIdx.x * 256 + threadIdx.x;
    int d = g_deg[i];
    int rp = g_bsum[blockIdx.x] + g_pre[i] - d;
    g_rowptr[i] = rp;
    g_cursor[i] = rp;
    g_inv_deg[i] = (d > 0) ? 1.0f / (float)d : 0.0f;
}
__global__ void fill_kernel(const int* __restrict__ ei32) {
    int i = blockIdx.x * blockDim.x + threadIdx.x;
    if (i < N_EDGES) {
        int is64 = g_is64;
        int src = edge_val(ei32, i, is64);
        int dst = edge_val(ei32, N_EDGES + i, is64);
        g_colidx[atomicAdd(&g_cursor[dst], 1)] = src;
    }
}

// ---------------------------------------------------------------------------
// Gate + active-row list build
// ---------------------------------------------------------------------------
__global__ void gate_kernel(const float* __restrict__ x,
                            const float* __restrict__ gW,
                            const float* __restrict__ gb) {
    int gtid = blockIdx.x * blockDim.x + threadIdx.x;
    int node = gtid >> 5, lane = gtid & 31;
    if (node >= N_NODES) return;
    const float* xr = x + (size_t)node * D;
    float a0 = 0.f, a1 = 0.f, a2 = 0.f, a3 = 0.f;
    for (int i = lane; i < D; i += 32) {
        float xv = xr[i];
        float4 w = *(const float4*)&gW[i * 4];
        a0 = fmaf(xv, w.x, a0); a1 = fmaf(xv, w.y, a1);
        a2 = fmaf(xv, w.z, a2); a3 = fmaf(xv, w.w, a3);
    }
#pragma unroll
    for (int off = 16; off; off >>= 1) {
        a0 += __shfl_down_sync(0xffffffffu, a0, off);
        a1 += __shfl_down_sync(0xffffffffu, a1, off);
        a2 += __shfl_down_sync(0xffffffffu, a2, off);
        a3 += __shfl_down_sync(0xffffffffu, a3, off);
    }
    if (lane == 0) {
        float l[4] = {a0 + gb[0], a1 + gb[1], a2 + gb[2], a3 + gb[3]};
        float m = fmaxf(fmaxf(l[0], l[1]), fmaxf(l[2], l[3]));
        float e[4], s = 0.f;
#pragma unroll
        for (int k = 0; k < 4; k++) { e[k] = expf(l[k] - m); s += e[k]; }
        float inv = 1.0f / s;
        float p[4];
#pragma unroll
        for (int k = 0; k < 4; k++) p[k] = e[k] * inv;
        int i1 = 0;
#pragma unroll
        for (int k = 1; k < 4; k++) if (p[k] > p[i1]) i1 = k;
        int i2 = -1;
#pragma unroll
        for (int k = 0; k < 4; k++) {
            if (k == i1) continue;
            if (i2 < 0 || p[k] > p[i2]) i2 = k;
        }
#pragma unroll
        for (int k = 0; k < 4; k++)
            g_gatew[node * 4 + k] = (k == i1) ? p[i1] : ((k == i2) ? p[i2] : 0.0f);
        int p1 = atomicAdd(&g_cnt[i1], 1);
        g_rows[i1][p1] = node;
        int p2 = atomicAdd(&g_cnt[i2], 1);
        g_rows[i2][p2] = node;
    }
}

// ---------------------------------------------------------------------------
// Conversions / weight prep
// ---------------------------------------------------------------------------
__global__ void convert_x_kernel(const float* __restrict__ x) {
    int i = blockIdx.x * blockDim.x + threadIdx.x;
    float4 v = *(const float4*)&x[(size_t)i * 4];
    union { fp16 b[4]; uint2 u; } ph, pl;
    split_f16(v.x, ph.b[0], pl.b[0]);
    split_f16(v.y, ph.b[1], pl.b[1]);
    split_f16(v.z, ph.b[2], pl.b[2]);
    split_f16(v.w, ph.b[3], pl.b[3]);
    *(uint2*)&g_xhi[(size_t)i * 4] = ph.u;
    *(uint2*)&g_xlo[(size_t)i * 4] = pl.u;
}

__global__ void prep_w_kernel(const float* __restrict__ Wl, const float* __restrict__ Wr) {
    __shared__ float sm[32][33];
    int m = blockIdx.z;
    int k0 = blockIdx.x * 32, n0 = blockIdx.y * 32;
    int tx = threadIdx.x, ty = threadIdx.y;
    const float* W = (k0 < 512) ? (Wl + (size_t)m * 512 * 512 + (size_t)(k0 + ty) * 512)
                                : (Wr + (size_t)m * 512 * 512 + (size_t)(k0 - 512 + ty) * 512);
    sm[ty][tx] = W[n0 + tx];
    __syncthreads();
    float v = sm[tx][ty];
    fp16 h, l;
    split_f16(v, h, l);
    size_t o = (size_t)m * 512 * 1024 + (size_t)(n0 + ty) * 1024 + (k0 + tx);
    g_wthi[o] = h;
    g_wtlo[o] = l;
}

// ---------------------------------------------------------------------------
// Aggregations
// ---------------------------------------------------------------------------
__global__ void aggregate_x_kernel(const float* __restrict__ x) {
    int node = blockIdx.x;
    int c = threadIdx.x * 4;
    float4 acc = make_float4(0.f, 0.f, 0.f, 0.f);
    int beg = g_rowptr[node], end = g_rowptr[node + 1];
    for (int j = beg; j < end; j++) {
        float4 v = *(const float4*)&x[(size_t)g_colidx[j] * D + c];
        acc.x += v.x; acc.y += v.y; acc.z += v.z; acc.w += v.w;
    }
    float inv = g_inv_deg[node];
    union { fp16 b[4]; uint2 u; } ph, pl;
    split_f16(acc.x * inv, ph.b[0], pl.b[0]);
    split_f16(acc.y * inv, ph.b[1], pl.b[1]);
    split_f16(acc.z * inv, ph.b[2], pl.b[2]);
    split_f16(acc.w * inv, ph.b[3], pl.b[3]);
    *(uint2*)&g_ahi[(size_t)node * D + c] = ph.u;
    *(uint2*)&g_alo[(size_t)node * D + c] = pl.u;
}

__global__ void aggregate_h2_kernel() {
    int e = blockIdx.y;
    int i = blockIdx.x;
    if (i >= g_cnt[e]) return;
    int node = g_rows[e][i];
    const fp16* __restrict__ hh = g_h1hi + (size_t)e * ND;
    const fp16* __restrict__ hl = g_h1lo + (size_t)e * ND;
    int c = threadIdx.x * 4;
    float4 acc = make_float4(0.f, 0.f, 0.f, 0.f);
    int beg = g_rowptr[node], end = g_rowptr[node + 1];
    for (int j = beg; j < end; j++) {
        size_t base = (size_t)g_colidx[j] * D + c;
        union { fp16 b[4]; uint2 u; } vh, vl;
        vh.u = *(const uint2*)&hh[base];
        vl.u = *(const uint2*)&hl[base];
        acc.x += __half2float(vh.b[0]) + __half2float(vl.b[0]);
        acc.y += __half2float(vh.b[1]) + __half2float(vl.b[1]);
        acc.z += __half2float(vh.b[2]) + __half2float(vl.b[2]);
        acc.w += __half2float(vh.b[3]) + __half2float(vl.b[3]);
    }
    float inv = g_inv_deg[node];
    union { fp16 b[4]; uint2 u; } ph, pl;
    split_f16(acc.x * inv, ph.b[0], pl.b[0]);
    split_f16(acc.y * inv, ph.b[1], pl.b[1]);
    split_f16(acc.z * inv, ph.b[2], pl.b[2]);
    split_f16(acc.w * inv, ph.b[3], pl.b[3]);
    size_t o = (size_t)e * ND + (size_t)i * D + c;
    *(uint2*)&g_cahi[o] = ph.u;
    *(uint2*)&g_calo[o] = pl.u;
}

// ---------------------------------------------------------------------------
// Tensor-core GEMM: ldmatrix + 3-stage cp.async pipeline (1 barrier/iter).
// layer==1: grid (4,256,4), dense rows, store h1[e].
// layer==2: grid (4,256,4), compacted rows; deterministic atomicAdd combine.
// ---------------------------------------------------------------------------
#define ROWB 80
#define TILE_B (128 * ROWB)
#define STAGE_B (4 * TILE_B)       // 40960
#define GEMM_SMEM (3 * STAGE_B)    // 122880 (epilogue 67584 fits)

__device__ __forceinline__ uint32_t smem_u32(const void* p) {
    uint32_t a;
    asm("{ .reg .u64 t; cvta.to.shared.u64 t, %1; cvt.u32.u64 %0, t; }"
        : "=r"(a) : "l"(p));
    return a;
}
__device__ __forceinline__ void cp16(uint32_t dst, const void* src) {
    asm volatile("cp.async.cg.shared.global [%0], [%1], 16;" :: "r"(dst), "l"(src));
}
__device__ __forceinline__ void ldmx4(uint32_t* r, uint32_t addr) {
    asm volatile("ldmatrix.sync.aligned.m8n8.x4.shared.b16 {%0,%1,%2,%3}, [%4];"
                 : "=r"(r[0]), "=r"(r[1]), "=r"(r[2]), "=r"(r[3]) : "r"(addr));
}
__device__ __forceinline__ void mma16816(float* c, const uint32_t* a, const uint32_t* b) {
    asm volatile("mma.sync.aligned.m16n8k16.row.col.f32.f16.f16.f32 "
                 "{%0,%1,%2,%3}, {%4,%5,%6,%7}, {%8,%9}, {%0,%1,%2,%3};"
                 : "+f"(c[0]), "+f"(c[1]), "+f"(c[2]), "+f"(c[3])
                 : "r"(a[0]), "r"(a[1]), "r"(a[2]), "r"(a[3]), "r"(b[0]), "r"(b[1]));
}

__global__ void __launch_bounds__(256, 1)
sage_gemm_mma(int layer, const float* __restrict__ blv, float* __restrict__ out) {
    extern __shared__ char smem[];
    uint32_t sb = smem_u32(smem);
    int tid = threadIdx.x, lane = tid & 31, wid = tid >> 5;
    int wm = wid >> 2, wn = wid & 3;
    int g = lane >> 2, lam = lane & 3;
    int bn = blockIdx.x * 128, bm = blockIdx.y * 128;
    int e = blockIdx.z;
    int w_idx = (layer == 1) ? 2 * e : 2 * e + 1;
    const float* __restrict__ bias = blv + w_idx * 512;

    int cnt = 0;
    if (layer == 2) {
        cnt = g_cnt[e];
        if (bm >= cnt) return;
    }

    const fp16* __restrict__ bh = g_wthi + (size_t)w_idx * 512 * 1024;
    const fp16* __restrict__ bl = g_wtlo + (size_t)w_idx * 512 * 1024;

    int row_s = tid >> 2, kc_s = tid & 3;
    int row_s2 = (tid + 256) >> 2, kc_s2 = (tid + 256) & 3;

    size_t aoff_s, aoff_s2, hoff_s, hoff_s2;
    const fp16 *p_ah, *p_al, *p_hh, *p_hl;
    if (layer == 1) {
        p_ah = g_ahi; p_al = g_alo;
        p_hh = g_xhi; p_hl = g_xlo;
        aoff_s = (size_t)(bm + row_s) * 512;  aoff_s2 = (size_t)(bm + row_s2) * 512;
        hoff_s = aoff_s;                      hoff_s2 = aoff_s2;
    } else {
        p_ah = g_cahi + (size_t)e * ND; p_al = g_calo + (size_t)e * ND;
        p_hh = g_h1hi + (size_t)e * ND; p_hl = g_h1lo + (size_t)e * ND;
        int cr_s = min(bm + row_s, cnt - 1), cr_s2 = min(bm + row_s2, cnt - 1);
        aoff_s = (size_t)cr_s * 512;  aoff_s2 = (size_t)cr_s2 * 512;
        hoff_s = (size_t)g_rows[e][cr_s] * 512;
        hoff_s2 = (size_t)g_rows[e][cr_s2] * 512;
    }

    float c[4][4][4];
#pragma unroll
    for (int i = 0; i < 4; i++)
#pragma unroll
        for (int j = 0; j < 4; j++)
#pragma unroll
            for (int q = 0; q < 4; q++) c[i][j][q] = 0.f;

    auto load_stage = [&](int n) {
        uint32_t st = sb + (n % 3) * STAGE_B;
        int ka = (n & 15) * 32, kb = n * 32;
        const fp16 *Ah, *Al;
        size_t o1, o2;
        if (n < 16) { Ah = p_ah; Al = p_al; o1 = aoff_s; o2 = aoff_s2; }
        else        { Ah = p_hh; Al = p_hl; o1 = hoff_s; o2 = hoff_s2; }
        uint32_t d1 = st + row_s * ROWB + kc_s * 16;
        uint32_t d2 = st + row_s2 * ROWB + kc_s2 * 16;
        cp16(d1 + 0 * TILE_B, Ah + o1 + ka + kc_s * 8);
        cp16(d2 + 0 * TILE_B, Ah + o2 + ka + kc_s2 * 8);
        cp16(d1 + 1 * TILE_B, Al + o1 + ka + kc_s * 8);
        cp16(d2 + 1 * TILE_B, Al + o2 + ka + kc_s2 * 8);
        cp16(d1 + 2 * TILE_B, bh + (size_t)(bn + row_s) * 1024 + kb + kc_s * 8);
        cp16(d2 + 2 * TILE_B, bh + (size_t)(bn + row_s2) * 1024 + kb + kc_s2 * 8);
        cp16(d1 + 3 * TILE_B, bl + (size_t)(bn + row_s) * 1024 + kb + kc_s * 8);
        cp16(d2 + 3 * TILE_B, bl + (size_t)(bn + row_s2) * 1024 + kb + kc_s2 * 8);
    };

    // 3-stage pipeline: loads issued AFTER the top barrier of each iteration
    // (all threads past prior compute), wait_group 1 keeps 2 chunks in flight.
    load_stage(0);
    asm volatile("cp.async.commit_group;");
    load_stage(1);
    asm volatile("cp.async.commit_group;");

    for (int it = 0; it < 32; it++) {
        if (it < 31) asm volatile("cp.async.wait_group 1;");
        else         asm volatile("cp.async.wait_group 0;");
        __syncthreads();
        if (it + 2 < 32) {
            load_stage(it + 2);
            asm volatile("cp.async.commit_group;");
        }

        uint32_t st = sb + (it % 3) * STAGE_B;
#pragma unroll
        for (int ks = 0; ks < 2; ks++) {
            uint32_t aH[4][4], aL[4][4], bH[4][2], bL[4][2];
#pragma unroll
            for (int mb = 0; mb < 4; mb++) {
                uint32_t ra = st + (wm * 64 + mb * 16 + (lane & 15)) * ROWB
                              + ks * 32 + ((lane >> 4) << 4);
                ldmx4(aH[mb], ra);
                ldmx4(aL[mb], ra + TILE_B);
            }
#pragma unroll
            for (int np = 0; np < 2; np++) {
                int brow = wn * 32 + np * 16 + (lane & 7) + ((lane & 16) ? 8 : 0);
                uint32_t rb = st + 2 * TILE_B + brow * ROWB + ks * 32
                              + ((lane & 8) ? 16 : 0);
                uint32_t q[4];
                ldmx4(q, rb);
                bH[np * 2][0] = q[0]; bH[np * 2][1] = q[1];
                bH[np * 2 + 1][0] = q[2]; bH[np * 2 + 1][1] = q[3];
                ldmx4(q, rb + TILE_B);
                bL[np * 2][0] = q[0]; bL[np * 2][1] = q[1];
                bL[np * 2 + 1][0] = q[2]; bL[np * 2 + 1][1] = q[3];
            }
#pragma unroll
            for (int mb = 0; mb < 4; mb++)
#pragma unroll
                for (int nb = 0; nb < 4; nb++) {
                    mma16816(c[mb][nb], aH[mb], bH[nb]);
                    mma16816(c[mb][nb], aH[mb], bL[nb]);
                    mma16816(c[mb][nb], aL[mb], bH[nb]);
                }
        }
    }
    __syncthreads();

    // Epilogue: fragments -> SMEM fp32 -> coalesced / atomic stores
    float* sep = (float*)smem;  // [128][132]
#pragma unroll
    for (int mb = 0; mb < 4; mb++)
#pragma unroll
        for (int nb = 0; nb < 4; nb++)
#pragma unroll
            for (int q = 0; q < 4; q++) {
                int row = wm * 64 + mb * 16 + g + ((q >> 1) << 3);
                int col = wn * 32 + nb * 8 + 2 * lam + (q & 1);
                sep[row * 132 + col] = c[mb][nb][q];
            }
    __syncthreads();

    if (layer == 1) {
        fp16* ohi = g_h1hi + (size_t)e * ND;
        fp16* olo = g_h1lo + (size_t)e * ND;
        int w = tid & 63, rs = tid >> 6;
        float b0 = bias[bn + 2 * w], b1 = bias[bn + 2 * w + 1];
#pragma unroll
        for (int it = 0; it < 32; it++) {
            int rr = rs + it * 4;
            float v0 = fmaxf(sep[rr * 132 + 2 * w] + b0, 0.f);
            float v1 = fmaxf(sep[rr * 132 + 2 * w + 1] + b1, 0.f);
            union { fp16 b[2]; uint32_t u; } ph, pl;
            split_f16(v0, ph.b[0], pl.b[0]);
            split_f16(v1, ph.b[1], pl.b[1]);
            size_t o = (size_t)(bm + rr) * D + bn + 2 * w;
            *(uint32_t*)&ohi[o] = ph.u;
            *(uint32_t*)&olo[o] = pl.u;
        }
    } else {
        // Deterministic: each out element gets exactly 2 atomic contributions
        // onto zeroed memory; fl(a+b) is order-independent for two terms.
        float4 bc = *(const float4*)&bias[bn + lane * 4];
#pragma unroll
        for (int it = 0; it < 16; it++) {
            int rr = wid + it * 8;
            if (bm + rr < cnt) {
                int m = g_rows[e][bm + rr];
                float gw = g_gatew[m * 4 + e];
                float* p = out + (size_t)m * D + bn + lane * 4;
                atomicAdd(p + 0, gw * fmaxf(sep[rr * 132 + lane * 4 + 0] + bc.x, 0.f));
                atomicAdd(p + 1, gw * fmaxf(sep[rr * 132 + lane * 4 + 1] + bc.y, 0.f));
                atomicAdd(p + 2, gw * fmaxf(sep[rr * 132 + lane * 4 + 2] + bc.z, 0.f));
                atomicAdd(p + 3, gw * fmaxf(sep[rr * 132 + lane * 4 + 3] + bc.w, 0.f));
            }
        }
    }
}

// ---------------------------------------------------------------------------
// Launch — only harness pointers and integers cross the host boundary.
// ---------------------------------------------------------------------------
extern "C" void kernel_launch(void* const* d_in, const int* in_sizes, int n_in,
                              void* d_out, int out_size) {
    const float* x = 0; const float* gW = 0; const float* gb = 0;
    const float* Wl = 0; const float* blv = 0; const float* Wr = 0;
    const int*   ei = 0;
    for (int i = 0; i < n_in; i++) {
        long long s = in_sizes[i];
        if (s == 16777216)      { if (!x)  x  = (const float*)d_in[i]; }
        else if (s == 2048)     { if (!gW) gW = (const float*)d_in[i]; }
        else if (s == 4)        { if (!gb) gb = (const float*)d_in[i]; }
        else if (s == 2097152)  { if (!Wl) Wl = (const float*)d_in[i];
                                  else if (!Wr) Wr = (const float*)d_in[i]; }
        else if (s == 4096)     { if (!blv) blv = (const float*)d_in[i]; }
        else if (s == 524288)   { if (!ei) ei = (const int*)d_in[i]; }
    }
    if (!x)   x   = (const float*)d_in[0];
    if (!gW)  gW  = (const float*)d_in[1];
    if (!gb)  gb  = (const float*)d_in[2];
    if (!Wl)  Wl  = (const float*)d_in[3];
    if (!blv) blv = (const float*)d_in[4];
    if (!Wr)  Wr  = (const float*)d_in[5];
    if (!ei)  ei  = (const int*)d_in[6];
    float* out = (float*)d_out;

    cudaFuncSetAttribute(sage_gemm_mma,
                         cudaFuncAttributeMaxDynamicSharedMemorySize, GEMM_SMEM);

    detect_kernel<<<1, 32>>>(ei);
    zero_deg_kernel<<<N_NODES / 256, 256>>>();
    deg_kernel<<<N_EDGES / 256, 256>>>(ei);
    scan1_kernel<<<128, 256>>>();
    scan2_kernel<<<1, 128>>>();
    scan3_kernel<<<128, 256>>>();
    fill_kernel<<<N_EDGES / 256, 256>>>(ei);
    gate_kernel<<<N_NODES / 8, 256>>>(x, gW, gb);
    convert_x_kernel<<<ND / 4 / 256, 256>>>(x);
    prep_w_kernel<<<dim3(32, 16, 8), dim3(32, 32)>>>(Wl, Wr);

    // Layer 1: shared aggr(x), all 4 experts batched
    aggregate_x_kernel<<<N_NODES, 128>>>(x);
    sage_gemm_mma<<<dim3(4, 256, 4), 256, GEMM_SMEM>>>(1, blv, out);

    // Layer 2: compact aggregations, then ONE batched GEMM launch (z=4)
    // with deterministic atomic gated-combine.
    cudaMemsetAsync(out, 0, (size_t)out_size * sizeof(float));
    aggregate_h2_kernel<<<dim3(N_NODES, NEXP), 128>>>();
    sage_gemm_mma<<<dim3(4, 256, 4), 256, GEMM_SMEM>>>(2, blv, out);
}

// round 12
// speedup vs baseline: 2.7645x; 1.1633x over previous
#include <cuda_runtime.h>
#include <cuda_fp16.h>
#include <cstdint>

// ---------------------------------------------------------------------------
// MoE GraphSAGE, mma.sync m16n8k16 fp16 (fp32 accum), fp16x3 split GEMM.
// R12: GEMM at occupancy 2 (2 CTAs/SM): 2-stage cp.async pipeline (81920B
// smem/CTA), __launch_bounds__(256,2), register diet (B fragments loaded
// per nb-pair). Everything else identical to the R11-passing kernel.
// __device__ globals resolved ONLY in device code (R7 ATS lesson).
// ---------------------------------------------------------------------------

#define N_NODES 32768
#define N_EDGES 262144
#define D 512
#define NEXP 4
#define ND (N_NODES * D)

typedef __half fp16;

__device__ fp16  g_xhi[ND], g_xlo[ND];
__device__ fp16  g_ahi[ND], g_alo[ND];            // layer-1 aggr (all nodes)
__device__ fp16  g_cahi[(size_t)NEXP * ND];       // layer-2 compact aggr
__device__ fp16  g_calo[(size_t)NEXP * ND];
__device__ fp16  g_h1hi[(size_t)NEXP * ND];
__device__ fp16  g_h1lo[(size_t)NEXP * ND];
__device__ fp16  g_wthi[8ull * 512 * 1024];       // [w_idx][n][k]
__device__ fp16  g_wtlo[8ull * 512 * 1024];
__device__ float g_inv_deg[N_NODES];
__device__ int   g_deg[N_NODES];
__device__ int   g_rowptr[N_NODES + 1];
__device__ int   g_cursor[N_NODES];
__device__ int   g_colidx[N_EDGES];
__device__ float g_gatew[N_NODES * NEXP];
__device__ int   g_rows[NEXP][N_NODES];
__device__ int   g_cnt[NEXP];
__device__ int   g_pre[N_NODES];
__device__ int   g_bsum[128];
__device__ int   g_is64;

__device__ __forceinline__ void split_f16(float v, fp16& h, fp16& l) {
    h = __float2half_rn(v);
    l = __float2half_rn(v - __half2float(h));
}

// ---------------------------------------------------------------------------
// Edge dtype detect + CSR
// ---------------------------------------------------------------------------
__global__ void detect_kernel(const int* __restrict__ ei32) {
    if (threadIdx.x == 0) {
        int is64 = 1;
        for (int i = 0; i < 128; i++)
            if (ei32[2 * i + 1] != 0) { is64 = 0; break; }
        g_is64 = is64;
    }
}
__device__ __forceinline__ int edge_val(const int* __restrict__ e, int idx, int is64) {
    return is64 ? e[2 * idx] : e[idx];
}
__global__ void zero_deg_kernel() {
    int i = blockIdx.x * blockDim.x + threadIdx.x;
    if (i < N_NODES) g_deg[i] = 0;
    if (i < NEXP) g_cnt[i] = 0;
}
__global__ void deg_kernel(const int* __restrict__ ei32) {
    int i = blockIdx.x * blockDim.x + threadIdx.x;
    if (i < N_EDGES) atomicAdd(&g_deg[edge_val(ei32, N_EDGES + i, g_is64)], 1);
}
__global__ void scan1_kernel() {
    __shared__ int sm[256];
    int t = threadIdx.x, i = blockIdx.x * 256 + t;
    sm[t] = g_deg[i];
    __syncthreads();
    for (int off = 1; off < 256; off <<= 1) {
        int v = (t >= off) ? sm[t - off] : 0;
        __syncthreads();
        sm[t] += v;
        __syncthreads();
    }
    g_pre[i] = sm[t];
    if (t == 255) g_bsum[blockIdx.x] = sm[255];
}
__global__ void scan2_kernel() {
    __shared__ int sm[128];
    int t = threadIdx.x;
    int orig = g_bsum[t];
    sm[t] = orig;
    __syncthreads();
    for (int off = 1; off < 128; off <<= 1) {
        int v = (t >= off) ? sm[t - off] : 0;
        __syncthreads();
        sm[t] += v;
        __syncthreads();
    }
    g_bsum[t] = sm[t] - orig;
    if (t == 127) g_rowptr[N_NODES] = sm[127];
}
__global__ void scan3_kernel() {
    int i = blockIdx.x * 256 + threadIdx.x;
    int d = g_deg[i];
    int rp = g_bsum[blockIdx.x] + g_pre[i] - d;
    g_rowptr[i] = rp;
    g_cursor[i] = rp;
    g_inv_deg[i] = (d > 0) ? 1.0f / (float)d : 0.0f;
}
__global__ void fill_kernel(const int* __restrict__ ei32) {
    int i = blockIdx.x * blockDim.x + threadIdx.x;
    if (i < N_EDGES) {
        int is64 = g_is64;
        int src = edge_val(ei32, i, is64);
        int dst = edge_val(ei32, N_EDGES + i, is64);
        g_colidx[atomicAdd(&g_cursor[dst], 1)] = src;
    }
}

// ---------------------------------------------------------------------------
// Gate + active-row list build
// ---------------------------------------------------------------------------
__global__ void gate_kernel(const float* __restrict__ x,
                            const float* __restrict__ gW,
                            const float* __restrict__ gb) {
    int gtid = blockIdx.x * blockDim.x + threadIdx.x;
    int node = gtid >> 5, lane = gtid & 31;
    if (node >= N_NODES) return;
    const float* xr = x + (size_t)node * D;
    float a0 = 0.f, a1 = 0.f, a2 = 0.f, a3 = 0.f;
    for (int i = lane; i < D; i += 32) {
        float xv = xr[i];
        float4 w = *(const float4*)&gW[i * 4];
        a0 = fmaf(xv, w.x, a0); a1 = fmaf(xv, w.y, a1);
        a2 = fmaf(xv, w.z, a2); a3 = fmaf(xv, w.w, a3);
    }
#pragma unroll
    for (int off = 16; off; off >>= 1) {
        a0 += __shfl_down_sync(0xffffffffu, a0, off);
        a1 += __shfl_down_sync(0xffffffffu, a1, off);
        a2 += __shfl_down_sync(0xffffffffu, a2, off);
        a3 += __shfl_down_sync(0xffffffffu, a3, off);
    }
    if (lane == 0) {
        float l[4] = {a0 + gb[0], a1 + gb[1], a2 + gb[2], a3 + gb[3]};
        float m = fmaxf(fmaxf(l[0], l[1]), fmaxf(l[2], l[3]));
        float e[4], s = 0.f;
#pragma unroll
        for (int k = 0; k < 4; k++) { e[k] = expf(l[k] - m); s += e[k]; }
        float inv = 1.0f / s;
        float p[4];
#pragma unroll
        for (int k = 0; k < 4; k++) p[k] = e[k] * inv;
        int i1 = 0;
#pragma unroll
        for (int k = 1; k < 4; k++) if (p[k] > p[i1]) i1 = k;
        int i2 = -1;
#pragma unroll
        for (int k = 0; k < 4; k++) {
            if (k == i1) continue;
            if (i2 < 0 || p[k] > p[i2]) i2 = k;
        }
#pragma unroll
        for (int k = 0; k < 4; k++)
            g_gatew[node * 4 + k] = (k == i1) ? p[i1] : ((k == i2) ? p[i2] : 0.0f);
        int p1 = atomicAdd(&g_cnt[i1], 1);
        g_rows[i1][p1] = node;
        int p2 = atomicAdd(&g_cnt[i2], 1);
        g_rows[i2][p2] = node;
    }
}

// ---------------------------------------------------------------------------
// Conversions / weight prep
// ---------------------------------------------------------------------------
__global__ void convert_x_kernel(const float* __restrict__ x) {
    int i = blockIdx.x * blockDim.x + threadIdx.x;
    float4 v = *(const float4*)&x[(size_t)i * 4];
    union { fp16 b[4]; uint2 u; } ph, pl;
    split_f16(v.x, ph.b[0], pl.b[0]);
    split_f16(v.y, ph.b[1], pl.b[1]);
    split_f16(v.z, ph.b[2], pl.b[2]);
    split_f16(v.w, ph.b[3], pl.b[3]);
    *(uint2*)&g_xhi[(size_t)i * 4] = ph.u;
    *(uint2*)&g_xlo[(size_t)i * 4] = pl.u;
}

__global__ void prep_w_kernel(const float* __restrict__ Wl, const float* __restrict__ Wr) {
    __shared__ float sm[32][33];
    int m = blockIdx.z;
    int k0 = blockIdx.x * 32, n0 = blockIdx.y * 32;
    int tx = threadIdx.x, ty = threadIdx.y;
    const float* W = (k0 < 512) ? (Wl + (size_t)m * 512 * 512 + (size_t)(k0 + ty) * 512)
                                : (Wr + (size_t)m * 512 * 512 + (size_t)(k0 - 512 + ty) * 512);
    sm[ty][tx] = W[n0 + tx];
    __syncthreads();
    float v = sm[tx][ty];
    fp16 h, l;
    split_f16(v, h, l);
    size_t o = (size_t)m * 512 * 1024 + (size_t)(n0 + ty) * 1024 + (k0 + tx);
    g_wthi[o] = h;
    g_wtlo[o] = l;
}

// ---------------------------------------------------------------------------
// Aggregations
// ---------------------------------------------------------------------------
__global__ void aggregate_x_kernel(const float* __restrict__ x) {
    int node = blockIdx.x;
    int c = threadIdx.x * 4;
    float4 acc = make_float4(0.f, 0.f, 0.f, 0.f);
    int beg = g_rowptr[node], end = g_rowptr[node + 1];
    for (int j = beg; j < end; j++) {
        float4 v = *(const float4*)&x[(size_t)g_colidx[j] * D + c];
        acc.x += v.x; acc.y += v.y; acc.z += v.z; acc.w += v.w;
    }
    float inv = g_inv_deg[node];
    union { fp16 b[4]; uint2 u; } ph, pl;
    split_f16(acc.x * inv, ph.b[0], pl.b[0]);
    split_f16(acc.y * inv, ph.b[1], pl.b[1]);
    split_f16(acc.z * inv, ph.b[2], pl.b[2]);
    split_f16(acc.w * inv, ph.b[3], pl.b[3]);
    *(uint2*)&g_ahi[(size_t)node * D + c] = ph.u;
    *(uint2*)&g_alo[(size_t)node * D + c] = pl.u;
}

__global__ void aggregate_h2_kernel() {
    int e = blockIdx.y;
    int i = blockIdx.x;
    if (i >= g_cnt[e]) return;
    int node = g_rows[e][i];
    const fp16* __restrict__ hh = g_h1hi + (size_t)e * ND;
    const fp16* __restrict__ hl = g_h1lo + (size_t)e * ND;
    int c = threadIdx.x * 4;
    float4 acc = make_float4(0.f, 0.f, 0.f, 0.f);
    int beg = g_rowptr[node], end = g_rowptr[node + 1];
    for (int j = beg; j < end; j++) {
        size_t base = (size_t)g_colidx[j] * D + c;
        union { fp16 b[4]; uint2 u; } vh, vl;
        vh.u = *(const uint2*)&hh[base];
        vl.u = *(const uint2*)&hl[base];
        acc.x += __half2float(vh.b[0]) + __half2float(vl.b[0]);
        acc.y += __half2float(vh.b[1]) + __half2float(vl.b[1]);
        acc.z += __half2float(vh.b[2]) + __half2float(vl.b[2]);
        acc.w += __half2float(vh.b[3]) + __half2float(vl.b[3]);
    }
    float inv = g_inv_deg[node];
    union { fp16 b[4]; uint2 u; } ph, pl;
    split_f16(acc.x * inv, ph.b[0], pl.b[0]);
    split_f16(acc.y * inv, ph.b[1], pl.b[1]);
    split_f16(acc.z * inv, ph.b[2], pl.b[2]);
    split_f16(acc.w * inv, ph.b[3], pl.b[3]);
    size_t o = (size_t)e * ND + (size_t)i * D + c;
    *(uint2*)&g_cahi[o] = ph.u;
    *(uint2*)&g_calo[o] = pl.u;
}

// ---------------------------------------------------------------------------
// Tensor-core GEMM: ldmatrix + 2-stage cp.async pipeline, 2 CTAs/SM.
// layer==1: grid (4,256,4), dense rows, store h1[e].
// layer==2: grid (4,256,4), compacted rows; deterministic atomicAdd combine.
// ---------------------------------------------------------------------------
#define ROWB 80
#define TILE_B (128 * ROWB)
#define STAGE_B (4 * TILE_B)       // 40960
#define GEMM_SMEM (2 * STAGE_B)    // 81920/CTA -> 2 CTAs/SM (163840 <= 228K)

__device__ __forceinline__ uint32_t smem_u32(const void* p) {
    uint32_t a;
    asm("{ .reg .u64 t; cvta.to.shared.u64 t, %1; cvt.u32.u64 %0, t; }"
        : "=r"(a) : "l"(p));
    return a;
}
__device__ __forceinline__ void cp16(uint32_t dst, const void* src) {
    asm volatile("cp.async.cg.shared.global [%0], [%1], 16;" :: "r"(dst), "l"(src));
}
__device__ __forceinline__ void ldmx4(uint32_t* r, uint32_t addr) {
    asm volatile("ldmatrix.sync.aligned.m8n8.x4.shared.b16 {%0,%1,%2,%3}, [%4];"
                 : "=r"(r[0]), "=r"(r[1]), "=r"(r[2]), "=r"(r[3]) : "r"(addr));
}
__device__ __forceinline__ void mma16816(float* c, const uint32_t* a, const uint32_t* b) {
    asm volatile("mma.sync.aligned.m16n8k16.row.col.f32.f16.f16.f32 "
                 "{%0,%1,%2,%3}, {%4,%5,%6,%7}, {%8,%9}, {%0,%1,%2,%3};"
                 : "+f"(c[0]), "+f"(c[1]), "+f"(c[2]), "+f"(c[3])
                 : "r"(a[0]), "r"(a[1]), "r"(a[2]), "r"(a[3]), "r"(b[0]), "r"(b[1]));
}

__global__ void __launch_bounds__(256, 2)
sage_gemm_mma(int layer, const float* __restrict__ blv, float* __restrict__ out) {
    extern __shared__ char smem[];
    uint32_t sb = smem_u32(smem);
    int tid = threadIdx.x, lane = tid & 31, wid = tid >> 5;
    int wm = wid >> 2, wn = wid & 3;
    int g = lane >> 2, lam = lane & 3;
    int bn = blockIdx.x * 128, bm = blockIdx.y * 128;
    int e = blockIdx.z;
    int w_idx = (layer == 1) ? 2 * e : 2 * e + 1;
    const float* __restrict__ bias = blv + w_idx * 512;

    int cnt = 0;
    if (layer == 2) {
        cnt = g_cnt[e];
        if (bm >= cnt) return;
    }

    const fp16* __restrict__ bh = g_wthi + (size_t)w_idx * 512 * 1024;
    const fp16* __restrict__ bl = g_wtlo + (size_t)w_idx * 512 * 1024;

    int row_s = tid >> 2, kc_s = tid & 3;
    int row_s2 = (tid + 256) >> 2, kc_s2 = (tid + 256) & 3;

    size_t aoff_s, aoff_s2, hoff_s, hoff_s2;
    const fp16 *p_ah, *p_al, *p_hh, *p_hl;
    if (layer == 1) {
        p_ah = g_ahi; p_al = g_alo;
        p_hh = g_xhi; p_hl = g_xlo;
        aoff_s = (size_t)(bm + row_s) * 512;  aoff_s2 = (size_t)(bm + row_s2) * 512;
        hoff_s = aoff_s;                      hoff_s2 = aoff_s2;
    } else {
        p_ah = g_cahi + (size_t)e * ND; p_al = g_calo + (size_t)e * ND;
        p_hh = g_h1hi + (size_t)e * ND; p_hl = g_h1lo + (size_t)e * ND;
        int cr_s = min(bm + row_s, cnt - 1), cr_s2 = min(bm + row_s2, cnt - 1);
        aoff_s = (size_t)cr_s * 512;  aoff_s2 = (size_t)cr_s2 * 512;
        hoff_s = (size_t)g_rows[e][cr_s] * 512;
        hoff_s2 = (size_t)g_rows[e][cr_s2] * 512;
    }

    float c[4][4][4];
#pragma unroll
    for (int i = 0; i < 4; i++)
#pragma unroll
        for (int j = 0; j < 4; j++)
#pragma unroll
            for (int q = 0; q < 4; q++) c[i][j][q] = 0.f;

    auto load_stage = [&](int n) {
        uint32_t st = sb + (n & 1) * STAGE_B;
        int ka = (n & 15) * 32, kb = n * 32;
        const fp16 *Ah, *Al;
        size_t o1, o2;
        if (n < 16) { Ah = p_ah; Al = p_al; o1 = aoff_s; o2 = aoff_s2; }
        else        { Ah = p_hh; Al = p_hl; o1 = hoff_s; o2 = hoff_s2; }
        uint32_t d1 = st + row_s * ROWB + kc_s * 16;
        uint32_t d2 = st + row_s2 * ROWB + kc_s2 * 16;
        cp16(d1 + 0 * TILE_B, Ah + o1 + ka + kc_s * 8);
        cp16(d2 + 0 * TILE_B, Ah + o2 + ka + kc_s2 * 8);
        cp16(d1 + 1 * TILE_B, Al + o1 + ka + kc_s * 8);
        cp16(d2 + 1 * TILE_B, Al + o2 + ka + kc_s2 * 8);
        cp16(d1 + 2 * TILE_B, bh + (size_t)(bn + row_s) * 1024 + kb + kc_s * 8);
        cp16(d2 + 2 * TILE_B, bh + (size_t)(bn + row_s2) * 1024 + kb + kc_s2 * 8);
        cp16(d1 + 3 * TILE_B, bl + (size_t)(bn + row_s) * 1024 + kb + kc_s * 8);
        cp16(d2 + 3 * TILE_B, bl + (size_t)(bn + row_s2) * 1024 + kb + kc_s2 * 8);
    };

    load_stage(0);
    asm volatile("cp.async.commit_group;");

    for (int it = 0; it < 32; it++) {
        int buf = it & 1;
        if (it + 1 < 32) {
            load_stage(it + 1);
            asm volatile("cp.async.commit_group;");
            asm volatile("cp.async.wait_group 1;");
        } else {
            asm volatile("cp.async.wait_group 0;");
        }
        __syncthreads();

        uint32_t st = sb + buf * STAGE_B;
#pragma unroll
        for (int ks = 0; ks < 2; ks++) {
            // A fragments for the whole ks (32 regs live)
            uint32_t aH[4][4], aL[4][4];
#pragma unroll
            for (int mb = 0; mb < 4; mb++) {
                uint32_t ra = st + (wm * 64 + mb * 16 + (lane & 15)) * ROWB
                              + ks * 32 + ((lane >> 4) << 4);
                ldmx4(aH[mb], ra);
                ldmx4(aL[mb], ra + TILE_B);
            }
            // B fragments per nb-pair (8 regs live) -> lower peak registers
#pragma unroll
            for (int np = 0; np < 2; np++) {
                int brow = wn * 32 + np * 16 + (lane & 7) + ((lane & 16) ? 8 : 0);
                uint32_t rb = st + 2 * TILE_B + brow * ROWB + ks * 32
                              + ((lane & 8) ? 16 : 0);
                uint32_t qh[4], ql[4];
                ldmx4(qh, rb);
                ldmx4(ql, rb + TILE_B);
#pragma unroll
                for (int mb = 0; mb < 4; mb++) {
                    mma16816(c[mb][np * 2],     aH[mb], qh);
                    mma16816(c[mb][np * 2],     aH[mb], ql);
                    mma16816(c[mb][np * 2],     aL[mb], qh);
                    mma16816(c[mb][np * 2 + 1], aH[mb], qh + 2);
                    mma16816(c[mb][np * 2 + 1], aH[mb], ql + 2);
                    mma16816(c[mb][np * 2 + 1], aL[mb], qh + 2);
                }
            }
        }
        __syncthreads();
    }

    // Epilogue: fragments -> SMEM fp32 -> coalesced / atomic stores
    float* sep = (float*)smem;  // [128][132] = 67584 <= 81920
#pragma unroll
    for (int mb = 0; mb < 4; mb++)
#pragma unroll
        for (int nb = 0; nb < 4; nb++)
#pragma unroll
            for (int q = 0; q < 4; q++) {
                int row = wm * 64 + mb * 16 + g + ((q >> 1) << 3);
                int col = wn * 32 + nb * 8 + 2 * lam + (q & 1);
                sep[row * 132 + col] = c[mb][nb][q];
            }
    __syncthreads();

    if (layer == 1) {
        fp16* ohi = g_h1hi + (size_t)e * ND;
        fp16* olo = g_h1lo + (size_t)e * ND;
        int w = tid & 63, rs = tid >> 6;
        float b0 = bias[bn + 2 * w], b1 = bias[bn + 2 * w + 1];
#pragma unroll
        for (int it = 0; it < 32; it++) {
            int rr = rs + it * 4;
            float v0 = fmaxf(sep[rr * 132 + 2 * w] + b0, 0.f);
            float v1 = fmaxf(sep[rr * 132 + 2 * w + 1] + b1, 0.f);
            union { fp16 b[2]; uint32_t u; } ph, pl;
            split_f16(v0, ph.b[0], pl.b[0]);
            split_f16(v1, ph.b[1], pl.b[1]);
            size_t o = (size_t)(bm + rr) * D + bn + 2 * w;
            *(uint32_t*)&ohi[o] = ph.u;
            *(uint32_t*)&olo[o] = pl.u;
        }
    } else {
        // Deterministic: each out element gets exactly 2 atomic contributions
        // onto zeroed memory; fl(a+b) is order-independent for two terms.
        float4 bc = *(const float4*)&bias[bn + lane * 4];
#pragma unroll
        for (int it = 0; it < 16; it++) {
            int rr = wid + it * 8;
            if (bm + rr < cnt) {
                int m = g_rows[e][bm + rr];
                float gw = g_gatew[m * 4 + e];
                float* p = out + (size_t)m * D + bn + lane * 4;
                atomicAdd(p + 0, gw * fmaxf(sep[rr * 132 + lane * 4 + 0] + bc.x, 0.f));
                atomicAdd(p + 1, gw * fmaxf(sep[rr * 132 + lane * 4 + 1] + bc.y, 0.f));
                atomicAdd(p + 2, gw * fmaxf(sep[rr * 132 + lane * 4 + 2] + bc.z, 0.f));
                atomicAdd(p + 3, gw * fmaxf(sep[rr * 132 + lane * 4 + 3] + bc.w, 0.f));
            }
        }
    }
}

// ---------------------------------------------------------------------------
// Launch — only harness pointers and integers cross the host boundary.
// ---------------------------------------------------------------------------
extern "C" void kernel_launch(void* const* d_in, const int* in_sizes, int n_in,
                              void* d_out, int out_size) {
    const float* x = 0; const float* gW = 0; const float* gb = 0;
    const float* Wl = 0; const float* blv = 0; const float* Wr = 0;
    const int*   ei = 0;
    for (int i = 0; i < n_in; i++) {
        long long s = in_sizes[i];
        if (s == 16777216)      { if (!x)  x  = (const float*)d_in[i]; }
        else if (s == 2048)     { if (!gW) gW = (const float*)d_in[i]; }
        else if (s == 4)        { if (!gb) gb = (const float*)d_in[i]; }
        else if (s == 2097152)  { if (!Wl) Wl = (const float*)d_in[i];
                                  else if (!Wr) Wr = (const float*)d_in[i]; }
        else if (s == 4096)     { if (!blv) blv = (const float*)d_in[i]; }
        else if (s == 524288)   { if (!ei) ei = (const int*)d_in[i]; }
    }
    if (!x)   x   = (const float*)d_in[0];
    if (!gW)  gW  = (const float*)d_in[1];
    if (!gb)  gb  = (const float*)d_in[2];
    if (!Wl)  Wl  = (const float*)d_in[3];
    if (!blv) blv = (const float*)d_in[4];
    if (!Wr)  Wr  = (const float*)d_in[5];
    if (!ei)  ei  = (const int*)d_in[6];
    float* out = (float*)d_out;

    cudaFuncSetAttribute(sage_gemm_mma,
                         cudaFuncAttributeMaxDynamicSharedMemorySize, GEMM_SMEM);

    detect_kernel<<<1, 32>>>(ei);
    zero_deg_kernel<<<N_NODES / 256, 256>>>();
    deg_kernel<<<N_EDGES / 256, 256>>>(ei);
    scan1_kernel<<<128, 256>>>();
    scan2_kernel<<<1, 128>>>();
    scan3_kernel<<<128, 256>>>();
    fill_kernel<<<N_EDGES / 256, 256>>>(ei);
    gate_kernel<<<N_NODES / 8, 256>>>(x, gW, gb);
    convert_x_kernel<<<ND / 4 / 256, 256>>>(x);
    prep_w_kernel<<<dim3(32, 16, 8), dim3(32, 32)>>>(Wl, Wr);

    // Layer 1: shared aggr(x), all 4 experts batched
    aggregate_x_kernel<<<N_NODES, 128>>>(x);
    sage_gemm_mma<<<dim3(4, 256, 4), 256, GEMM_SMEM>>>(1, blv, out);

    // Layer 2: compact aggregations, then ONE batched GEMM launch (z=4)
    // with deterministic atomic gated-combine.
    cudaMemsetAsync(out, 0, (size_t)out_size * sizeof(float));
    aggregate_h2_kernel<<<dim3(N_NODES, NEXP), 128>>>();
    sage_gemm_mma<<<dim3(4, 256, 4), 256, GEMM_SMEM>>>(2, blv, out);
}

// round 13
// speedup vs baseline: 2.7972x; 1.0118x over previous
#include <cuda_runtime.h>
#include <cuda_fp16.h>
#include <cstdint>

// ---------------------------------------------------------------------------
// MoE GraphSAGE, mma.sync m16n8k16 fp16 (fp32 accum), fp16x3 split GEMM.
// R13: one-barrier-per-iteration 2-stage mainloop (load issued AFTER the top
// barrier), convert_x folded into gate_kernel, detect+zero merged.
// GEMM at occupancy 2 (R12). __device__ globals resolved ONLY in device code.
// ---------------------------------------------------------------------------

#define N_NODES 32768
#define N_EDGES 262144
#define D 512
#define NEXP 4
#define ND (N_NODES * D)

typedef __half fp16;

__device__ fp16  g_xhi[ND], g_xlo[ND];
__device__ fp16  g_ahi[ND], g_alo[ND];            // layer-1 aggr (all nodes)
__device__ fp16  g_cahi[(size_t)NEXP * ND];       // layer-2 compact aggr
__device__ fp16  g_calo[(size_t)NEXP * ND];
__device__ fp16  g_h1hi[(size_t)NEXP * ND];
__device__ fp16  g_h1lo[(size_t)NEXP * ND];
__device__ fp16  g_wthi[8ull * 512 * 1024];       // [w_idx][n][k]
__device__ fp16  g_wtlo[8ull * 512 * 1024];
__device__ float g_inv_deg[N_NODES];
__device__ int   g_deg[N_NODES];
__device__ int   g_rowptr[N_NODES + 1];
__device__ int   g_cursor[N_NODES];
__device__ int   g_colidx[N_EDGES];
__device__ float g_gatew[N_NODES * NEXP];
__device__ int   g_rows[NEXP][N_NODES];
__device__ int   g_cnt[NEXP];
__device__ int   g_pre[N_NODES];
__device__ int   g_bsum[128];
__device__ int   g_is64;

__device__ __forceinline__ void split_f16(float v, fp16& h, fp16& l) {
    h = __float2half_rn(v);
    l = __float2half_rn(v - __half2float(h));
}

// ---------------------------------------------------------------------------
// Init (detect dtype + zero counters) + CSR
// ---------------------------------------------------------------------------
__global__ void init_kernel(const int* __restrict__ ei32) {
    int i = blockIdx.x * blockDim.x + threadIdx.x;
    if (i < N_NODES) g_deg[i] = 0;
    if (i < NEXP) g_cnt[i] = 0;
    if (i == 0) {
        int is64 = 1;
        for (int k = 0; k < 128; k++)
            if (ei32[2 * k + 1] != 0) { is64 = 0; break; }
        g_is64 = is64;
    }
}
__device__ __forceinline__ int edge_val(const int* __restrict__ e, int idx, int is64) {
    return is64 ? e[2 * idx] : e[idx];
}
__global__ void deg_kernel(const int* __restrict__ ei32) {
    int i = blockIdx.x * blockDim.x + threadIdx.x;
    if (i < N_EDGES) atomicAdd(&g_deg[edge_val(ei32, N_EDGES + i, g_is64)], 1);
}
__global__ void scan1_kernel() {
    __shared__ int sm[256];
    int t = threadIdx.x, i = blockIdx.x * 256 + t;
    sm[t] = g_deg[i];
    __syncthreads();
    for (int off = 1; off < 256; off <<= 1) {
        int v = (t >= off) ? sm[t - off] : 0;
        __syncthreads();
        sm[t] += v;
        __syncthreads();
    }
    g_pre[i] = sm[t];
    if (t == 255) g_bsum[blockIdx.x] = sm[255];
}
__global__ void scan2_kernel() {
    __shared__ int sm[128];
    int t = threadIdx.x;
    int orig = g_bsum[t];
    sm[t] = orig;
    __syncthreads();
    for (int off = 1; off < 128; off <<= 1) {
        int v = (t >= off) ? sm[t - off] : 0;
        __syncthreads();
        sm[t] += v;
        __syncthreads();
    }
    g_bsum[t] = sm[t] - orig;
    if (t == 127) g_rowptr[N_NODES] = sm[127];
}
__global__ void scan3_kernel() {
    int i = blockIdx.x * 256 + threadIdx.x;
    int d = g_deg[i];
    int rp = g_bsum[blockIdx.x] + g_pre[i] - d;
    g_rowptr[i] = rp;
    g_cursor[i] = rp;
    g_inv_deg[i] = (d > 0) ? 1.0f / (float)d : 0.0f;
}
__global__ void fill_kernel(const int* __restrict__ ei32) {
    int i = blockIdx.x * blockDim.x + threadIdx.x;
    if (i < N_EDGES) {
        int is64 = g_is64;
        int src = edge_val(ei32, i, is64);
        int dst = edge_val(ei32, N_EDGES + i, is64);
        g_colidx[atomicAdd(&g_cursor[dst], 1)] = src;
    }
}

// ---------------------------------------------------------------------------
// Gate + active-row lists + x -> fp16 hi/lo (fused; warp streams x coalesced)
// ---------------------------------------------------------------------------
__global__ void gate_kernel(const float* __restrict__ x,
                            const float* __restrict__ gW,
                            const float* __restrict__ gb) {
    int gtid = blockIdx.x * blockDim.x + threadIdx.x;
    int node = gtid >> 5, lane = gtid & 31;
    if (node >= N_NODES) return;
    const float* xr = x + (size_t)node * D;
    fp16* xh = g_xhi + (size_t)node * D;
    fp16* xl = g_xlo + (size_t)node * D;
    float a0 = 0.f, a1 = 0.f, a2 = 0.f, a3 = 0.f;
    for (int i = lane; i < D; i += 32) {
        float xv = xr[i];
        fp16 h, l;
        split_f16(xv, h, l);
        xh[i] = h;
        xl[i] = l;
        float4 w = *(const float4*)&gW[i * 4];
        a0 = fmaf(xv, w.x, a0); a1 = fmaf(xv, w.y, a1);
        a2 = fmaf(xv, w.z, a2); a3 = fmaf(xv, w.w, a3);
    }
#pragma unroll
    for (int off = 16; off; off >>= 1) {
        a0 += __shfl_down_sync(0xffffffffu, a0, off);
        a1 += __shfl_down_sync(0xffffffffu, a1, off);
        a2 += __shfl_down_sync(0xffffffffu, a2, off);
        a3 += __shfl_down_sync(0xffffffffu, a3, off);
    }
    if (lane == 0) {
        float l[4] = {a0 + gb[0], a1 + gb[1], a2 + gb[2], a3 + gb[3]};
        float m = fmaxf(fmaxf(l[0], l[1]), fmaxf(l[2], l[3]));
        float e[4], s = 0.f;
#pragma unroll
        for (int k = 0; k < 4; k++) { e[k] = expf(l[k] - m); s += e[k]; }
        float inv = 1.0f / s;
        float p[4];
#pragma unroll
        for (int k = 0; k < 4; k++) p[k] = e[k] * inv;
        int i1 = 0;
#pragma unroll
        for (int k = 1; k < 4; k++) if (p[k] > p[i1]) i1 = k;
        int i2 = -1;
#pragma unroll
        for (int k = 0; k < 4; k++) {
            if (k == i1) continue;
            if (i2 < 0 || p[k] > p[i2]) i2 = k;
        }
#pragma unroll
        for (int k = 0; k < 4; k++)
            g_gatew[node * 4 + k] = (k == i1) ? p[i1] : ((k == i2) ? p[i2] : 0.0f);
        int p1 = atomicAdd(&g_cnt[i1], 1);
        g_rows[i1][p1] = node;
        int p2 = atomicAdd(&g_cnt[i2], 1);
        g_rows[i2][p2] = node;
    }
}

// ---------------------------------------------------------------------------
// Weight prep
// ---------------------------------------------------------------------------
__global__ void prep_w_kernel(const float* __restrict__ Wl, const float* __restrict__ Wr) {
    __shared__ float sm[32][33];
    int m = blockIdx.z;
    int k0 = blockIdx.x * 32, n0 = blockIdx.y * 32;
    int tx = threadIdx.x, ty = threadIdx.y;
    const float* W = (k0 < 512) ? (Wl + (size_t)m * 512 * 512 + (size_t)(k0 + ty) * 512)
                                : (Wr + (size_t)m * 512 * 512 + (size_t)(k0 - 512 + ty) * 512);
    sm[ty][tx] = W[n0 + tx];
    __syncthreads();
    float v = sm[tx][ty];
    fp16 h, l;
    split_f16(v, h, l);
    size_t o = (size_t)m * 512 * 1024 + (size_t)(n0 + ty) * 1024 + (k0 + tx);
    g_wthi[o] = h;
    g_wtlo[o] = l;
}

// ---------------------------------------------------------------------------
// Aggregations
// ---------------------------------------------------------------------------
__global__ void aggregate_x_kernel(const float* __restrict__ x) {
    int node = blockIdx.x;
    int c = threadIdx.x * 4;
    float4 acc = make_float4(0.f, 0.f, 0.f, 0.f);
    int beg = g_rowptr[node], end = g_rowptr[node + 1];
    for (int j = beg; j < end; j++) {
        float4 v = *(const float4*)&x[(size_t)g_colidx[j] * D + c];
        acc.x += v.x; acc.y += v.y; acc.z += v.z; acc.w += v.w;
    }
    float inv = g_inv_deg[node];
    union { fp16 b[4]; uint2 u; } ph, pl;
    split_f16(acc.x * inv, ph.b[0], pl.b[0]);
    split_f16(acc.y * inv, ph.b[1], pl.b[1]);
    split_f16(acc.z * inv, ph.b[2], pl.b[2]);
    split_f16(acc.w * inv, ph.b[3], pl.b[3]);
    *(uint2*)&g_ahi[(size_t)node * D + c] = ph.u;
    *(uint2*)&g_alo[(size_t)node * D + c] = pl.u;
}

__global__ void aggregate_h2_kernel() {
    int e = blockIdx.y;
    int i = blockIdx.x;
    if (i >= g_cnt[e]) return;
    int node = g_rows[e][i];
    const fp16* __restrict__ hh = g_h1hi + (size_t)e * ND;
    const fp16* __restrict__ hl = g_h1lo + (size_t)e * ND;
    int c = threadIdx.x * 4;
    float4 acc = make_float4(0.f, 0.f, 0.f, 0.f);
    int beg = g_rowptr[node], end = g_rowptr[node + 1];
    for (int j = beg; j < end; j++) {
        size_t base = (size_t)g_colidx[j] * D + c;
        union { fp16 b[4]; uint2 u; } vh, vl;
        vh.u = *(const uint2*)&hh[base];
        vl.u = *(const uint2*)&hl[base];
        acc.x += __half2float(vh.b[0]) + __half2float(vl.b[0]);
        acc.y += __half2float(vh.b[1]) + __half2float(vl.b[1]);
        acc.z += __half2float(vh.b[2]) + __half2float(vl.b[2]);
        acc.w += __half2float(vh.b[3]) + __half2float(vl.b[3]);
    }
    float inv = g_inv_deg[node];
    union { fp16 b[4]; uint2 u; } ph, pl;
    split_f16(acc.x * inv, ph.b[0], pl.b[0]);
    split_f16(acc.y * inv, ph.b[1], pl.b[1]);
    split_f16(acc.z * inv, ph.b[2], pl.b[2]);
    split_f16(acc.w * inv, ph.b[3], pl.b[3]);
    size_t o = (size_t)e * ND + (size_t)i * D + c;
    *(uint2*)&g_cahi[o] = ph.u;
    *(uint2*)&g_calo[o] = pl.u;
}

// ---------------------------------------------------------------------------
// Tensor-core GEMM: ldmatrix + 2-stage cp.async, ONE barrier per iteration,
// 2 CTAs/SM. layer==1: dense rows, store h1[e]. layer==2: compacted rows,
// deterministic atomicAdd combine (exactly 2 contributions per element).
// ---------------------------------------------------------------------------
#define ROWB 80
#define TILE_B (128 * ROWB)
#define STAGE_B (4 * TILE_B)       // 40960
#define GEMM_SMEM (2 * STAGE_B)    // 81920/CTA -> 2 CTAs/SM

__device__ __forceinline__ uint32_t smem_u32(const void* p) {
    uint32_t a;
    asm("{ .reg .u64 t; cvta.to.shared.u64 t, %1; cvt.u32.u64 %0, t; }"
        : "=r"(a) : "l"(p));
    return a;
}
__device__ __forceinline__ void cp16(uint32_t dst, const void* src) {
    asm volatile("cp.async.cg.shared.global [%0], [%1], 16;" :: "r"(dst), "l"(src));
}
__device__ __forceinline__ void ldmx4(uint32_t* r, uint32_t addr) {
    asm volatile("ldmatrix.sync.aligned.m8n8.x4.shared.b16 {%0,%1,%2,%3}, [%4];"
                 : "=r"(r[0]), "=r"(r[1]), "=r"(r[2]), "=r"(r[3]) : "r"(addr));
}
__device__ __forceinline__ void mma16816(float* c, const uint32_t* a, const uint32_t* b) {
    asm volatile("mma.sync.aligned.m16n8k16.row.col.f32.f16.f16.f32 "
                 "{%0,%1,%2,%3}, {%4,%5,%6,%7}, {%8,%9}, {%0,%1,%2,%3};"
                 : "+f"(c[0]), "+f"(c[1]), "+f"(c[2]), "+f"(c[3])
                 : "r"(a[0]), "r"(a[1]), "r"(a[2]), "r"(a[3]), "r"(b[0]), "r"(b[1]));
}

__global__ void __launch_bounds__(256, 2)
sage_gemm_mma(int layer, const float* __restrict__ blv, float* __restrict__ out) {
    extern __shared__ char smem[];
    uint32_t sb = smem_u32(smem);
    int tid = threadIdx.x, lane = tid & 31, wid = tid >> 5;
    int wm = wid >> 2, wn = wid & 3;
    int g = lane >> 2, lam = lane & 3;
    int bn = blockIdx.x * 128, bm = blockIdx.y * 128;
    int e = blockIdx.z;
    int w_idx = (layer == 1) ? 2 * e : 2 * e + 1;
    const float* __restrict__ bias = blv + w_idx * 512;

    int cnt = 0;
    if (layer == 2) {
        cnt = g_cnt[e];
        if (bm >= cnt) return;
    }

    const fp16* __restrict__ bh = g_wthi + (size_t)w_idx * 512 * 1024;
    const fp16* __restrict__ bl = g_wtlo + (size_t)w_idx * 512 * 1024;

    int row_s = tid >> 2, kc_s = tid & 3;
    int row_s2 = (tid + 256) >> 2, kc_s2 = (tid + 256) & 3;

    size_t aoff_s, aoff_s2, hoff_s, hoff_s2;
    const fp16 *p_ah, *p_al, *p_hh, *p_hl;
    if (layer == 1) {
        p_ah = g_ahi; p_al = g_alo;
        p_hh = g_xhi; p_hl = g_xlo;
        aoff_s = (size_t)(bm + row_s) * 512;  aoff_s2 = (size_t)(bm + row_s2) * 512;
        hoff_s = aoff_s;                      hoff_s2 = aoff_s2;
    } else {
        p_ah = g_cahi + (size_t)e * ND; p_al = g_calo + (size_t)e * ND;
        p_hh = g_h1hi + (size_t)e * ND; p_hl = g_h1lo + (size_t)e * ND;
        int cr_s = min(bm + row_s, cnt - 1), cr_s2 = min(bm + row_s2, cnt - 1);
        aoff_s = (size_t)cr_s * 512;  aoff_s2 = (size_t)cr_s2 * 512;
        hoff_s = (size_t)g_rows[e][cr_s] * 512;
        hoff_s2 = (size_t)g_rows[e][cr_s2] * 512;
    }

    float c[4][4][4];
#pragma unroll
    for (int i = 0; i < 4; i++)
#pragma unroll
        for (int j = 0; j < 4; j++)
#pragma unroll
            for (int q = 0; q < 4; q++) c[i][j][q] = 0.f;

    auto load_stage = [&](int n) {
        uint32_t st = sb + (n & 1) * STAGE_B;
        int ka = (n & 15) * 32, kb = n * 32;
        const fp16 *Ah, *Al;
        size_t o1, o2;
        if (n < 16) { Ah = p_ah; Al = p_al; o1 = aoff_s; o2 = aoff_s2; }
        else        { Ah = p_hh; Al = p_hl; o1 = hoff_s; o2 = hoff_s2; }
        uint32_t d1 = st + row_s * ROWB + kc_s * 16;
        uint32_t d2 = st + row_s2 * ROWB + kc_s2 * 16;
        cp16(d1 + 0 * TILE_B, Ah + o1 + ka + kc_s * 8);
        cp16(d2 + 0 * TILE_B, Ah + o2 + ka + kc_s2 * 8);
        cp16(d1 + 1 * TILE_B, Al + o1 + ka + kc_s * 8);
        cp16(d2 + 1 * TILE_B, Al + o2 + ka + kc_s2 * 8);
        cp16(d1 + 2 * TILE_B, bh + (size_t)(bn + row_s) * 1024 + kb + kc_s * 8);
        cp16(d2 + 2 * TILE_B, bh + (size_t)(bn + row_s2) * 1024 + kb + kc_s2 * 8);
        cp16(d1 + 3 * TILE_B, bl + (size_t)(bn + row_s) * 1024 + kb + kc_s * 8);
        cp16(d2 + 3 * TILE_B, bl + (size_t)(bn + row_s2) * 1024 + kb + kc_s2 * 8);
    };

    // ONE barrier per iteration: wait stage it -> barrier (also proves all
    // threads finished compute(it-1), so issuing the it+1 load after it is
    // write-after-read safe) -> issue load it+1 -> compute it (overlapped).
    load_stage(0);
    asm volatile("cp.async.commit_group;");

    for (int it = 0; it < 32; it++) {
        asm volatile("cp.async.wait_group 0;");
        __syncthreads();
        if (it + 1 < 32) {
            load_stage(it + 1);
            asm volatile("cp.async.commit_group;");
        }

        uint32_t st = sb + (it & 1) * STAGE_B;
#pragma unroll
        for (int ks = 0; ks < 2; ks++) {
            uint32_t aH[4][4], aL[4][4];
#pragma unroll
            for (int mb = 0; mb < 4; mb++) {
                uint32_t ra = st + (wm * 64 + mb * 16 + (lane & 15)) * ROWB
                              + ks * 32 + ((lane >> 4) << 4);
                ldmx4(aH[mb], ra);
                ldmx4(aL[mb], ra + TILE_B);
            }
#pragma unroll
            for (int np = 0; np < 2; np++) {
                int brow = wn * 32 + np * 16 + (lane & 7) + ((lane & 16) ? 8 : 0);
                uint32_t rb = st + 2 * TILE_B + brow * ROWB + ks * 32
                              + ((lane & 8) ? 16 : 0);
                uint32_t qh[4], ql[4];
                ldmx4(qh, rb);
                ldmx4(ql, rb + TILE_B);
#pragma unroll
                for (int mb = 0; mb < 4; mb++) {
                    mma16816(c[mb][np * 2],     aH[mb], qh);
                    mma16816(c[mb][np * 2],     aH[mb], ql);
                    mma16816(c[mb][np * 2],     aL[mb], qh);
                    mma16816(c[mb][np * 2 + 1], aH[mb], qh + 2);
                    mma16816(c[mb][np * 2 + 1], aH[mb], ql + 2);
                    mma16816(c[mb][np * 2 + 1], aL[mb], qh + 2);
                }
            }
        }
    }
    __syncthreads();

    // Epilogue: fragments -> SMEM fp32 -> coalesced / atomic stores
    float* sep = (float*)smem;  // [128][132] = 67584 <= 81920
#pragma unroll
    for (int mb = 0; mb < 4; mb++)
#pragma unroll
        for (int nb = 0; nb < 4; nb++)
#pragma unroll
            for (int q = 0; q < 4; q++) {
                int row = wm * 64 + mb * 16 + g + ((q >> 1) << 3);
                int col = wn * 32 + nb * 8 + 2 * lam + (q & 1);
                sep[row * 132 + col] = c[mb][nb][q];
            }
    __syncthreads();

    if (layer == 1) {
        fp16* ohi = g_h1hi + (size_t)e * ND;
        fp16* olo = g_h1lo + (size_t)e * ND;
        int w = tid & 63, rs = tid >> 6;
        float b0 = bias[bn + 2 * w], b1 = bias[bn + 2 * w + 1];
#pragma unroll
        for (int it = 0; it < 32; it++) {
            int rr = rs + it * 4;
            float v0 = fmaxf(sep[rr * 132 + 2 * w] + b0, 0.f);
            float v1 = fmaxf(sep[rr * 132 + 2 * w + 1] + b1, 0.f);
            union { fp16 b[2]; uint32_t u; } ph, pl;
            split_f16(v0, ph.b[0], pl.b[0]);
            split_f16(v1, ph.b[1], pl.b[1]);
            size_t o = (size_t)(bm + rr) * D + bn + 2 * w;
            *(uint32_t*)&ohi[o] = ph.u;
            *(uint32_t*)&olo[o] = pl.u;
        }
    } else {
        // Deterministic: each out element gets exactly 2 atomic contributions
        // onto zeroed memory; fl(a+b) is order-independent for two terms.
        float4 bc = *(const float4*)&bias[bn + lane * 4];
#pragma unroll
        for (int it = 0; it < 16; it++) {
            int rr = wid + it * 8;
            if (bm + rr < cnt) {
                int m = g_rows[e][bm + rr];
                float gw = g_gatew[m * 4 + e];
                float* p = out + (size_t)m * D + bn + lane * 4;
                atomicAdd(p + 0, gw * fmaxf(sep[rr * 132 + lane * 4 + 0] + bc.x, 0.f));
                atomicAdd(p + 1, gw * fmaxf(sep[rr * 132 + lane * 4 + 1] + bc.y, 0.f));
                atomicAdd(p + 2, gw * fmaxf(sep[rr * 132 + lane * 4 + 2] + bc.z, 0.f));
                atomicAdd(p + 3, gw * fmaxf(sep[rr * 132 + lane * 4 + 3] + bc.w, 0.f));
            }
        }
    }
}

// ---------------------------------------------------------------------------
// Launch — only harness pointers and integers cross the host boundary.
// ---------------------------------------------------------------------------
extern "C" void kernel_launch(void* const* d_in, const int* in_sizes, int n_in,
                              void* d_out, int out_size) {
    const float* x = 0; const float* gW = 0; const float* gb = 0;
    const float* Wl = 0; const float* blv = 0; const float* Wr = 0;
    const int*   ei = 0;
    for (int i = 0; i < n_in; i++) {
        long long s = in_sizes[i];
        if (s == 16777216)      { if (!x)  x  = (const float*)d_in[i]; }
        else if (s == 2048)     { if (!gW) gW = (const float*)d_in[i]; }
        else if (s == 4)        { if (!gb) gb = (const float*)d_in[i]; }
        else if (s == 2097152)  { if (!Wl) Wl = (const float*)d_in[i];
                                  else if (!Wr) Wr = (const float*)d_in[i]; }
        else if (s == 4096)     { if (!blv) blv = (const float*)d_in[i]; }
        else if (s == 524288)   { if (!ei) ei = (const int*)d_in[i]; }
    }
    if (!x)   x   = (const float*)d_in[0];
    if (!gW)  gW  = (const float*)d_in[1];
    if (!gb)  gb  = (const float*)d_in[2];
    if (!Wl)  Wl  = (const float*)d_in[3];
    if (!blv) blv = (const float*)d_in[4];
    if (!Wr)  Wr  = (const float*)d_in[5];
    if (!ei)  ei  = (const int*)d_in[6];
    float* out = (float*)d_out;

    cudaFuncSetAttribute(sage_gemm_mma,
                         cudaFuncAttributeMaxDynamicSharedMemorySize, GEMM_SMEM);

    init_kernel<<<N_NODES / 256, 256>>>(ei);
    deg_kernel<<<N_EDGES / 256, 256>>>(ei);
    scan1_kernel<<<128, 256>>>();
    scan2_kernel<<<1, 128>>>();
    scan3_kernel<<<128, 256>>>();
    fill_kernel<<<N_EDGES / 256, 256>>>(ei);
    gate_kernel<<<N_NODES / 8, 256>>>(x, gW, gb);    // also writes x hi/lo
    prep_w_kernel<<<dim3(32, 16, 8), dim3(32, 32)>>>(Wl, Wr);

    // Layer 1: shared aggr(x), all 4 experts batched
    aggregate_x_kernel<<<N_NODES, 128>>>(x);
    sage_gemm_mma<<<dim3(4, 256, 4), 256, GEMM_SMEM>>>(1, blv, out);

    // Layer 2: compact aggregations, then ONE batched GEMM launch (z=4)
    // with deterministic atomic gated-combine.
    cudaMemsetAsync(out, 0, (size_t)out_size * sizeof(float));
    aggregate_h2_kernel<<<dim3(N_NODES, NEXP), 128>>>();
    sage_gemm_mma<<<dim3(4, 256, 4), 256, GEMM_SMEM>>>(2, blv, out);
}

// round 15
// speedup vs baseline: 2.8150x; 1.0063x over previous
#include <cuda_runtime.h>
#include <cuda_fp16.h>
#include <cstdint>

// ---------------------------------------------------------------------------
// MoE GraphSAGE, mma.sync m16n8k16 fp16 (fp32 accum), fp16x3 split GEMM.
// R15: revert to single-stream R13 structure (stream/event creation allocates
// device memory -> forbidden). New: 4-way MLP-unrolled aggregation loops
// (bitwise-identical accumulation order). Everything else == R13 (1948us).
// ---------------------------------------------------------------------------

#define N_NODES 32768
#define N_EDGES 262144
#define D 512
#define NEXP 4
#define ND (N_NODES * D)

typedef __half fp16;

__device__ fp16  g_xhi[ND], g_xlo[ND];
__device__ fp16  g_ahi[ND], g_alo[ND];            // layer-1 aggr (all nodes)
__device__ fp16  g_cahi[(size_t)NEXP * ND];       // layer-2 compact aggr
__device__ fp16  g_calo[(size_t)NEXP * ND];
__device__ fp16  g_h1hi[(size_t)NEXP * ND];
__device__ fp16  g_h1lo[(size_t)NEXP * ND];
__device__ fp16  g_wthi[8ull * 512 * 1024];       // [w_idx][n][k]
__device__ fp16  g_wtlo[8ull * 512 * 1024];
__device__ float g_inv_deg[N_NODES];
__device__ int   g_deg[N_NODES];
__device__ int   g_rowptr[N_NODES + 1];
__device__ int   g_cursor[N_NODES];
__device__ int   g_colidx[N_EDGES];
__device__ float g_gatew[N_NODES * NEXP];
__device__ int   g_rows[NEXP][N_NODES];
__device__ int   g_cnt[NEXP];
__device__ int   g_pre[N_NODES];
__device__ int   g_bsum[128];
__device__ int   g_is64;

__device__ __forceinline__ void split_f16(float v, fp16& h, fp16& l) {
    h = __float2half_rn(v);
    l = __float2half_rn(v - __half2float(h));
}

// ---------------------------------------------------------------------------
// Init (detect dtype + zero counters) + CSR
// ---------------------------------------------------------------------------
__global__ void init_kernel(const int* __restrict__ ei32) {
    int i = blockIdx.x * blockDim.x + threadIdx.x;
    if (i < N_NODES) g_deg[i] = 0;
    if (i < NEXP) g_cnt[i] = 0;
    if (i == 0) {
        int is64 = 1;
        for (int k = 0; k < 128; k++)
            if (ei32[2 * k + 1] != 0) { is64 = 0; break; }
        g_is64 = is64;
    }
}
__device__ __forceinline__ int edge_val(const int* __restrict__ e, int idx, int is64) {
    return is64 ? e[2 * idx] : e[idx];
}
__global__ void deg_kernel(const int* __restrict__ ei32) {
    int i = blockIdx.x * blockDim.x + threadIdx.x;
    if (i < N_EDGES) atomicAdd(&g_deg[edge_val(ei32, N_EDGES + i, g_is64)], 1);
}
__global__ void scan1_kernel() {
    __shared__ int sm[256];
    int t = threadIdx.x, i = blockIdx.x * 256 + t;
    sm[t] = g_deg[i];
    __syncthreads();
    for (int off = 1; off < 256; off <<= 1) {
        int v = (t >= off) ? sm[t - off] : 0;
        __syncthreads();
        sm[t] += v;
        __syncthreads();
    }
    g_pre[i] = sm[t];
    if (t == 255) g_bsum[blockIdx.x] = sm[255];
}
__global__ void scan2_kernel() {
    __shared__ int sm[128];
    int t = threadIdx.x;
    int orig = g_bsum[t];
    sm[t] = orig;
    __syncthreads();
    for (int off = 1; off < 128; off <<= 1) {
        int v = (t >= off) ? sm[t - off] : 0;
        __syncthreads();
        sm[t] += v;
        __syncthreads();
    }
    g_bsum[t] = sm[t] - orig;
    if (t == 127) g_rowptr[N_NODES] = sm[127];
}
__global__ void scan3_kernel() {
    int i = blockIdx.x * 256 + threadIdx.x;
    int d = g_deg[i];
    int rp = g_bsum[blockIdx.x] + g_pre[i] - d;
    g_rowptr[i] = rp;
    g_cursor[i] = rp;
    g_inv_deg[i] = (d > 0) ? 1.0f / (float)d : 0.0f;
}
__global__ void fill_kernel(const int* __restrict__ ei32) {
    int i = blockIdx.x * blockDim.x + threadIdx.x;
    if (i < N_EDGES) {
        int is64 = g_is64;
        int src = edge_val(ei32, i, is64);
        int dst = edge_val(ei32, N_EDGES + i, is64);
        g_colidx[atomicAdd(&g_cursor[dst], 1)] = src;
    }
}

// ---------------------------------------------------------------------------
// Gate + active-row lists + x -> fp16 hi/lo (fused)
// ---------------------------------------------------------------------------
__global__ void gate_kernel(const float* __restrict__ x,
                            const float* __restrict__ gW,
                            const float* __restrict__ gb) {
    int gtid = blockIdx.x * blockDim.x + threadIdx.x;
    int node = gtid >> 5, lane = gtid & 31;
    if (node >= N_NODES) return;
    const float* xr = x + (size_t)node * D;
    fp16* xh = g_xhi + (size_t)node * D;
    fp16* xl = g_xlo + (size_t)node * D;
    float a0 = 0.f, a1 = 0.f, a2 = 0.f, a3 = 0.f;
    for (int i = lane; i < D; i += 32) {
        float xv = xr[i];
        fp16 h, l;
        split_f16(xv, h, l);
        xh[i] = h;
        xl[i] = l;
        float4 w = *(const float4*)&gW[i * 4];
        a0 = fmaf(xv, w.x, a0); a1 = fmaf(xv, w.y, a1);
        a2 = fmaf(xv, w.z, a2); a3 = fmaf(xv, w.w, a3);
    }
#pragma unroll
    for (int off = 16; off; off >>= 1) {
        a0 += __shfl_down_sync(0xffffffffu, a0, off);
        a1 += __shfl_down_sync(0xffffffffu, a1, off);
        a2 += __shfl_down_sync(0xffffffffu, a2, off);
        a3 += __shfl_down_sync(0xffffffffu, a3, off);
    }
    if (lane == 0) {
        float l[4] = {a0 + gb[0], a1 + gb[1], a2 + gb[2], a3 + gb[3]};
        float m = fmaxf(fmaxf(l[0], l[1]), fmaxf(l[2], l[3]));
        float e[4], s = 0.f;
#pragma unroll
        for (int k = 0; k < 4; k++) { e[k] = expf(l[k] - m); s += e[k]; }
        float inv = 1.0f / s;
        float p[4];
#pragma unroll
        for (int k = 0; k < 4; k++) p[k] = e[k] * inv;
        int i1 = 0;
#pragma unroll
        for (int k = 1; k < 4; k++) if (p[k] > p[i1]) i1 = k;
        int i2 = -1;
#pragma unroll
        for (int k = 0; k < 4; k++) {
            if (k == i1) continue;
            if (i2 < 0 || p[k] > p[i2]) i2 = k;
        }
#pragma unroll
        for (int k = 0; k < 4; k++)
            g_gatew[node * 4 + k] = (k == i1) ? p[i1] : ((k == i2) ? p[i2] : 0.0f);
        int p1 = atomicAdd(&g_cnt[i1], 1);
        g_rows[i1][p1] = node;
        int p2 = atomicAdd(&g_cnt[i2], 1);
        g_rows[i2][p2] = node;
    }
}

// ---------------------------------------------------------------------------
// Weight prep
// ---------------------------------------------------------------------------
__global__ void prep_w_kernel(const float* __restrict__ Wl, const float* __restrict__ Wr) {
    __shared__ float sm[32][33];
    int m = blockIdx.z;
    int k0 = blockIdx.x * 32, n0 = blockIdx.y * 32;
    int tx = threadIdx.x, ty = threadIdx.y;
    const float* W = (k0 < 512) ? (Wl + (size_t)m * 512 * 512 + (size_t)(k0 + ty) * 512)
                                : (Wr + (size_t)m * 512 * 512 + (size_t)(k0 - 512 + ty) * 512);
    sm[ty][tx] = W[n0 + tx];
    __syncthreads();
    float v = sm[tx][ty];
    fp16 h, l;
    split_f16(v, h, l);
    size_t o = (size_t)m * 512 * 1024 + (size_t)(n0 + ty) * 1024 + (k0 + tx);
    g_wthi[o] = h;
    g_wtlo[o] = l;
}

// ---------------------------------------------------------------------------
// Aggregations — 4-way MLP-unrolled neighbor loops (order-preserving)
// ---------------------------------------------------------------------------
__global__ void aggregate_x_kernel(const float* __restrict__ x) {
    int node = blockIdx.x;
    int c = threadIdx.x * 4;
    float4 acc = make_float4(0.f, 0.f, 0.f, 0.f);
    int beg = g_rowptr[node], end = g_rowptr[node + 1];
    int j = beg;
    for (; j + 4 <= end; j += 4) {
        int s0 = g_colidx[j],     s1 = g_colidx[j + 1];
        int s2 = g_colidx[j + 2], s3 = g_colidx[j + 3];
        float4 v0 = *(const float4*)&x[(size_t)s0 * D + c];
        float4 v1 = *(const float4*)&x[(size_t)s1 * D + c];
        float4 v2 = *(const float4*)&x[(size_t)s2 * D + c];
        float4 v3 = *(const float4*)&x[(size_t)s3 * D + c];
        acc.x += v0.x; acc.y += v0.y; acc.z += v0.z; acc.w += v0.w;
        acc.x += v1.x; acc.y += v1.y; acc.z += v1.z; acc.w += v1.w;
        acc.x += v2.x; acc.y += v2.y; acc.z += v2.z; acc.w += v2.w;
        acc.x += v3.x; acc.y += v3.y; acc.z += v3.z; acc.w += v3.w;
    }
    for (; j < end; j++) {
        float4 v = *(const float4*)&x[(size_t)g_colidx[j] * D + c];
        acc.x += v.x; acc.y += v.y; acc.z += v.z; acc.w += v.w;
    }
    float inv = g_inv_deg[node];
    union { fp16 b[4]; uint2 u; } ph, pl;
    split_f16(acc.x * inv, ph.b[0], pl.b[0]);
    split_f16(acc.y * inv, ph.b[1], pl.b[1]);
    split_f16(acc.z * inv, ph.b[2], pl.b[2]);
    split_f16(acc.w * inv, ph.b[3], pl.b[3]);
    *(uint2*)&g_ahi[(size_t)node * D + c] = ph.u;
    *(uint2*)&g_alo[(size_t)node * D + c] = pl.u;
}

__device__ __forceinline__ void acc_hl(float4& acc, uint2 uh, uint2 ul) {
    union { fp16 b[4]; uint2 u; } vh, vl;
    vh.u = uh; vl.u = ul;
    acc.x += __half2float(vh.b[0]) + __half2float(vl.b[0]);
    acc.y += __half2float(vh.b[1]) + __half2float(vl.b[1]);
    acc.z += __half2float(vh.b[2]) + __half2float(vl.b[2]);
    acc.w += __half2float(vh.b[3]) + __half2float(vl.b[3]);
}

__global__ void aggregate_h2_kernel() {
    int e = blockIdx.y;
    int i = blockIdx.x;
    if (i >= g_cnt[e]) return;
    int node = g_rows[e][i];
    const fp16* __restrict__ hh = g_h1hi + (size_t)e * ND;
    const fp16* __restrict__ hl = g_h1lo + (size_t)e * ND;
    int c = threadIdx.x * 4;
    float4 acc = make_float4(0.f, 0.f, 0.f, 0.f);
    int beg = g_rowptr[node], end = g_rowptr[node + 1];
    int j = beg;
    for (; j + 4 <= end; j += 4) {
        int s0 = g_colidx[j],     s1 = g_colidx[j + 1];
        int s2 = g_colidx[j + 2], s3 = g_colidx[j + 3];
        size_t b0 = (size_t)s0 * D + c, b1 = (size_t)s1 * D + c;
        size_t b2 = (size_t)s2 * D + c, b3 = (size_t)s3 * D + c;
        uint2 h0 = *(const uint2*)&hh[b0], l0 = *(const uint2*)&hl[b0];
        uint2 h1 = *(const uint2*)&hh[b1], l1 = *(const uint2*)&hl[b1];
        uint2 h2 = *(const uint2*)&hh[b2], l2 = *(const uint2*)&hl[b2];
        uint2 h3 = *(const uint2*)&hh[b3], l3 = *(const uint2*)&hl[b3];
        acc_hl(acc, h0, l0);
        acc_hl(acc, h1, l1);
        acc_hl(acc, h2, l2);
        acc_hl(acc, h3, l3);
    }
    for (; j < end; j++) {
        size_t base = (size_t)g_colidx[j] * D + c;
        acc_hl(acc, *(const uint2*)&hh[base], *(const uint2*)&hl[base]);
    }
    float inv = g_inv_deg[node];
    union { fp16 b[4]; uint2 u; } ph, pl;
    split_f16(acc.x * inv, ph.b[0], pl.b[0]);
    split_f16(acc.y * inv, ph.b[1], pl.b[1]);
    split_f16(acc.z * inv, ph.b[2], pl.b[2]);
    split_f16(acc.w * inv, ph.b[3], pl.b[3]);
    size_t o = (size_t)e * ND + (size_t)i * D + c;
    *(uint2*)&g_cahi[o] = ph.u;
    *(uint2*)&g_calo[o] = pl.u;
}

// ---------------------------------------------------------------------------
// Tensor-core GEMM (R13-verified): ldmatrix + 2-stage cp.async, one barrier
// per iteration, 2 CTAs/SM. layer==1: dense rows, store h1[e]. layer==2:
// compacted rows, deterministic atomicAdd combine.
// ---------------------------------------------------------------------------
#define ROWB 80
#define TILE_B (128 * ROWB)
#define STAGE_B (4 * TILE_B)       // 40960
#define GEMM_SMEM (2 * STAGE_B)    // 81920/CTA -> 2 CTAs/SM

__device__ __forceinline__ uint32_t smem_u32(const void* p) {
    uint32_t a;
    asm("{ .reg .u64 t; cvta.to.shared.u64 t, %1; cvt.u32.u64 %0, t; }"
        : "=r"(a) : "l"(p));
    return a;
}
__device__ __forceinline__ void cp16(uint32_t dst, const void* src) {
    asm volatile("cp.async.cg.shared.global [%0], [%1], 16;" :: "r"(dst), "l"(src));
}
__device__ __forceinline__ void ldmx4(uint32_t* r, uint32_t addr) {
    asm volatile("ldmatrix.sync.aligned.m8n8.x4.shared.b16 {%0,%1,%2,%3}, [%4];"
                 : "=r"(r[0]), "=r"(r[1]), "=r"(r[2]), "=r"(r[3]) : "r"(addr));
}
__device__ __forceinline__ void mma16816(float* c, const uint32_t* a, const uint32_t* b) {
    asm volatile("mma.sync.aligned.m16n8k16.row.col.f32.f16.f16.f32 "
                 "{%0,%1,%2,%3}, {%4,%5,%6,%7}, {%8,%9}, {%0,%1,%2,%3};"
                 : "+f"(c[0]), "+f"(c[1]), "+f"(c[2]), "+f"(c[3])
                 : "r"(a[0]), "r"(a[1]), "r"(a[2]), "r"(a[3]), "r"(b[0]), "r"(b[1]));
}

__global__ void __launch_bounds__(256, 2)
sage_gemm_mma(int layer, const float* __restrict__ blv, float* __restrict__ out) {
    extern __shared__ char smem[];
    uint32_t sb = smem_u32(smem);
    int tid = threadIdx.x, lane = tid & 31, wid = tid >> 5;
    int wm = wid >> 2, wn = wid & 3;
    int g = lane >> 2, lam = lane & 3;
    int bn = blockIdx.x * 128, bm = blockIdx.y * 128;
    int e = blockIdx.z;
    int w_idx = (layer == 1) ? 2 * e : 2 * e + 1;
    const float* __restrict__ bias = blv + w_idx * 512;

    int cnt = 0;
    if (layer == 2) {
        cnt = g_cnt[e];
        if (bm >= cnt) return;
    }

    const fp16* __restrict__ bh = g_wthi + (size_t)w_idx * 512 * 1024;
    const fp16* __restrict__ bl = g_wtlo + (size_t)w_idx * 512 * 1024;

    int row_s = tid >> 2, kc_s = tid & 3;
    int row_s2 = (tid + 256) >> 2, kc_s2 = (tid + 256) & 3;

    size_t aoff_s, aoff_s2, hoff_s, hoff_s2;
    const fp16 *p_ah, *p_al, *p_hh, *p_hl;
    if (layer == 1) {
        p_ah = g_ahi; p_al = g_alo;
        p_hh = g_xhi; p_hl = g_xlo;
        aoff_s = (size_t)(bm + row_s) * 512;  aoff_s2 = (size_t)(bm + row_s2) * 512;
        hoff_s = aoff_s;                      hoff_s2 = aoff_s2;
    } else {
        p_ah = g_cahi + (size_t)e * ND; p_al = g_calo + (size_t)e * ND;
        p_hh = g_h1hi + (size_t)e * ND; p_hl = g_h1lo + (size_t)e * ND;
        int cr_s = min(bm + row_s, cnt - 1), cr_s2 = min(bm + row_s2, cnt - 1);
        aoff_s = (size_t)cr_s * 512;  aoff_s2 = (size_t)cr_s2 * 512;
        hoff_s = (size_t)g_rows[e][cr_s] * 512;
        hoff_s2 = (size_t)g_rows[e][cr_s2] * 512;
    }

    float c[4][4][4];
#pragma unroll
    for (int i = 0; i < 4; i++)
#pragma unroll
        for (int j = 0; j < 4; j++)
#pragma unroll
            for (int q = 0; q < 4; q++) c[i][j][q] = 0.f;

    auto load_stage = [&](int n) {
        uint32_t st = sb + (n & 1) * STAGE_B;
        int ka = (n & 15) * 32, kb = n * 32;
        const fp16 *Ah, *Al;
        size_t o1, o2;
        if (n < 16) { Ah = p_ah; Al = p_al; o1 = aoff_s; o2 = aoff_s2; }
        else        { Ah = p_hh; Al = p_hl; o1 = hoff_s; o2 = hoff_s2; }
        uint32_t d1 = st + row_s * ROWB + kc_s * 16;
        uint32_t d2 = st + row_s2 * ROWB + kc_s2 * 16;
        cp16(d1 + 0 * TILE_B, Ah + o1 + ka + kc_s * 8);
        cp16(d2 + 0 * TILE_B, Ah + o2 + ka + kc_s2 * 8);
        cp16(d1 + 1 * TILE_B, Al + o1 + ka + kc_s * 8);
        cp16(d2 + 1 * TILE_B, Al + o2 + ka + kc_s2 * 8);
        cp16(d1 + 2 * TILE_B, bh + (size_t)(bn + row_s) * 1024 + kb + kc_s * 8);
        cp16(d2 + 2 * TILE_B, bh + (size_t)(bn + row_s2) * 1024 + kb + kc_s2 * 8);
        cp16(d1 + 3 * TILE_B, bl + (size_t)(bn + row_s) * 1024 + kb + kc_s * 8);
        cp16(d2 + 3 * TILE_B, bl + (size_t)(bn + row_s2) * 1024 + kb + kc_s2 * 8);
    };

    load_stage(0);
    asm volatile("cp.async.commit_group;");

    for (int it = 0; it < 32; it++) {
        asm volatile("cp.async.wait_group 0;");
        __syncthreads();
        if (it + 1 < 32) {
            load_stage(it + 1);
            asm volatile("cp.async.commit_group;");
        }

        uint32_t st = sb + (it & 1) * STAGE_B;
#pragma unroll
        for (int ks = 0; ks < 2; ks++) {
            uint32_t aH[4][4], aL[4][4];
#pragma unroll
            for (int mb = 0; mb < 4; mb++) {
                uint32_t ra = st + (wm * 64 + mb * 16 + (lane & 15)) * ROWB
                              + ks * 32 + ((lane >> 4) << 4);
                ldmx4(aH[mb], ra);
                ldmx4(aL[mb], ra + TILE_B);
            }
#pragma unroll
            for (int np = 0; np < 2; np++) {
                int brow = wn * 32 + np * 16 + (lane & 7) + ((lane & 16) ? 8 : 0);
                uint32_t rb = st + 2 * TILE_B + brow * ROWB + ks * 32
                              + ((lane & 8) ? 16 : 0);
                uint32_t qh[4], ql[4];
                ldmx4(qh, rb);
                ldmx4(ql, rb + TILE_B);
#pragma unroll
                for (int mb = 0; mb < 4; mb++) {
                    mma16816(c[mb][np * 2],     aH[mb], qh);
                    mma16816(c[mb][np * 2],     aH[mb], ql);
                    mma16816(c[mb][np * 2],     aL[mb], qh);
                    mma16816(c[mb][np * 2 + 1], aH[mb], qh + 2);
                    mma16816(c[mb][np * 2 + 1], aH[mb], ql + 2);
                    mma16816(c[mb][np * 2 + 1], aL[mb], qh + 2);
                }
            }
        }
    }
    __syncthreads();

    float* sep = (float*)smem;  // [128][132] = 67584 <= 81920
#pragma unroll
    for (int mb = 0; mb < 4; mb++)
#pragma unroll
        for (int nb = 0; nb < 4; nb++)
#pragma unroll
            for (int q = 0; q < 4; q++) {
                int row = wm * 64 + mb * 16 + g + ((q >> 1) << 3);
                int col = wn * 32 + nb * 8 + 2 * lam + (q & 1);
                sep[row * 132 + col] = c[mb][nb][q];
            }
    __syncthreads();

    if (layer == 1) {
        fp16* ohi = g_h1hi + (size_t)e * ND;
        fp16* olo = g_h1lo + (size_t)e * ND;
        int w = tid & 63, rs = tid >> 6;
        float b0 = bias[bn + 2 * w], b1 = bias[bn + 2 * w + 1];
#pragma unroll
        for (int it = 0; it < 32; it++) {
            int rr = rs + it * 4;
            float v0 = fmaxf(sep[rr * 132 + 2 * w] + b0, 0.f);
            float v1 = fmaxf(sep[rr * 132 + 2 * w + 1] + b1, 0.f);
            union { fp16 b[2]; uint32_t u; } ph, pl;
            split_f16(v0, ph.b[0], pl.b[0]);
            split_f16(v1, ph.b[1], pl.b[1]);
            size_t o = (size_t)(bm + rr) * D + bn + 2 * w;
            *(uint32_t*)&ohi[o] = ph.u;
            *(uint32_t*)&olo[o] = pl.u;
        }
    } else {
        // Deterministic: exactly 2 atomic contributions per element onto
        // zeroed memory; 2-term fp add commutes.
        float4 bc = *(const float4*)&bias[bn + lane * 4];
#pragma unroll
        for (int it = 0; it < 16; it++) {
            int rr = wid + it * 8;
            if (bm + rr < cnt) {
                int m = g_rows[e][bm + rr];
                float gw = g_gatew[m * 4 + e];
                float* p = out + (size_t)m * D + bn + lane * 4;
                atomicAdd(p + 0, gw * fmaxf(sep[rr * 132 + lane * 4 + 0] + bc.x, 0.f));
                atomicAdd(p + 1, gw * fmaxf(sep[rr * 132 + lane * 4 + 1] + bc.y, 0.f));
                atomicAdd(p + 2, gw * fmaxf(sep[rr * 132 + lane * 4 + 2] + bc.z, 0.f));
                atomicAdd(p + 3, gw * fmaxf(sep[rr * 132 + lane * 4 + 3] + bc.w, 0.f));
            }
        }
    }
}

// ---------------------------------------------------------------------------
// Launch — single stream (stream/event creation allocates -> forbidden).
// ---------------------------------------------------------------------------
extern "C" void kernel_launch(void* const* d_in, const int* in_sizes, int n_in,
                              void* d_out, int out_size) {
    const float* x = 0; const float* gW = 0; const float* gb = 0;
    const float* Wl = 0; const float* blv = 0; const float* Wr = 0;
    const int*   ei = 0;
    for (int i = 0; i < n_in; i++) {
        long long s = in_sizes[i];
        if (s == 16777216)      { if (!x)  x  = (const float*)d_in[i]; }
        else if (s == 2048)     { if (!gW) gW = (const float*)d_in[i]; }
        else if (s == 4)        { if (!gb) gb = (const float*)d_in[i]; }
        else if (s == 2097152)  { if (!Wl) Wl = (const float*)d_in[i];
                                  else if (!Wr) Wr = (const float*)d_in[i]; }
        else if (s == 4096)     { if (!blv) blv = (const float*)d_in[i]; }
        else if (s == 524288)   { if (!ei) ei = (const int*)d_in[i]; }
    }
    if (!x)   x   = (const float*)d_in[0];
    if (!gW)  gW  = (const float*)d_in[1];
    if (!gb)  gb  = (const float*)d_in[2];
    if (!Wl)  Wl  = (const float*)d_in[3];
    if (!blv) blv = (const float*)d_in[4];
    if (!Wr)  Wr  = (const float*)d_in[5];
    if (!ei)  ei  = (const int*)d_in[6];
    float* out = (float*)d_out;

    cudaFuncSetAttribute(sage_gemm_mma,
                         cudaFuncAttributeMaxDynamicSharedMemorySize, GEMM_SMEM);

    init_kernel<<<N_NODES / 256, 256>>>(ei);
    deg_kernel<<<N_EDGES / 256, 256>>>(ei);
    scan1_kernel<<<128, 256>>>();
    scan2_kernel<<<1, 128>>>();
    scan3_kernel<<<128, 256>>>();
    fill_kernel<<<N_EDGES / 256, 256>>>(ei);
    gate_kernel<<<N_NODES / 8, 256>>>(x, gW, gb);    // also writes x hi/lo
    prep_w_kernel<<<dim3(32, 16, 8), dim3(32, 32)>>>(Wl, Wr);

    // Layer 1: shared aggr(x), all 4 experts batched
    aggregate_x_kernel<<<N_NODES, 128>>>(x);
    sage_gemm_mma<<<dim3(4, 256, 4), 256, GEMM_SMEM>>>(1, blv, out);

    // Layer 2: compact aggregations (batched), then one batched GEMM launch
    // with deterministic atomic gated-combine.
    cudaMemsetAsync(out, 0, (size_t)out_size * sizeof(float));
    aggregate_h2_kernel<<<dim3(N_NODES, NEXP), 128>>>();
    sage_gemm_mma<<<dim3(4, 256, 4), 256, GEMM_SMEM>>>(2, blv, out);
}

// round 16
// speedup vs baseline: 3.9764x; 1.4126x over previous
#include <cuda_runtime.h>
#include <cuda_fp16.h>
#include <cstdint>

// ---------------------------------------------------------------------------
// MoE GraphSAGE, mma.sync m16n8k16 fp16 (fp32 accum).
// R16: 2-product split GEMM — C ~= Ahi@Bhi + Ahi@Blo (A-side lo dropped;
// weights keep hi+lo). Error budget: ~2e-4 << 1e-3 threshold (was 5e-6 with
// 3 products). All feature arrays stored fp16-only -> aggregation traffic
// halves; GEMM HMMA count -33%, cp.async -25%.
// Structure otherwise == R15-passing kernel (single stream; device-resolved
// globals; compacted layer 2; deterministic atomic combine).
// ---------------------------------------------------------------------------

#define N_NODES 32768
#define N_EDGES 262144
#define D 512
#define NEXP 4
#define ND (N_NODES * D)

typedef __half fp16;

__device__ fp16  g_x16[ND];                       // x as fp16 (RN)
__device__ fp16  g_a16[ND];                       // layer-1 aggr (all nodes)
__device__ fp16  g_ca16[(size_t)NEXP * ND];       // layer-2 compact aggr
__device__ fp16  g_h116[(size_t)NEXP * ND];       // layer-1 outputs
__device__ fp16  g_wthi[8ull * 512 * 1024];       // [w_idx][n][k]
__device__ fp16  g_wtlo[8ull * 512 * 1024];
__device__ float g_inv_deg[N_NODES];
__device__ int   g_deg[N_NODES];
__device__ int   g_rowptr[N_NODES + 1];
__device__ int   g_cursor[N_NODES];
__device__ int   g_colidx[N_EDGES];
__device__ float g_gatew[N_NODES * NEXP];
__device__ int   g_rows[NEXP][N_NODES];
__device__ int   g_cnt[NEXP];
__device__ int   g_pre[N_NODES];
__device__ int   g_bsum[128];
__device__ int   g_is64;

__device__ __forceinline__ void split_f16(float v, fp16& h, fp16& l) {
    h = __float2half_rn(v);
    l = __float2half_rn(v - __half2float(h));
}

// ---------------------------------------------------------------------------
// Init + CSR
// ---------------------------------------------------------------------------
__global__ void init_kernel(const int* __restrict__ ei32) {
    int i = blockIdx.x * blockDim.x + threadIdx.x;
    if (i < N_NODES) g_deg[i] = 0;
    if (i < NEXP) g_cnt[i] = 0;
    if (i == 0) {
        int is64 = 1;
        for (int k = 0; k < 128; k++)
            if (ei32[2 * k + 1] != 0) { is64 = 0; break; }
        g_is64 = is64;
    }
}
__device__ __forceinline__ int edge_val(const int* __restrict__ e, int idx, int is64) {
    return is64 ? e[2 * idx] : e[idx];
}
__global__ void deg_kernel(const int* __restrict__ ei32) {
    int i = blockIdx.x * blockDim.x + threadIdx.x;
    if (i < N_EDGES) atomicAdd(&g_deg[edge_val(ei32, N_EDGES + i, g_is64)], 1);
}
__global__ void scan1_kernel() {
    __shared__ int sm[256];
    int t = threadIdx.x, i = blockIdx.x * 256 + t;
    sm[t] = g_deg[i];
    __syncthreads();
    for (int off = 1; off < 256; off <<= 1) {
        int v = (t >= off) ? sm[t - off] : 0;
        __syncthreads();
        sm[t] += v;
        __syncthreads();
    }
    g_pre[i] = sm[t];
    if (t == 255) g_bsum[blockIdx.x] = sm[255];
}
__global__ void scan2_kernel() {
    __shared__ int sm[128];
    int t = threadIdx.x;
    int orig = g_bsum[t];
    sm[t] = orig;
    __syncthreads();
    for (int off = 1; off < 128; off <<= 1) {
        int v = (t >= off) ? sm[t - off] : 0;
        __syncthreads();
        sm[t] += v;
        __syncthreads();
    }
    g_bsum[t] = sm[t] - orig;
    if (t == 127) g_rowptr[N_NODES] = sm[127];
}
__global__ void scan3_kernel() {
    int i = blockIdx.x * 256 + threadIdx.x;
    int d = g_deg[i];
    int rp = g_bsum[blockIdx.x] + g_pre[i] - d;
    g_rowptr[i] = rp;
    g_cursor[i] = rp;
    g_inv_deg[i] = (d > 0) ? 1.0f / (float)d : 0.0f;
}
__global__ void fill_kernel(const int* __restrict__ ei32) {
    int i = blockIdx.x * blockDim.x + threadIdx.x;
    if (i < N_EDGES) {
        int is64 = g_is64;
        int src = edge_val(ei32, i, is64);
        int dst = edge_val(ei32, N_EDGES + i, is64);
        g_colidx[atomicAdd(&g_cursor[dst], 1)] = src;
    }
}

// ---------------------------------------------------------------------------
// Gate + active-row lists + x -> fp16 (fused)
// ---------------------------------------------------------------------------
__global__ void gate_kernel(const float* __restrict__ x,
                            const float* __restrict__ gW,
                            const float* __restrict__ gb) {
    int gtid = blockIdx.x * blockDim.x + threadIdx.x;
    int node = gtid >> 5, lane = gtid & 31;
    if (node >= N_NODES) return;
    const float* xr = x + (size_t)node * D;
    fp16* xh = g_x16 + (size_t)node * D;
    float a0 = 0.f, a1 = 0.f, a2 = 0.f, a3 = 0.f;
    for (int i = lane; i < D; i += 32) {
        float xv = xr[i];
        xh[i] = __float2half_rn(xv);
        float4 w = *(const float4*)&gW[i * 4];
        a0 = fmaf(xv, w.x, a0); a1 = fmaf(xv, w.y, a1);
        a2 = fmaf(xv, w.z, a2); a3 = fmaf(xv, w.w, a3);
    }
#pragma unroll
    for (int off = 16; off; off >>= 1) {
        a0 += __shfl_down_sync(0xffffffffu, a0, off);
        a1 += __shfl_down_sync(0xffffffffu, a1, off);
        a2 += __shfl_down_sync(0xffffffffu, a2, off);
        a3 += __shfl_down_sync(0xffffffffu, a3, off);
    }
    if (lane == 0) {
        float l[4] = {a0 + gb[0], a1 + gb[1], a2 + gb[2], a3 + gb[3]};
        float m = fmaxf(fmaxf(l[0], l[1]), fmaxf(l[2], l[3]));
        float e[4], s = 0.f;
#pragma unroll
        for (int k = 0; k < 4; k++) { e[k] = expf(l[k] - m); s += e[k]; }
        float inv = 1.0f / s;
        float p[4];
#pragma unroll
        for (int k = 0; k < 4; k++) p[k] = e[k] * inv;
        int i1 = 0;
#pragma unroll
        for (int k = 1; k < 4; k++) if (p[k] > p[i1]) i1 = k;
        int i2 = -1;
#pragma unroll
        for (int k = 0; k < 4; k++) {
            if (k == i1) continue;
            if (i2 < 0 || p[k] > p[i2]) i2 = k;
        }
#pragma unroll
        for (int k = 0; k < 4; k++)
            g_gatew[node * 4 + k] = (k == i1) ? p[i1] : ((k == i2) ? p[i2] : 0.0f);
        int p1 = atomicAdd(&g_cnt[i1], 1);
        g_rows[i1][p1] = node;
        int p2 = atomicAdd(&g_cnt[i2], 1);
        g_rows[i2][p2] = node;
    }
}

// ---------------------------------------------------------------------------
// Weight prep (weights keep full hi+lo split)
// ---------------------------------------------------------------------------
__global__ void prep_w_kernel(const float* __restrict__ Wl, const float* __restrict__ Wr) {
    __shared__ float sm[32][33];
    int m = blockIdx.z;
    int k0 = blockIdx.x * 32, n0 = blockIdx.y * 32;
    int tx = threadIdx.x, ty = threadIdx.y;
    const float* W = (k0 < 512) ? (Wl + (size_t)m * 512 * 512 + (size_t)(k0 + ty) * 512)
                                : (Wr + (size_t)m * 512 * 512 + (size_t)(k0 - 512 + ty) * 512);
    sm[ty][tx] = W[n0 + tx];
    __syncthreads();
    float v = sm[tx][ty];
    fp16 h, l;
    split_f16(v, h, l);
    size_t o = (size_t)m * 512 * 1024 + (size_t)(n0 + ty) * 1024 + (k0 + tx);
    g_wthi[o] = h;
    g_wtlo[o] = l;
}

// ---------------------------------------------------------------------------
// Aggregations (fp32 accumulate, fp16 in/out; 4-way unrolled)
// ---------------------------------------------------------------------------
__global__ void aggregate_x_kernel(const float* __restrict__ x) {
    int node = blockIdx.x;
    int c = threadIdx.x * 4;
    float4 acc = make_float4(0.f, 0.f, 0.f, 0.f);
    int beg = g_rowptr[node], end = g_rowptr[node + 1];
    int j = beg;
    for (; j + 4 <= end; j += 4) {
        int s0 = g_colidx[j],     s1 = g_colidx[j + 1];
        int s2 = g_colidx[j + 2], s3 = g_colidx[j + 3];
        float4 v0 = *(const float4*)&x[(size_t)s0 * D + c];
        float4 v1 = *(const float4*)&x[(size_t)s1 * D + c];
        float4 v2 = *(const float4*)&x[(size_t)s2 * D + c];
        float4 v3 = *(const float4*)&x[(size_t)s3 * D + c];
        acc.x += v0.x; acc.y += v0.y; acc.z += v0.z; acc.w += v0.w;
        acc.x += v1.x; acc.y += v1.y; acc.z += v1.z; acc.w += v1.w;
        acc.x += v2.x; acc.y += v2.y; acc.z += v2.z; acc.w += v2.w;
        acc.x += v3.x; acc.y += v3.y; acc.z += v3.z; acc.w += v3.w;
    }
    for (; j < end; j++) {
        float4 v = *(const float4*)&x[(size_t)g_colidx[j] * D + c];
        acc.x += v.x; acc.y += v.y; acc.z += v.z; acc.w += v.w;
    }
    float inv = g_inv_deg[node];
    union { fp16 b[4]; uint2 u; } p;
    p.b[0] = __float2half_rn(acc.x * inv);
    p.b[1] = __float2half_rn(acc.y * inv);
    p.b[2] = __float2half_rn(acc.z * inv);
    p.b[3] = __float2half_rn(acc.w * inv);
    *(uint2*)&g_a16[(size_t)node * D + c] = p.u;
}

__device__ __forceinline__ void acc_h4(float4& acc, uint2 uh) {
    union { fp16 b[4]; uint2 u; } v;
    v.u = uh;
    acc.x += __half2float(v.b[0]);
    acc.y += __half2float(v.b[1]);
    acc.z += __half2float(v.b[2]);
    acc.w += __half2float(v.b[3]);
}

__global__ void aggregate_h2_kernel() {
    int e = blockIdx.y;
    int i = blockIdx.x;
    if (i >= g_cnt[e]) return;
    int node = g_rows[e][i];
    const fp16* __restrict__ hh = g_h116 + (size_t)e * ND;
    int c = threadIdx.x * 4;
    float4 acc = make_float4(0.f, 0.f, 0.f, 0.f);
    int beg = g_rowptr[node], end = g_rowptr[node + 1];
    int j = beg;
    for (; j + 4 <= end; j += 4) {
        int s0 = g_colidx[j],     s1 = g_colidx[j + 1];
        int s2 = g_colidx[j + 2], s3 = g_colidx[j + 3];
        uint2 h0 = *(const uint2*)&hh[(size_t)s0 * D + c];
        uint2 h1 = *(const uint2*)&hh[(size_t)s1 * D + c];
        uint2 h2 = *(const uint2*)&hh[(size_t)s2 * D + c];
        uint2 h3 = *(const uint2*)&hh[(size_t)s3 * D + c];
        acc_h4(acc, h0);
        acc_h4(acc, h1);
        acc_h4(acc, h2);
        acc_h4(acc, h3);
    }
    for (; j < end; j++)
        acc_h4(acc, *(const uint2*)&hh[(size_t)g_colidx[j] * D + c]);
    float inv = g_inv_deg[node];
    union { fp16 b[4]; uint2 u; } p;
    p.b[0] = __float2half_rn(acc.x * inv);
    p.b[1] = __float2half_rn(acc.y * inv);
    p.b[2] = __float2half_rn(acc.z * inv);
    p.b[3] = __float2half_rn(acc.w * inv);
    *(uint2*)&g_ca16[(size_t)e * ND + (size_t)i * D + c] = p.u;
}

// ---------------------------------------------------------------------------
// Tensor-core GEMM, 2-product split: C = A@Bhi + A@Blo.
// Stage = 3 tiles [A, Bhi, Blo] (30720B), 2 stages, 1 barrier/iter, 2 CTAs/SM.
// layer==1: dense rows, store h1[e] (fp16). layer==2: compacted rows,
// deterministic atomicAdd combine.
// ---------------------------------------------------------------------------
#define ROWB 80
#define TILE_B (128 * ROWB)        // 10240
#define STAGE_B (3 * TILE_B)       // 30720
#define GEMM_SMEM 67584            // epilogue [128][132] fp32 dominates

__device__ __forceinline__ uint32_t smem_u32(const void* p) {
    uint32_t a;
    asm("{ .reg .u64 t; cvta.to.shared.u64 t, %1; cvt.u32.u64 %0, t; }"
        : "=r"(a) : "l"(p));
    return a;
}
__device__ __forceinline__ void cp16(uint32_t dst, const void* src) {
    asm volatile("cp.async.cg.shared.global [%0], [%1], 16;" :: "r"(dst), "l"(src));
}
__device__ __forceinline__ void ldmx4(uint32_t* r, uint32_t addr) {
    asm volatile("ldmatrix.sync.aligned.m8n8.x4.shared.b16 {%0,%1,%2,%3}, [%4];"
                 : "=r"(r[0]), "=r"(r[1]), "=r"(r[2]), "=r"(r[3]) : "r"(addr));
}
__device__ __forceinline__ void mma16816(float* c, const uint32_t* a, const uint32_t* b) {
    asm volatile("mma.sync.aligned.m16n8k16.row.col.f32.f16.f16.f32 "
                 "{%0,%1,%2,%3}, {%4,%5,%6,%7}, {%8,%9}, {%0,%1,%2,%3};"
                 : "+f"(c[0]), "+f"(c[1]), "+f"(c[2]), "+f"(c[3])
                 : "r"(a[0]), "r"(a[1]), "r"(a[2]), "r"(a[3]), "r"(b[0]), "r"(b[1]));
}

__global__ void __launch_bounds__(256, 2)
sage_gemm_mma(int layer, const float* __restrict__ blv, float* __restrict__ out) {
    extern __shared__ char smem[];
    uint32_t sb = smem_u32(smem);
    int tid = threadIdx.x, lane = tid & 31, wid = tid >> 5;
    int wm = wid >> 2, wn = wid & 3;
    int g = lane >> 2, lam = lane & 3;
    int bn = blockIdx.x * 128, bm = blockIdx.y * 128;
    int e = blockIdx.z;
    int w_idx = (layer == 1) ? 2 * e : 2 * e + 1;
    const float* __restrict__ bias = blv + w_idx * 512;

    int cnt = 0;
    if (layer == 2) {
        cnt = g_cnt[e];
        if (bm >= cnt) return;
    }

    const fp16* __restrict__ bh = g_wthi + (size_t)w_idx * 512 * 1024;
    const fp16* __restrict__ bl = g_wtlo + (size_t)w_idx * 512 * 1024;

    int row_s = tid >> 2, kc_s = tid & 3;
    int row_s2 = (tid + 256) >> 2, kc_s2 = (tid + 256) & 3;

    size_t aoff_s, aoff_s2, hoff_s, hoff_s2;
    const fp16 *p_a, *p_h;
    if (layer == 1) {
        p_a = g_a16;
        p_h = g_x16;
        aoff_s = (size_t)(bm + row_s) * 512;  aoff_s2 = (size_t)(bm + row_s2) * 512;
        hoff_s = aoff_s;                      hoff_s2 = aoff_s2;
    } else {
        p_a = g_ca16 + (size_t)e * ND;
        p_h = g_h116 + (size_t)e * ND;
        int cr_s = min(bm + row_s, cnt - 1), cr_s2 = min(bm + row_s2, cnt - 1);
        aoff_s = (size_t)cr_s * 512;  aoff_s2 = (size_t)cr_s2 * 512;
        hoff_s = (size_t)g_rows[e][cr_s] * 512;
        hoff_s2 = (size_t)g_rows[e][cr_s2] * 512;
    }

    float c[4][4][4];
#pragma unroll
    for (int i = 0; i < 4; i++)
#pragma unroll
        for (int j = 0; j < 4; j++)
#pragma unroll
            for (int q = 0; q < 4; q++) c[i][j][q] = 0.f;

    auto load_stage = [&](int n) {
        uint32_t st = sb + (n & 1) * STAGE_B;
        int ka = (n & 15) * 32, kb = n * 32;
        const fp16* A;
        size_t o1, o2;
        if (n < 16) { A = p_a; o1 = aoff_s; o2 = aoff_s2; }
        else        { A = p_h; o1 = hoff_s; o2 = hoff_s2; }
        uint32_t d1 = st + row_s * ROWB + kc_s * 16;
        uint32_t d2 = st + row_s2 * ROWB + kc_s2 * 16;
        cp16(d1 + 0 * TILE_B, A + o1 + ka + kc_s * 8);
        cp16(d2 + 0 * TILE_B, A + o2 + ka + kc_s2 * 8);
        cp16(d1 + 1 * TILE_B, bh + (size_t)(bn + row_s) * 1024 + kb + kc_s * 8);
        cp16(d2 + 1 * TILE_B, bh + (size_t)(bn + row_s2) * 1024 + kb + kc_s2 * 8);
        cp16(d1 + 2 * TILE_B, bl + (size_t)(bn + row_s) * 1024 + kb + kc_s * 8);
        cp16(d2 + 2 * TILE_B, bl + (size_t)(bn + row_s2) * 1024 + kb + kc_s2 * 8);
    };

    load_stage(0);
    asm volatile("cp.async.commit_group;");

    for (int it = 0; it < 32; it++) {
        asm volatile("cp.async.wait_group 0;");
        __syncthreads();
        if (it + 1 < 32) {
            load_stage(it + 1);
            asm volatile("cp.async.commit_group;");
        }

        uint32_t st = sb + (it & 1) * STAGE_B;
#pragma unroll
        for (int ks = 0; ks < 2; ks++) {
            uint32_t aH[4][4];
#pragma unroll
            for (int mb = 0; mb < 4; mb++) {
                uint32_t ra = st + (wm * 64 + mb * 16 + (lane & 15)) * ROWB
                              + ks * 32 + ((lane >> 4) << 4);
                ldmx4(aH[mb], ra);
            }
#pragma unroll
            for (int np = 0; np < 2; np++) {
                int brow = wn * 32 + np * 16 + (lane & 7) + ((lane & 16) ? 8 : 0);
                uint32_t rb = st + 1 * TILE_B + brow * ROWB + ks * 32
                              + ((lane & 8) ? 16 : 0);
                uint32_t qh[4], ql[4];
                ldmx4(qh, rb);
                ldmx4(ql, rb + TILE_B);
#pragma unroll
                for (int mb = 0; mb < 4; mb++) {
                    mma16816(c[mb][np * 2],     aH[mb], qh);
                    mma16816(c[mb][np * 2],     aH[mb], ql);
                    mma16816(c[mb][np * 2 + 1], aH[mb], qh + 2);
                    mma16816(c[mb][np * 2 + 1], aH[mb], ql + 2);
                }
            }
        }
    }
    __syncthreads();

    float* sep = (float*)smem;  // [128][132] = 67584
#pragma unroll
    for (int mb = 0; mb < 4; mb++)
#pragma unroll
        for (int nb = 0; nb < 4; nb++)
#pragma unroll
            for (int q = 0; q < 4; q++) {
                int row = wm * 64 + mb * 16 + g + ((q >> 1) << 3);
                int col = wn * 32 + nb * 8 + 2 * lam + (q & 1);
                sep[row * 132 + col] = c[mb][nb][q];
            }
    __syncthreads();

    if (layer == 1) {
        fp16* oh = g_h116 + (size_t)e * ND;
        int w = tid & 63, rs = tid >> 6;
        float b0 = bias[bn + 2 * w], b1 = bias[bn + 2 * w + 1];
#pragma unroll
        for (int it = 0; it < 32; it++) {
            int rr = rs + it * 4;
            float v0 = fmaxf(sep[rr * 132 + 2 * w] + b0, 0.f);
            float v1 = fmaxf(sep[rr * 132 + 2 * w + 1] + b1, 0.f);
            union { fp16 b[2]; uint32_t u; } p;
            p.b[0] = __float2half_rn(v0);
            p.b[1] = __float2half_rn(v1);
            *(uint32_t*)&oh[(size_t)(bm + rr) * D + bn + 2 * w] = p.u;
        }
    } else {
        // Deterministic: exactly 2 atomic contributions per element onto
        // zeroed memory; 2-term fp add commutes.
        float4 bc = *(const float4*)&bias[bn + lane * 4];
#pragma unroll
        for (int it = 0; it < 16; it++) {
            int rr = wid + it * 8;
            if (bm + rr < cnt) {
                int m = g_rows[e][bm + rr];
                float gw = g_gatew[m * 4 + e];
                float* p = out + (size_t)m * D + bn + lane * 4;
                atomicAdd(p + 0, gw * fmaxf(sep[rr * 132 + lane * 4 + 0] + bc.x, 0.f));
                atomicAdd(p + 1, gw * fmaxf(sep[rr * 132 + lane * 4 + 1] + bc.y, 0.f));
                atomicAdd(p + 2, gw * fmaxf(sep[rr * 132 + lane * 4 + 2] + bc.z, 0.f));
                atomicAdd(p + 3, gw * fmaxf(sep[rr * 132 + lane * 4 + 3] + bc.w, 0.f));
            }
        }
    }
}

// ---------------------------------------------------------------------------
// Launch — single stream.
// ---------------------------------------------------------------------------
extern "C" void kernel_launch(void* const* d_in, const int* in_sizes, int n_in,
                              void* d_out, int out_size) {
    const float* x = 0; const float* gW = 0; const float* gb = 0;
    const float* Wl = 0; const float* blv = 0; const float* Wr = 0;
    const int*   ei = 0;
    for (int i = 0; i < n_in; i++) {
        long long s = in_sizes[i];
        if (s == 16777216)      { if (!x)  x  = (const float*)d_in[i]; }
        else if (s == 2048)     { if (!gW) gW = (const float*)d_in[i]; }
        else if (s == 4)        { if (!gb) gb = (const float*)d_in[i]; }
        else if (s == 2097152)  { if (!Wl) Wl = (const float*)d_in[i];
                                  else if (!Wr) Wr = (const float*)d_in[i]; }
        else if (s == 4096)     { if (!blv) blv = (const float*)d_in[i]; }
        else if (s == 524288)   { if (!ei) ei = (const int*)d_in[i]; }
    }
    if (!x)   x   = (const float*)d_in[0];
    if (!gW)  gW  = (const float*)d_in[1];
    if (!gb)  gb  = (const float*)d_in[2];
    if (!Wl)  Wl  = (const float*)d_in[3];
    if (!blv) blv = (const float*)d_in[4];
    if (!Wr)  Wr  = (const float*)d_in[5];
    if (!ei)  ei  = (const int*)d_in[6];
    float* out = (float*)d_out;

    cudaFuncSetAttribute(sage_gemm_mma,
                         cudaFuncAttributeMaxDynamicSharedMemorySize, GEMM_SMEM);

    init_kernel<<<N_NODES / 256, 256>>>(ei);
    deg_kernel<<<N_EDGES / 256, 256>>>(ei);
    scan1_kernel<<<128, 256>>>();
    scan2_kernel<<<1, 128>>>();
    scan3_kernel<<<128, 256>>>();
    fill_kernel<<<N_EDGES / 256, 256>>>(ei);
    gate_kernel<<<N_NODES / 8, 256>>>(x, gW, gb);    // also writes x fp16
    prep_w_kernel<<<dim3(32, 16, 8), dim3(32, 32)>>>(Wl, Wr);

    // Layer 1: shared aggr(x), all 4 experts batched
    aggregate_x_kernel<<<N_NODES, 128>>>(x);
    sage_gemm_mma<<<dim3(4, 256, 4), 256, GEMM_SMEM>>>(1, blv, out);

    // Layer 2: compact aggregations (batched), then one batched GEMM launch
    // with deterministic atomic gated-combine.
    cudaMemsetAsync(out, 0, (size_t)out_size * sizeof(float));
    aggregate_h2_kernel<<<dim3(N_NODES, NEXP), 128>>>();
    sage_gemm_mma<<<dim3(4, 256, 4), 256, GEMM_SMEM>>>(2, blv, out);
}

// round 17
// speedup vs baseline: 5.7074x; 1.4353x over previous
#include <cuda_runtime.h>
#include <cuda_fp16.h>
#include <cstdint>

// ---------------------------------------------------------------------------
// MoE GraphSAGE, mma.sync m16n8k16 fp16 (fp32 accum).
// R17: pure fp16 GEMM — single product C ~= A16 @ B16 (both operands RN
// fp16). Error: A-side rounding measured at 2.47e-4 (R16); B-side adds an
// independent same-magnitude term -> ~3.5e-4 total, ~2.9x under the 1e-3
// threshold. HMMA count halves vs R16; cp.async stage 3 -> 2 tiles.
// Structure otherwise == R16-passing kernel.
// ---------------------------------------------------------------------------

#define N_NODES 32768
#define N_EDGES 262144
#define D 512
#define NEXP 4
#define ND (N_NODES * D)

typedef __half fp16;

__device__ fp16  g_x16[ND];                       // x as fp16 (RN)
__device__ fp16  g_a16[ND];                       // layer-1 aggr (all nodes)
__device__ fp16  g_ca16[(size_t)NEXP * ND];       // layer-2 compact aggr
__device__ fp16  g_h116[(size_t)NEXP * ND];       // layer-1 outputs
__device__ fp16  g_wt16[8ull * 512 * 1024];       // [w_idx][n][k], fp16 RN
__device__ float g_inv_deg[N_NODES];
__device__ int   g_deg[N_NODES];
__device__ int   g_rowptr[N_NODES + 1];
__device__ int   g_cursor[N_NODES];
__device__ int   g_colidx[N_EDGES];
__device__ float g_gatew[N_NODES * NEXP];
__device__ int   g_rows[NEXP][N_NODES];
__device__ int   g_cnt[NEXP];
__device__ int   g_pre[N_NODES];
__device__ int   g_bsum[128];
__device__ int   g_is64;

// ---------------------------------------------------------------------------
// Init + CSR
// ---------------------------------------------------------------------------
__global__ void init_kernel(const int* __restrict__ ei32) {
    int i = blockIdx.x * blockDim.x + threadIdx.x;
    if (i < N_NODES) g_deg[i] = 0;
    if (i < NEXP) g_cnt[i] = 0;
    if (i == 0) {
        int is64 = 1;
        for (int k = 0; k < 128; k++)
            if (ei32[2 * k + 1] != 0) { is64 = 0; break; }
        g_is64 = is64;
    }
}
__device__ __forceinline__ int edge_val(const int* __restrict__ e, int idx, int is64) {
    return is64 ? e[2 * idx] : e[idx];
}
__global__ void deg_kernel(const int* __restrict__ ei32) {
    int i = blockIdx.x * blockDim.x + threadIdx.x;
    if (i < N_EDGES) atomicAdd(&g_deg[edge_val(ei32, N_EDGES + i, g_is64)], 1);
}
__global__ void scan1_kernel() {
    __shared__ int sm[256];
    int t = threadIdx.x, i = blockIdx.x * 256 + t;
    sm[t] = g_deg[i];
    __syncthreads();
    for (int off = 1; off < 256; off <<= 1) {
        int v = (t >= off) ? sm[t - off] : 0;
        __syncthreads();
        sm[t] += v;
        __syncthreads();
    }
    g_pre[i] = sm[t];
    if (t == 255) g_bsum[blockIdx.x] = sm[255];
}
__global__ void scan2_kernel() {
    __shared__ int sm[128];
    int t = threadIdx.x;
    int orig = g_bsum[t];
    sm[t] = orig;
    __syncthreads();
    for (int off = 1; off < 128; off <<= 1) {
        int v = (t >= off) ? sm[t - off] : 0;
        __syncthreads();
        sm[t] += v;
        __syncthreads();
    }
    g_bsum[t] = sm[t] - orig;
    if (t == 127) g_rowptr[N_NODES] = sm[127];
}
__global__ void scan3_kernel() {
    int i = blockIdx.x * 256 + threadIdx.x;
    int d = g_deg[i];
    int rp = g_bsum[blockIdx.x] + g_pre[i] - d;
    g_rowptr[i] = rp;
    g_cursor[i] = rp;
    g_inv_deg[i] = (d > 0) ? 1.0f / (float)d : 0.0f;
}
__global__ void fill_kernel(const int* __restrict__ ei32) {
    int i = blockIdx.x * blockDim.x + threadIdx.x;
    if (i < N_EDGES) {
        int is64 = g_is64;
        int src = edge_val(ei32, i, is64);
        int dst = edge_val(ei32, N_EDGES + i, is64);
        g_colidx[atomicAdd(&g_cursor[dst], 1)] = src;
    }
}

// ---------------------------------------------------------------------------
// Gate + active-row lists + x -> fp16 (fused)
// ---------------------------------------------------------------------------
__global__ void gate_kernel(const float* __restrict__ x,
                            const float* __restrict__ gW,
                            const float* __restrict__ gb) {
    int gtid = blockIdx.x * blockDim.x + threadIdx.x;
    int node = gtid >> 5, lane = gtid & 31;
    if (node >= N_NODES) return;
    const float* xr = x + (size_t)node * D;
    fp16* xh = g_x16 + (size_t)node * D;
    float a0 = 0.f, a1 = 0.f, a2 = 0.f, a3 = 0.f;
    for (int i = lane; i < D; i += 32) {
        float xv = xr[i];
        xh[i] = __float2half_rn(xv);
        float4 w = *(const float4*)&gW[i * 4];
        a0 = fmaf(xv, w.x, a0); a1 = fmaf(xv, w.y, a1);
        a2 = fmaf(xv, w.z, a2); a3 = fmaf(xv, w.w, a3);
    }
#pragma unroll
    for (int off = 16; off; off >>= 1) {
        a0 += __shfl_down_sync(0xffffffffu, a0, off);
        a1 += __shfl_down_sync(0xffffffffu, a1, off);
        a2 += __shfl_down_sync(0xffffffffu, a2, off);
        a3 += __shfl_down_sync(0xffffffffu, a3, off);
    }
    if (lane == 0) {
        float l[4] = {a0 + gb[0], a1 + gb[1], a2 + gb[2], a3 + gb[3]};
        float m = fmaxf(fmaxf(l[0], l[1]), fmaxf(l[2], l[3]));
        float e[4], s = 0.f;
#pragma unroll
        for (int k = 0; k < 4; k++) { e[k] = expf(l[k] - m); s += e[k]; }
        float inv = 1.0f / s;
        float p[4];
#pragma unroll
        for (int k = 0; k < 4; k++) p[k] = e[k] * inv;
        int i1 = 0;
#pragma unroll
        for (int k = 1; k < 4; k++) if (p[k] > p[i1]) i1 = k;
        int i2 = -1;
#pragma unroll
        for (int k = 0; k < 4; k++) {
            if (k == i1) continue;
            if (i2 < 0 || p[k] > p[i2]) i2 = k;
        }
#pragma unroll
        for (int k = 0; k < 4; k++)
            g_gatew[node * 4 + k] = (k == i1) ? p[i1] : ((k == i2) ? p[i2] : 0.0f);
        int p1 = atomicAdd(&g_cnt[i1], 1);
        g_rows[i1][p1] = node;
        int p2 = atomicAdd(&g_cnt[i2], 1);
        g_rows[i2][p2] = node;
    }
}

// ---------------------------------------------------------------------------
// Weight prep (fp16 RN only)
// ---------------------------------------------------------------------------
__global__ void prep_w_kernel(const float* __restrict__ Wl, const float* __restrict__ Wr) {
    __shared__ float sm[32][33];
    int m = blockIdx.z;
    int k0 = blockIdx.x * 32, n0 = blockIdx.y * 32;
    int tx = threadIdx.x, ty = threadIdx.y;
    const float* W = (k0 < 512) ? (Wl + (size_t)m * 512 * 512 + (size_t)(k0 + ty) * 512)
                                : (Wr + (size_t)m * 512 * 512 + (size_t)(k0 - 512 + ty) * 512);
    sm[ty][tx] = W[n0 + tx];
    __syncthreads();
    size_t o = (size_t)m * 512 * 1024 + (size_t)(n0 + ty) * 1024 + (k0 + tx);
    g_wt16[o] = __float2half_rn(sm[tx][ty]);
}

// ---------------------------------------------------------------------------
// Aggregations (fp32 accumulate, fp16 in/out; 4-way unrolled)
// ---------------------------------------------------------------------------
__global__ void aggregate_x_kernel(const float* __restrict__ x) {
    int node = blockIdx.x;
    int c = threadIdx.x * 4;
    float4 acc = make_float4(0.f, 0.f, 0.f, 0.f);
    int beg = g_rowptr[node], end = g_rowptr[node + 1];
    int j = beg;
    for (; j + 4 <= end; j += 4) {
        int s0 = g_colidx[j],     s1 = g_colidx[j + 1];
        int s2 = g_colidx[j + 2], s3 = g_colidx[j + 3];
        float4 v0 = *(const float4*)&x[(size_t)s0 * D + c];
        float4 v1 = *(const float4*)&x[(size_t)s1 * D + c];
        float4 v2 = *(const float4*)&x[(size_t)s2 * D + c];
        float4 v3 = *(const float4*)&x[(size_t)s3 * D + c];
        acc.x += v0.x; acc.y += v0.y; acc.z += v0.z; acc.w += v0.w;
        acc.x += v1.x; acc.y += v1.y; acc.z += v1.z; acc.w += v1.w;
        acc.x += v2.x; acc.y += v2.y; acc.z += v2.z; acc.w += v2.w;
        acc.x += v3.x; acc.y += v3.y; acc.z += v3.z; acc.w += v3.w;
    }
    for (; j < end; j++) {
        float4 v = *(const float4*)&x[(size_t)g_colidx[j] * D + c];
        acc.x += v.x; acc.y += v.y; acc.z += v.z; acc.w += v.w;
    }
    float inv = g_inv_deg[node];
    union { fp16 b[4]; uint2 u; } p;
    p.b[0] = __float2half_rn(acc.x * inv);
    p.b[1] = __float2half_rn(acc.y * inv);
    p.b[2] = __float2half_rn(acc.z * inv);
    p.b[3] = __float2half_rn(acc.w * inv);
    *(uint2*)&g_a16[(size_t)node * D + c] = p.u;
}

__device__ __forceinline__ void acc_h4(float4& acc, uint2 uh) {
    union { fp16 b[4]; uint2 u; } v;
    v.u = uh;
    acc.x += __half2float(v.b[0]);
    acc.y += __half2float(v.b[1]);
    acc.z += __half2float(v.b[2]);
    acc.w += __half2float(v.b[3]);
}

__global__ void aggregate_h2_kernel() {
    int e = blockIdx.y;
    int i = blockIdx.x;
    if (i >= g_cnt[e]) return;
    int node = g_rows[e][i];
    const fp16* __restrict__ hh = g_h116 + (size_t)e * ND;
    int c = threadIdx.x * 4;
    float4 acc = make_float4(0.f, 0.f, 0.f, 0.f);
    int beg = g_rowptr[node], end = g_rowptr[node + 1];
    int j = beg;
    for (; j + 4 <= end; j += 4) {
        int s0 = g_colidx[j],     s1 = g_colidx[j + 1];
        int s2 = g_colidx[j + 2], s3 = g_colidx[j + 3];
        uint2 h0 = *(const uint2*)&hh[(size_t)s0 * D + c];
        uint2 h1 = *(const uint2*)&hh[(size_t)s1 * D + c];
        uint2 h2 = *(const uint2*)&hh[(size_t)s2 * D + c];
        uint2 h3 = *(const uint2*)&hh[(size_t)s3 * D + c];
        acc_h4(acc, h0);
        acc_h4(acc, h1);
        acc_h4(acc, h2);
        acc_h4(acc, h3);
    }
    for (; j < end; j++)
        acc_h4(acc, *(const uint2*)&hh[(size_t)g_colidx[j] * D + c]);
    float inv = g_inv_deg[node];
    union { fp16 b[4]; uint2 u; } p;
    p.b[0] = __float2half_rn(acc.x * inv);
    p.b[1] = __float2half_rn(acc.y * inv);
    p.b[2] = __float2half_rn(acc.z * inv);
    p.b[3] = __float2half_rn(acc.w * inv);
    *(uint2*)&g_ca16[(size_t)e * ND + (size_t)i * D + c] = p.u;
}

// ---------------------------------------------------------------------------
// Tensor-core GEMM, single product: C = A16 @ B16.
// Stage = 2 tiles [A, B] (20480B), 2 stages, 1 barrier/iter, 2 CTAs/SM.
// layer==1: dense rows, store h1[e] (fp16). layer==2: compacted rows,
// deterministic atomicAdd combine.
// ---------------------------------------------------------------------------
#define ROWB 80
#define TILE_B (128 * ROWB)        // 10240
#define STAGE_B (2 * TILE_B)       // 20480
#define GEMM_SMEM 67584            // epilogue [128][132] fp32 dominates

__device__ __forceinline__ uint32_t smem_u32(const void* p) {
    uint32_t a;
    asm("{ .reg .u64 t; cvta.to.shared.u64 t, %1; cvt.u32.u64 %0, t; }"
        : "=r"(a) : "l"(p));
    return a;
}
__device__ __forceinline__ void cp16(uint32_t dst, const void* src) {
    asm volatile("cp.async.cg.shared.global [%0], [%1], 16;" :: "r"(dst), "l"(src));
}
__device__ __forceinline__ void ldmx4(uint32_t* r, uint32_t addr) {
    asm volatile("ldmatrix.sync.aligned.m8n8.x4.shared.b16 {%0,%1,%2,%3}, [%4];"
                 : "=r"(r[0]), "=r"(r[1]), "=r"(r[2]), "=r"(r[3]) : "r"(addr));
}
__device__ __forceinline__ void mma16816(float* c, const uint32_t* a, const uint32_t* b) {
    asm volatile("mma.sync.aligned.m16n8k16.row.col.f32.f16.f16.f32 "
                 "{%0,%1,%2,%3}, {%4,%5,%6,%7}, {%8,%9}, {%0,%1,%2,%3};"
                 : "+f"(c[0]), "+f"(c[1]), "+f"(c[2]), "+f"(c[3])
                 : "r"(a[0]), "r"(a[1]), "r"(a[2]), "r"(a[3]), "r"(b[0]), "r"(b[1]));
}

__global__ void __launch_bounds__(256, 2)
sage_gemm_mma(int layer, const float* __restrict__ blv, float* __restrict__ out) {
    extern __shared__ char smem[];
    uint32_t sb = smem_u32(smem);
    int tid = threadIdx.x, lane = tid & 31, wid = tid >> 5;
    int wm = wid >> 2, wn = wid & 3;
    int g = lane >> 2, lam = lane & 3;
    int bn = blockIdx.x * 128, bm = blockIdx.y * 128;
    int e = blockIdx.z;
    int w_idx = (layer == 1) ? 2 * e : 2 * e + 1;
    const float* __restrict__ bias = blv + w_idx * 512;

    int cnt = 0;
    if (layer == 2) {
        cnt = g_cnt[e];
        if (bm >= cnt) return;
    }

    const fp16* __restrict__ bw = g_wt16 + (size_t)w_idx * 512 * 1024;

    int row_s = tid >> 2, kc_s = tid & 3;
    int row_s2 = (tid + 256) >> 2, kc_s2 = (tid + 256) & 3;

    size_t aoff_s, aoff_s2, hoff_s, hoff_s2;
    const fp16 *p_a, *p_h;
    if (layer == 1) {
        p_a = g_a16;
        p_h = g_x16;
        aoff_s = (size_t)(bm + row_s) * 512;  aoff_s2 = (size_t)(bm + row_s2) * 512;
        hoff_s = aoff_s;                      hoff_s2 = aoff_s2;
    } else {
        p_a = g_ca16 + (size_t)e * ND;
        p_h = g_h116 + (size_t)e * ND;
        int cr_s = min(bm + row_s, cnt - 1), cr_s2 = min(bm + row_s2, cnt - 1);
        aoff_s = (size_t)cr_s * 512;  aoff_s2 = (size_t)cr_s2 * 512;
        hoff_s = (size_t)g_rows[e][cr_s] * 512;
        hoff_s2 = (size_t)g_rows[e][cr_s2] * 512;
    }

    float c[4][4][4];
#pragma unroll
    for (int i = 0; i < 4; i++)
#pragma unroll
        for (int j = 0; j < 4; j++)
#pragma unroll
            for (int q = 0; q < 4; q++) c[i][j][q] = 0.f;

    auto load_stage = [&](int n) {
        uint32_t st = sb + (n & 1) * STAGE_B;
        int ka = (n & 15) * 32, kb = n * 32;
        const fp16* A;
        size_t o1, o2;
        if (n < 16) { A = p_a; o1 = aoff_s; o2 = aoff_s2; }
        else        { A = p_h; o1 = hoff_s; o2 = hoff_s2; }
        uint32_t d1 = st + row_s * ROWB + kc_s * 16;
        uint32_t d2 = st + row_s2 * ROWB + kc_s2 * 16;
        cp16(d1 + 0 * TILE_B, A + o1 + ka + kc_s * 8);
        cp16(d2 + 0 * TILE_B, A + o2 + ka + kc_s2 * 8);
        cp16(d1 + 1 * TILE_B, bw + (size_t)(bn + row_s) * 1024 + kb + kc_s * 8);
        cp16(d2 + 1 * TILE_B, bw + (size_t)(bn + row_s2) * 1024 + kb + kc_s2 * 8);
    };

    load_stage(0);
    asm volatile("cp.async.commit_group;");

    for (int it = 0; it < 32; it++) {
        asm volatile("cp.async.wait_group 0;");
        __syncthreads();
        if (it + 1 < 32) {
            load_stage(it + 1);
            asm volatile("cp.async.commit_group;");
        }

        uint32_t st = sb + (it & 1) * STAGE_B;
#pragma unroll
        for (int ks = 0; ks < 2; ks++) {
            uint32_t aH[4][4];
#pragma unroll
            for (int mb = 0; mb < 4; mb++) {
                uint32_t ra = st + (wm * 64 + mb * 16 + (lane & 15)) * ROWB
                              + ks * 32 + ((lane >> 4) << 4);
                ldmx4(aH[mb], ra);
            }
#pragma unroll
            for (int np = 0; np < 2; np++) {
                int brow = wn * 32 + np * 16 + (lane & 7) + ((lane & 16) ? 8 : 0);
                uint32_t rb = st + 1 * TILE_B + brow * ROWB + ks * 32
                              + ((lane & 8) ? 16 : 0);
                uint32_t qh[4];
                ldmx4(qh, rb);
#pragma unroll
                for (int mb = 0; mb < 4; mb++) {
                    mma16816(c[mb][np * 2],     aH[mb], qh);
                    mma16816(c[mb][np * 2 + 1], aH[mb], qh + 2);
                }
            }
        }
    }
    __syncthreads();

    float* sep = (float*)smem;  // [128][132] = 67584
#pragma unroll
    for (int mb = 0; mb < 4; mb++)
#pragma unroll
        for (int nb = 0; nb < 4; nb++)
#pragma unroll
            for (int q = 0; q < 4; q++) {
                int row = wm * 64 + mb * 16 + g + ((q >> 1) << 3);
                int col = wn * 32 + nb * 8 + 2 * lam + (q & 1);
                sep[row * 132 + col] = c[mb][nb][q];
            }
    __syncthreads();

    if (layer == 1) {
        fp16* oh = g_h116 + (size_t)e * ND;
        int w = tid & 63, rs = tid >> 6;
        float b0 = bias[bn + 2 * w], b1 = bias[bn + 2 * w + 1];
#pragma unroll
        for (int it = 0; it < 32; it++) {
            int rr = rs + it * 4;
            float v0 = fmaxf(sep[rr * 132 + 2 * w] + b0, 0.f);
            float v1 = fmaxf(sep[rr * 132 + 2 * w + 1] + b1, 0.f);
            union { fp16 b[2]; uint32_t u; } p;
            p.b[0] = __float2half_rn(v0);
            p.b[1] = __float2half_rn(v1);
            *(uint32_t*)&oh[(size_t)(bm + rr) * D + bn + 2 * w] = p.u;
        }
    } else {
        // Deterministic: exactly 2 atomic contributions per element onto
        // zeroed memory; 2-term fp add commutes.
        float4 bc = *(const float4*)&bias[bn + lane * 4];
#pragma unroll
        for (int it = 0; it < 16; it++) {
            int rr = wid + it * 8;
            if (bm + rr < cnt) {
                int m = g_rows[e][bm + rr];
                float gw = g_gatew[m * 4 + e];
                float* p = out + (size_t)m * D + bn + lane * 4;
                atomicAdd(p + 0, gw * fmaxf(sep[rr * 132 + lane * 4 + 0] + bc.x, 0.f));
                atomicAdd(p + 1, gw * fmaxf(sep[rr * 132 + lane * 4 + 1] + bc.y, 0.f));
                atomicAdd(p + 2, gw * fmaxf(sep[rr * 132 + lane * 4 + 2] + bc.z, 0.f));
                atomicAdd(p + 3, gw * fmaxf(sep[rr * 132 + lane * 4 + 3] + bc.w, 0.f));
            }
        }
    }
}

// ---------------------------------------------------------------------------
// Launch — single stream.
// ---------------------------------------------------------------------------
extern "C" void kernel_launch(void* const* d_in, const int* in_sizes, int n_in,
                              void* d_out, int out_size) {
    const float* x = 0; const float* gW = 0; const float* gb = 0;
    const float* Wl = 0; const float* blv = 0; const float* Wr = 0;
    const int*   ei = 0;
    for (int i = 0; i < n_in; i++) {
        long long s = in_sizes[i];
        if (s == 16777216)      { if (!x)  x  = (const float*)d_in[i]; }
        else if (s == 2048)     { if (!gW) gW = (const float*)d_in[i]; }
        else if (s == 4)        { if (!gb) gb = (const float*)d_in[i]; }
        else if (s == 2097152)  { if (!Wl) Wl = (const float*)d_in[i];
                                  else if (!Wr) Wr = (const float*)d_in[i]; }
        else if (s == 4096)     { if (!blv) blv = (const float*)d_in[i]; }
        else if (s == 524288)   { if (!ei) ei = (const int*)d_in[i]; }
    }
    if (!x)   x   = (const float*)d_in[0];
    if (!gW)  gW  = (const float*)d_in[1];
    if (!gb)  gb  = (const float*)d_in[2];
    if (!Wl)  Wl  = (const float*)d_in[3];
    if (!blv) blv = (const float*)d_in[4];
    if (!Wr)  Wr  = (const float*)d_in[5];
    if (!ei)  ei  = (const int*)d_in[6];
    float* out = (float*)d_out;

    cudaFuncSetAttribute(sage_gemm_mma,
                         cudaFuncAttributeMaxDynamicSharedMemorySize, GEMM_SMEM);

    init_kernel<<<N_NODES / 256, 256>>>(ei);
    deg_kernel<<<N_EDGES / 256, 256>>>(ei);
    scan1_kernel<<<128, 256>>>();
    scan2_kernel<<<1, 128>>>();
    scan3_kernel<<<128, 256>>>();
    fill_kernel<<<N_EDGES / 256, 256>>>(ei);
    gate_kernel<<<N_NODES / 8, 256>>>(x, gW, gb);    // also writes x fp16
    prep_w_kernel<<<dim3(32, 16, 8), dim3(32, 32)>>>(Wl, Wr);

    // Layer 1: shared aggr(x), all 4 experts batched
    aggregate_x_kernel<<<N_NODES, 128>>>(x);
    sage_gemm_mma<<<dim3(4, 256, 4), 256, GEMM_SMEM>>>(1, blv, out);

    // Layer 2: compact aggregations (batched), then one batched GEMM launch
    // with deterministic atomic gated-combine.
    cudaMemsetAsync(out, 0, (size_t)out_size * sizeof(float));
    aggregate_h2_kernel<<<dim3(N_NODES, NEXP), 128>>>();
    sage_gemm_mma<<<dim3(4, 256, 4), 256, GEMM_SMEM>>>(2, blv, out);
}